// round 9
// baseline (speedup 1.0000x reference)
#include <cuda_runtime.h>
#include <cuda_fp16.h>
#include <cstdint>
#include <math.h>

// ---------------------------------------------------------------------------
// Problem constants (Flux dual-stream attention block)
// ---------------------------------------------------------------------------
#define S_TXT   512
#define S_IMG   2048
#define S_TOT   2560
#define DMODEL  3072
#define NHEADS  24
#define DH      128
#define D3      9216

// ---------------------------------------------------------------------------
// Scratch (device globals -- allocation is forbidden)
// ---------------------------------------------------------------------------
__device__ __align__(256) __half g_qkvh [(size_t)S_IMG * D3];
__device__ __align__(256) __half g_eqkvh[(size_t)S_TXT * D3];
__device__ __align__(256) __half g_hh   [(size_t)S_IMG * DMODEL];
__device__ __align__(256) __half g_eh   [(size_t)S_TXT * DMODEL];
__device__ __align__(256) __half g_qh   [(size_t)S_TOT * DMODEL];
__device__ __align__(256) __half g_kh   [(size_t)S_TOT * DMODEL];
__device__ __align__(256) __half g_vt   [(size_t)DMODEL * S_TOT];
__device__ __align__(256) __half g_attnh[(size_t)S_TOT * DMODEL];
__device__ __align__(256) __half g_wtq  [(size_t)D3 * DMODEL];
__device__ __align__(256) __half g_wtaq [(size_t)D3 * DMODEL];
__device__ __align__(256) __half g_wto  [(size_t)DMODEL * DMODEL];
__device__ __align__(256) __half g_wtao [(size_t)DMODEL * DMODEL];

// ---------------------------------------------------------------------------
// helpers
// ---------------------------------------------------------------------------
__device__ __forceinline__ uint32_t smem_u32(const void* p) {
    uint32_t a;
    asm("{ .reg .u64 t; cvta.to.shared.u64 t, %1; cvt.u32.u64 %0, t; }" : "=r"(a) : "l"(p));
    return a;
}
__device__ __forceinline__ uint32_t packh2(float lo, float hi) {
    uint32_t r;
    asm("cvt.rn.f16x2.f32 %0, %1, %2;" : "=r"(r) : "f"(hi), "f"(lo));
    return r;
}
__device__ __forceinline__ uint32_t ex2h2(uint32_t x) {
    uint32_t r;
    asm("ex2.approx.f16x2 %0, %1;" : "=r"(r) : "r"(x));
    return r;
}
__device__ __forceinline__ void cp16(uint32_t saddr, const void* gptr) {
    asm volatile("cp.async.cg.shared.global [%0], [%1], 16;" :: "r"(saddr), "l"(gptr));
}
__device__ __forceinline__ void ldmx4(uint4& f, uint32_t addr) {
    asm volatile("ldmatrix.sync.aligned.m8n8.x4.shared.b16 {%0,%1,%2,%3}, [%4];"
                 : "=r"(f.x), "=r"(f.y), "=r"(f.z), "=r"(f.w) : "r"(addr));
}
#define MMA16816(acc, a, b0, b1)                                               \
    asm volatile("mma.sync.aligned.m16n8k16.row.col.f32.f16.f16.f32 "          \
                 "{%0,%1,%2,%3}, {%4,%5,%6,%7}, {%8,%9}, {%0,%1,%2,%3};"       \
                 : "+f"((acc)[0]), "+f"((acc)[1]), "+f"((acc)[2]), "+f"((acc)[3]) \
                 : "r"((a).x), "r"((a).y), "r"((a).z), "r"((a).w),             \
                   "r"(b0), "r"(b1))

// ---------------------------------------------------------------------------
// fp16 cp.async NT GEMM, 128x128 tile (proven; used for M=512 GEMMs)
// ---------------------------------------------------------------------------
#define STAGE_BYTES 16384
#define GEMM_SMEM_BYTES (4 * STAGE_BYTES)

__global__ __launch_bounds__(256)
void gemm_nt_h(const __half* __restrict__ A, const __half* __restrict__ B,
               const float* __restrict__ bias, void* __restrict__ Cv,
               int K, int lda, int ldb, int ldc,
               long long sA, long long sB, long long sC, int out_half)
{
    extern __shared__ char smem[];
    const uint32_t sbase = smem_u32(smem);
    const int tid    = threadIdx.x;
    const int lane   = tid & 31;
    const int wid    = tid >> 5;
    const int warp_m = wid >> 2;
    const int warp_n = wid & 3;
    const int bm     = blockIdx.y * 128;
    const int bn     = blockIdx.x * 128;

    A += (size_t)blockIdx.z * sA + (size_t)bm * lda;
    B += (size_t)blockIdx.z * sB + (size_t)bn * ldb;

    uint32_t soff[2];
    size_t   goa[2], gob[2];
#pragma unroll
    for (int j = 0; j < 2; j++) {
        const int c  = tid + j * 256;
        const int r  = c >> 2;
        const int kc = c & 3;
        const int sw = kc ^ ((r >> 1) & 3);
        soff[j] = (uint32_t)(r * 64 + sw * 16);
        goa[j]  = (size_t)r * lda + kc * 8;
        gob[j]  = (size_t)r * ldb + kc * 8;
    }

    const int T = K >> 5;

#pragma unroll
    for (int s = 0; s < 3; s++) {
        const uint32_t sa = sbase + s * STAGE_BYTES;
        if (s < T) {
#pragma unroll
            for (int j = 0; j < 2; j++) {
                cp16(sa + soff[j],        A + goa[j] + s * 32);
                cp16(sa + 8192 + soff[j], B + gob[j] + s * 32);
            }
        }
        asm volatile("cp.async.commit_group;");
    }

    float acc[4][4][4];
#pragma unroll
    for (int m = 0; m < 4; m++)
#pragma unroll
        for (int n = 0; n < 4; n++)
#pragma unroll
            for (int x = 0; x < 4; x++) acc[m][n][x] = 0.0f;

    const int p    = lane >> 3;
    const int li   = lane & 7;
    const int rA0  = warp_m * 64 + (p & 1) * 8 + li;
    const int rB0  = warp_n * 32 + (p & 1) * 8 + li;
    const int kaddp = p >> 1;

    for (int t = 0; t < T; t++) {
        asm volatile("cp.async.wait_group 2;");
        __syncthreads();
        {
            const int kt = t + 3;
            const uint32_t sa = sbase + (kt & 3) * STAGE_BYTES;
            if (kt < T) {
#pragma unroll
                for (int j = 0; j < 2; j++) {
                    cp16(sa + soff[j],        A + goa[j] + (size_t)kt * 32);
                    cp16(sa + 8192 + soff[j], B + gob[j] + (size_t)kt * 32);
                }
            }
            asm volatile("cp.async.commit_group;");
        }

        const uint32_t st = sbase + (t & 3) * STAGE_BYTES;
#pragma unroll
        for (int ks = 0; ks < 2; ks++) {
            const int kc = ks * 2 + kaddp;
            uint4 af[4];
#pragma unroll
            for (int mt = 0; mt < 4; mt++) {
                const int row = rA0 + mt * 16;
                const int sw  = kc ^ ((row >> 1) & 3);
                ldmx4(af[mt], st + row * 64 + sw * 16);
            }
            uint4 bq[2];
#pragma unroll
            for (int ntp = 0; ntp < 2; ntp++) {
                const int row = rB0 + ntp * 16;
                const int sw  = kc ^ ((row >> 1) & 3);
                ldmx4(bq[ntp], st + 8192 + row * 64 + sw * 16);
            }
            uint2 bf[4];
            bf[0] = make_uint2(bq[0].x, bq[0].z);
            bf[1] = make_uint2(bq[0].y, bq[0].w);
            bf[2] = make_uint2(bq[1].x, bq[1].z);
            bf[3] = make_uint2(bq[1].y, bq[1].w);
#pragma unroll
            for (int m = 0; m < 4; m++)
#pragma unroll
                for (int n = 0; n < 4; n++)
                    MMA16816(acc[m][n], af[m], bf[n].x, bf[n].y);
        }
        __syncthreads();
    }

    const int g  = lane >> 2;
    const int tg = lane & 3;
    if (out_half) {
        __half* C = (__half*)Cv + (size_t)blockIdx.z * sC;
#pragma unroll
        for (int m = 0; m < 4; m++) {
            const int row0 = bm + warp_m * 64 + m * 16 + g;
#pragma unroll
            for (int n = 0; n < 4; n++) {
                const int col = bn + warp_n * 32 + n * 8 + tg * 2;
                float bx = 0.f, by = 0.f;
                if (bias) { bx = bias[col]; by = bias[col + 1]; }
                *(uint32_t*)(C + (size_t)row0 * ldc + col) =
                    packh2(acc[m][n][0] + bx, acc[m][n][1] + by);
                *(uint32_t*)(C + (size_t)(row0 + 8) * ldc + col) =
                    packh2(acc[m][n][2] + bx, acc[m][n][3] + by);
            }
        }
    } else {
        float* C = (float*)Cv + (size_t)blockIdx.z * sC;
#pragma unroll
        for (int m = 0; m < 4; m++) {
            const int row0 = bm + warp_m * 64 + m * 16 + g;
#pragma unroll
            for (int n = 0; n < 4; n++) {
                const int col = bn + warp_n * 32 + n * 8 + tg * 2;
                float bx = 0.f, by = 0.f;
                if (bias) { bx = bias[col]; by = bias[col + 1]; }
                *(float2*)(C + (size_t)row0 * ldc + col) =
                    make_float2(acc[m][n][0] + bx, acc[m][n][1] + by);
                *(float2*)(C + (size_t)(row0 + 8) * ldc + col) =
                    make_float2(acc[m][n][2] + bx, acc[m][n][3] + by);
            }
        }
    }
}

// ---------------------------------------------------------------------------
// fp16 cp.async NT GEMM, 256x128 tile (for M=2048 GEMMs).
// 256 thr = 8 warps (4 M x 2 N), warp tile 64x64. Stage = A 16KB + B 8KB.
// ---------------------------------------------------------------------------
#define BSTAGE_BYTES 24576
#define BGEMM_SMEM   (4 * BSTAGE_BYTES)   // 98304

__global__ __launch_bounds__(256)
void gemm_nt_big(const __half* __restrict__ A, const __half* __restrict__ B,
                 const float* __restrict__ bias, void* __restrict__ Cv,
                 int K, int lda, int ldb, int ldc, int out_half)
{
    extern __shared__ char smem[];
    const uint32_t sbase = smem_u32(smem);
    const int tid    = threadIdx.x;
    const int lane   = tid & 31;
    const int wid    = tid >> 5;
    const int warp_m = wid & 3;        // 0..3
    const int warp_n = wid >> 2;       // 0..1
    const int bm     = blockIdx.y * 256;
    const int bn     = blockIdx.x * 128;

    A += (size_t)bm * lda;
    B += (size_t)bn * ldb;

    // A: 4 chunks/thread (1024 chunks), B: 2 chunks/thread (512 chunks)
    uint32_t soffA[4], soffB[2];
    size_t   goa[4],   gob[2];
#pragma unroll
    for (int j = 0; j < 4; j++) {
        const int c  = tid + j * 256;
        const int r  = c >> 2;
        const int kc = c & 3;
        soffA[j] = (uint32_t)(r * 64 + (kc ^ ((r >> 1) & 3)) * 16);
        goa[j]   = (size_t)r * lda + kc * 8;
    }
#pragma unroll
    for (int j = 0; j < 2; j++) {
        const int c  = tid + j * 256;
        const int r  = c >> 2;
        const int kc = c & 3;
        soffB[j] = (uint32_t)(16384 + r * 64 + (kc ^ ((r >> 1) & 3)) * 16);
        gob[j]   = (size_t)r * ldb + kc * 8;
    }

    const int T = K >> 5;

#pragma unroll
    for (int s = 0; s < 3; s++) {
        const uint32_t sa = sbase + s * BSTAGE_BYTES;
        if (s < T) {
#pragma unroll
            for (int j = 0; j < 4; j++)
                cp16(sa + soffA[j], A + goa[j] + s * 32);
#pragma unroll
            for (int j = 0; j < 2; j++)
                cp16(sa + soffB[j], B + gob[j] + s * 32);
        }
        asm volatile("cp.async.commit_group;");
    }

    float acc[4][8][4];
#pragma unroll
    for (int m = 0; m < 4; m++)
#pragma unroll
        for (int n = 0; n < 8; n++)
#pragma unroll
            for (int x = 0; x < 4; x++) acc[m][n][x] = 0.0f;

    const int p     = lane >> 3;
    const int li    = lane & 7;
    const int kaddp = p >> 1;
    const int rA0   = warp_m * 64 + (p & 1) * 8 + li;
    const int rB0   = warp_n * 64 + (p & 1) * 8 + li;

    for (int t = 0; t < T; t++) {
        asm volatile("cp.async.wait_group 2;");
        __syncthreads();
        {
            const int kt = t + 3;
            const uint32_t sa = sbase + ((kt & 3) * BSTAGE_BYTES);
            if (kt < T) {
#pragma unroll
                for (int j = 0; j < 4; j++)
                    cp16(sa + soffA[j], A + goa[j] + (size_t)kt * 32);
#pragma unroll
                for (int j = 0; j < 2; j++)
                    cp16(sa + soffB[j], B + gob[j] + (size_t)kt * 32);
            }
            asm volatile("cp.async.commit_group;");
        }

        const uint32_t st = sbase + (t & 3) * BSTAGE_BYTES;
#pragma unroll
        for (int ks = 0; ks < 2; ks++) {
            const int kc = ks * 2 + kaddp;
            uint4 af[4];
#pragma unroll
            for (int mt = 0; mt < 4; mt++) {
                const int row = rA0 + mt * 16;
                const int sw  = kc ^ ((row >> 1) & 3);
                ldmx4(af[mt], st + row * 64 + sw * 16);
            }
            uint2 bf[8];
#pragma unroll
            for (int ntp = 0; ntp < 4; ntp++) {
                const int row = rB0 + ntp * 16;
                const int sw  = kc ^ ((row >> 1) & 3);
                uint4 bq;
                ldmx4(bq, st + 16384 + row * 64 + sw * 16);
                bf[ntp * 2]     = make_uint2(bq.x, bq.z);
                bf[ntp * 2 + 1] = make_uint2(bq.y, bq.w);
            }
#pragma unroll
            for (int m = 0; m < 4; m++)
#pragma unroll
                for (int n = 0; n < 8; n++)
                    MMA16816(acc[m][n], af[m], bf[n].x, bf[n].y);
        }
        __syncthreads();
    }

    const int g  = lane >> 2;
    const int tg = lane & 3;
    if (out_half) {
        __half* C = (__half*)Cv;
#pragma unroll
        for (int m = 0; m < 4; m++) {
            const int row0 = bm + warp_m * 64 + m * 16 + g;
#pragma unroll
            for (int n = 0; n < 8; n++) {
                const int col = bn + warp_n * 64 + n * 8 + tg * 2;
                float bx = 0.f, by = 0.f;
                if (bias) { bx = bias[col]; by = bias[col + 1]; }
                *(uint32_t*)(C + (size_t)row0 * ldc + col) =
                    packh2(acc[m][n][0] + bx, acc[m][n][1] + by);
                *(uint32_t*)(C + (size_t)(row0 + 8) * ldc + col) =
                    packh2(acc[m][n][2] + bx, acc[m][n][3] + by);
            }
        }
    } else {
        float* C = (float*)Cv;
#pragma unroll
        for (int m = 0; m < 4; m++) {
            const int row0 = bm + warp_m * 64 + m * 16 + g;
#pragma unroll
            for (int n = 0; n < 8; n++) {
                const int col = bn + warp_n * 64 + n * 8 + tg * 2;
                float bx = 0.f, by = 0.f;
                if (bias) { bx = bias[col]; by = bias[col + 1]; }
                *(float2*)(C + (size_t)row0 * ldc + col) =
                    make_float2(acc[m][n][0] + bx, acc[m][n][1] + by);
                *(float2*)(C + (size_t)(row0 + 8) * ldc + col) =
                    make_float2(acc[m][n][2] + bx, acc[m][n][3] + by);
            }
        }
    }
}

// ---------------------------------------------------------------------------
// Fused flash attention (R8 version: log2 softmax, ex2.f16x2, mma row sums)
// ---------------------------------------------------------------------------
#define FA_QSM    32768
#define FA_KBYTES 32768
#define FA_VSEC   9216
#define FA_VBYTES (4 * FA_VSEC)
#define FA_KV     (FA_KBYTES + FA_VBYTES)
#define FA_SMEM   (FA_QSM + 2 * FA_KV)
#define NBLK      (S_TOT / 128)

__global__ __launch_bounds__(256)
void flash_attn(const __half* __restrict__ Qg, const __half* __restrict__ Kg,
                const __half* __restrict__ VTg, __half* __restrict__ Og)
{
    extern __shared__ char smem[];
    const uint32_t sbase = smem_u32(smem);
    const int tid  = threadIdx.x;
    const int lane = tid & 31;
    const int wid  = tid >> 5;
    const int qb   = blockIdx.x;
    const int h    = blockIdx.y;

    uint32_t soff[2];
    int rr[2], kc8[2];
#pragma unroll
    for (int j = 0; j < 2; j++) {
        const int c  = tid + j * 256;
        const int r  = c >> 2;
        const int kc = c & 3;
        soff[j] = (uint32_t)(r * 64 + (kc ^ ((r >> 1) & 3)) * 16);
        rr[j]   = r;
        kc8[j]  = kc * 8;
    }

    const __half* Qp = Qg + (size_t)(qb * 128) * DMODEL + h * DH;
    const __half* Kp = Kg + h * DH;
    const __half* Vp = VTg + (size_t)(h * DH) * S_TOT;

#pragma unroll
    for (int bs = 0; bs < 8; bs++) {
        const int buf = bs >> 2;
        const int sec = bs & 3;
        const uint32_t base = FA_QSM + buf * FA_KV + FA_KBYTES
                            + sec * FA_VSEC + 128 * 64;
        const int w = tid;
        *(uint32_t*)(smem + base + w * 4) = (w < 16) ? 0x3C003C00u : 0u;
    }

#pragma unroll
    for (int sec = 0; sec < 4; sec++)
#pragma unroll
        for (int j = 0; j < 2; j++)
            cp16(sbase + sec * 8192 + soff[j],
                 Qp + (size_t)rr[j] * DMODEL + sec * 32 + kc8[j]);
    {
        const uint32_t kb = sbase + FA_QSM;
        const uint32_t vb = kb + FA_KBYTES;
#pragma unroll
        for (int sec = 0; sec < 4; sec++)
#pragma unroll
            for (int j = 0; j < 2; j++) {
                cp16(kb + sec * 8192 + soff[j],
                     Kp + (size_t)rr[j] * DMODEL + sec * 32 + kc8[j]);
                cp16(vb + sec * FA_VSEC + soff[j],
                     Vp + (size_t)rr[j] * S_TOT + sec * 32 + kc8[j]);
            }
    }
    asm volatile("cp.async.commit_group;");
    {
        const uint32_t kb = sbase + FA_QSM + FA_KV;
        const uint32_t vb = kb + FA_KBYTES;
#pragma unroll
        for (int sec = 0; sec < 4; sec++)
#pragma unroll
            for (int j = 0; j < 2; j++) {
                cp16(kb + sec * 8192 + soff[j],
                     Kp + (size_t)(128 + rr[j]) * DMODEL + sec * 32 + kc8[j]);
                cp16(vb + sec * FA_VSEC + soff[j],
                     Vp + (size_t)rr[j] * S_TOT + 128 + sec * 32 + kc8[j]);
            }
    }
    asm volatile("cp.async.commit_group;");

    const int p     = lane >> 3;
    const int li    = lane & 7;
    const int kaddp = p >> 1;
    const int rowQ  = wid * 16 + (p & 1) * 8 + li;
    const int rB0   = (p & 1) * 8 + li;
    const int g     = lane >> 2;
    const int tg    = lane & 3;

    float mrow[2] = {-1e30f, -1e30f};
    float o[18][4];
#pragma unroll
    for (int j = 0; j < 18; j++)
#pragma unroll
        for (int x = 0; x < 4; x++) o[j][x] = 0.f;
    uint4 qf[8];

    for (int jb = 0; jb < NBLK; jb++) {
        asm volatile("cp.async.wait_group 1;");
        __syncthreads();

        if (jb == 0) {
#pragma unroll
            for (int kc = 0; kc < 8; kc++) {
                const int sec = kc >> 1;
                const int c   = (kc & 1) * 2 + kaddp;
                const int sw  = c ^ ((rowQ >> 1) & 3);
                ldmx4(qf[kc], sbase + sec * 8192 + rowQ * 64 + sw * 16);
            }
        }

        const uint32_t kb = sbase + FA_QSM + (jb & 1) * FA_KV;
        const uint32_t vb = kb + FA_KBYTES;

        float sacc[16][4];
#pragma unroll
        for (int j = 0; j < 16; j++)
#pragma unroll
            for (int x = 0; x < 4; x++) sacc[j][x] = 0.f;
#pragma unroll
        for (int kc = 0; kc < 8; kc++) {
            const int sec = kc >> 1;
            const int c   = (kc & 1) * 2 + kaddp;
#pragma unroll
            for (int np = 0; np < 8; np++) {
                const int row = np * 16 + rB0;
                const int sw  = c ^ ((row >> 1) & 3);
                uint4 bq;
                ldmx4(bq, kb + sec * 8192 + row * 64 + sw * 16);
                MMA16816(sacc[np * 2],     qf[kc], bq.x, bq.z);
                MMA16816(sacc[np * 2 + 1], qf[kc], bq.y, bq.w);
            }
        }

        float mx0 = -1e30f, mx1 = -1e30f;
#pragma unroll
        for (int j = 0; j < 16; j++) {
            mx0 = fmaxf(mx0, fmaxf(sacc[j][0], sacc[j][1]));
            mx1 = fmaxf(mx1, fmaxf(sacc[j][2], sacc[j][3]));
        }
        mx0 = fmaxf(mx0, __shfl_xor_sync(0xffffffffu, mx0, 1));
        mx0 = fmaxf(mx0, __shfl_xor_sync(0xffffffffu, mx0, 2));
        mx1 = fmaxf(mx1, __shfl_xor_sync(0xffffffffu, mx1, 1));
        mx1 = fmaxf(mx1, __shfl_xor_sync(0xffffffffu, mx1, 2));

        const float mn0 = fmaxf(mrow[0], mx0);
        const float mn1 = fmaxf(mrow[1], mx1);
        const float sc0 = exp2f(mrow[0] - mn0);
        const float sc1 = exp2f(mrow[1] - mn1);
        mrow[0] = mn0; mrow[1] = mn1;

        uint32_t pf[16][2];
#pragma unroll
        for (int j = 0; j < 16; j++) {
            pf[j][0] = ex2h2(packh2(sacc[j][0] - mn0, sacc[j][1] - mn0));
            pf[j][1] = ex2h2(packh2(sacc[j][2] - mn1, sacc[j][3] - mn1));
        }
#pragma unroll
        for (int j = 0; j < 18; j++) {
            o[j][0] *= sc0; o[j][1] *= sc0;
            o[j][2] *= sc1; o[j][3] *= sc1;
        }

#pragma unroll
        for (int kc = 0; kc < 8; kc++) {
            const int sec = kc >> 1;
            const int c   = (kc & 1) * 2 + kaddp;
            uint4 a;
            a.x = pf[kc * 2][0];
            a.y = pf[kc * 2][1];
            a.z = pf[kc * 2 + 1][0];
            a.w = pf[kc * 2 + 1][1];
#pragma unroll
            for (int np = 0; np < 9; np++) {
                const int row = np * 16 + rB0;
                const int sw  = c ^ ((row >> 1) & 3);
                uint4 bq;
                ldmx4(bq, vb + sec * FA_VSEC + row * 64 + sw * 16);
                MMA16816(o[np * 2],     a, bq.x, bq.z);
                MMA16816(o[np * 2 + 1], a, bq.y, bq.w);
            }
        }

        __syncthreads();

        const int nb = jb + 2;
        if (nb < NBLK) {
            const uint32_t nkb = sbase + FA_QSM + (nb & 1) * FA_KV;
            const uint32_t nvb = nkb + FA_KBYTES;
#pragma unroll
            for (int sec = 0; sec < 4; sec++)
#pragma unroll
                for (int j = 0; j < 2; j++) {
                    cp16(nkb + sec * 8192 + soff[j],
                         Kp + (size_t)(nb * 128 + rr[j]) * DMODEL + sec * 32 + kc8[j]);
                    cp16(nvb + sec * FA_VSEC + soff[j],
                         Vp + (size_t)rr[j] * S_TOT + nb * 128 + sec * 32 + kc8[j]);
                }
        }
        asm volatile("cp.async.commit_group;");
    }

    const float l0 = __shfl_sync(0xffffffffu, o[16][0], lane & 28);
    const float l1 = __shfl_sync(0xffffffffu, o[16][2], lane & 28);
    const float inv0 = 1.0f / l0;
    const float inv1 = 1.0f / l1;
    __half* Op = Og + (size_t)(qb * 128) * DMODEL + h * DH;
#pragma unroll
    for (int j = 0; j < 16; j++) {
        const int col  = j * 8 + tg * 2;
        const int row0 = wid * 16 + g;
        *(uint32_t*)(Op + (size_t)row0 * DMODEL + col) =
            packh2(o[j][0] * inv0, o[j][1] * inv0);
        *(uint32_t*)(Op + (size_t)(row0 + 8) * DMODEL + col) =
            packh2(o[j][2] * inv1, o[j][3] * inv1);
    }
}

// ---------------------------------------------------------------------------
// float -> half elementwise
// ---------------------------------------------------------------------------
__global__ __launch_bounds__(256)
void f2h_kernel(const float* __restrict__ in, __half* __restrict__ out)
{
    const size_t i = ((size_t)blockIdx.x * 256 + threadIdx.x) * 4;
    float4 v = *(const float4*)(in + i);
    *(uint2*)(out + i) = make_uint2(packh2(v.x, v.y), packh2(v.z, v.w));
}

// ---------------------------------------------------------------------------
// 64x64 vectorized transpose fp32 -> fp16: out[C,R] = half(in[R,C]^T)
// 256 threads; float4 loads, uint2 (4x fp16) stores.
// ---------------------------------------------------------------------------
__global__ __launch_bounds__(256)
void transpose64(const float* __restrict__ in, __half* __restrict__ out,
                 int R, int C)
{
    __shared__ float t[64][65];
    const int bx  = blockIdx.x * 64;   // col base (input)
    const int by  = blockIdx.y * 64;   // row base (input)
    const int tx4 = (threadIdx.x & 15) * 4;
    const int ty  = threadIdx.x >> 4;  // 0..15
#pragma unroll
    for (int j = 0; j < 4; j++) {
        const int row = ty + j * 16;
        float4 v = *(const float4*)(in + (size_t)(by + row) * C + bx + tx4);
        t[row][tx4 + 0] = v.x; t[row][tx4 + 1] = v.y;
        t[row][tx4 + 2] = v.z; t[row][tx4 + 3] = v.w;
    }
    __syncthreads();
#pragma unroll
    for (int j = 0; j < 4; j++) {
        const int orow = ty + j * 16;           // output row = input col
        uint2 w = make_uint2(
            packh2(t[tx4 + 0][orow], t[tx4 + 1][orow]),
            packh2(t[tx4 + 2][orow], t[tx4 + 3][orow]));
        *(uint2*)(out + (size_t)(bx + orow) * R + by + tx4) = w;
    }
}

// ---------------------------------------------------------------------------
// Fused RMSNorm + RoPE (fp16 in) -> fp16 q (scale*log2e), k, V^T
// ---------------------------------------------------------------------------
__device__ __forceinline__ float warp_sum(float v) {
#pragma unroll
    for (int o = 16; o > 0; o >>= 1) v += __shfl_xor_sync(0xffffffffu, v, o);
    return v;
}

__global__ __launch_bounds__(128)
void fuse_norm_rope(const __half* __restrict__ qkv, const __half* __restrict__ eqkv,
                    const int* __restrict__ ids,
                    const float* __restrict__ nq_w,  const float* __restrict__ nk_w,
                    const float* __restrict__ naq_w, const float* __restrict__ nak_w,
                    __half* __restrict__ Q, __half* __restrict__ Ko,
                    __half* __restrict__ VT)
{
    const int s = blockIdx.x;
    const int h = blockIdx.y;
    const int d = threadIdx.x;

    const __half* src;
    const float* qw;
    const float* kw;
    if (s < S_TXT) { src = eqkv + (size_t)s * D3;           qw = naq_w; kw = nak_w; }
    else           { src = qkv  + (size_t)(s - S_TXT) * D3; qw = nq_w;  kw = nk_w; }

    float qv = __half2float(src[h * DH + d]);
    float kv = __half2float(src[DMODEL   + h * DH + d]);
    float vv = __half2float(src[2*DMODEL + h * DH + d]);

    __shared__ float sq[4], sk[4];
    float wq = warp_sum(qv * qv);
    float wk = warp_sum(kv * kv);
    const int w = d >> 5;
    if ((d & 31) == 0) { sq[w] = wq; sk[w] = wk; }
    __syncthreads();
    float qsum = sq[0] + sq[1] + sq[2] + sq[3];
    float ksum = sk[0] + sk[1] + sk[2] + sk[3];
    float qn = qv * rsqrtf(qsum * (1.0f / DH) + 1e-5f) * qw[d];
    float kn = kv * rsqrtf(ksum * (1.0f / DH) + 1e-5f) * kw[d];

    const int pr = d >> 1;
    int axis, base, dax;
    if      (pr < 8)  { axis = 0; base = 0;  dax = 16; }
    else if (pr < 36) { axis = 1; base = 8;  dax = 56; }
    else              { axis = 2; base = 36; dax = 56; }
    float e    = (2.0f * (float)(pr - base)) / (float)dax;
    float freq = expf(-e * 9.210340371976184f);
    float pos  = (float)ids[s * 3 + axis];
    float ang  = pos * freq;
    float cs, sn;
    sincosf(ang, &sn, &cs);

    float q_other = __shfl_xor_sync(0xffffffffu, qn, 1);
    float k_other = __shfl_xor_sync(0xffffffffu, kn, 1);
    float qr, kr;
    if (d & 1) { qr = qn * cs + q_other * sn; kr = kn * cs + k_other * sn; }
    else       { qr = qn * cs - q_other * sn; kr = kn * cs - k_other * sn; }

    const size_t o = (size_t)s * DMODEL + h * DH + d;
    Q[o]  = __float2half(qr * (0.08838834764831845f * 1.4426950408889634f));
    Ko[o] = __float2half(kr);
    VT[(size_t)(h * DH + d) * S_TOT + s] = __float2half(vv);
}

// ---------------------------------------------------------------------------
// kernel_launch
// ---------------------------------------------------------------------------
extern "C" void kernel_launch(void* const* d_in, const int* in_sizes, int n_in,
                              void* d_out, int out_size)
{
    const float* hidden     = (const float*)d_in[0];
    const float* enc        = (const float*)d_in[1];
    const int*   ids        = (const int*)  d_in[2];
    const float* w_qkv      = (const float*)d_in[3];
    const float* w_add_qkv  = (const float*)d_in[4];
    const float* b_add_qkv  = (const float*)d_in[5];
    const float* w_out      = (const float*)d_in[6];
    const float* b_out      = (const float*)d_in[7];
    const float* w_add_out  = (const float*)d_in[8];
    const float* b_add_out  = (const float*)d_in[9];
    const float* norm_q_w   = (const float*)d_in[10];
    const float* norm_k_w   = (const float*)d_in[11];
    const float* norm_aq_w  = (const float*)d_in[12];
    const float* norm_ak_w  = (const float*)d_in[13];
    float* out = (float*)d_out;

    __half *qkvh, *eqkvh, *hh, *eh, *qh, *kh, *vt, *attnh, *wtq, *wtaq, *wto, *wtao;
    cudaGetSymbolAddress((void**)&qkvh,  g_qkvh);
    cudaGetSymbolAddress((void**)&eqkvh, g_eqkvh);
    cudaGetSymbolAddress((void**)&hh,    g_hh);
    cudaGetSymbolAddress((void**)&eh,    g_eh);
    cudaGetSymbolAddress((void**)&qh,    g_qh);
    cudaGetSymbolAddress((void**)&kh,    g_kh);
    cudaGetSymbolAddress((void**)&vt,    g_vt);
    cudaGetSymbolAddress((void**)&attnh, g_attnh);
    cudaGetSymbolAddress((void**)&wtq,   g_wtq);
    cudaGetSymbolAddress((void**)&wtaq,  g_wtaq);
    cudaGetSymbolAddress((void**)&wto,   g_wto);
    cudaGetSymbolAddress((void**)&wtao,  g_wtao);

    cudaFuncSetAttribute(gemm_nt_h, cudaFuncAttributeMaxDynamicSharedMemorySize,
                         GEMM_SMEM_BYTES);
    cudaFuncSetAttribute(gemm_nt_big, cudaFuncAttributeMaxDynamicSharedMemorySize,
                         BGEMM_SMEM);
    cudaFuncSetAttribute(flash_attn, cudaFuncAttributeMaxDynamicSharedMemorySize,
                         FA_SMEM);

    // 0) convert activations, transpose+convert weights (fp16 K-major)
    f2h_kernel<<<(S_IMG * DMODEL) / 1024, 256>>>(hidden, hh);
    f2h_kernel<<<(S_TXT * DMODEL) / 1024, 256>>>(enc, eh);
    transpose64<<<dim3(D3/64, DMODEL/64), 256>>>(w_qkv,     wtq,  DMODEL, D3);
    transpose64<<<dim3(D3/64, DMODEL/64), 256>>>(w_add_qkv, wtaq, DMODEL, D3);
    transpose64<<<dim3(DMODEL/64, DMODEL/64), 256>>>(w_out,     wto,  DMODEL, DMODEL);
    transpose64<<<dim3(DMODEL/64, DMODEL/64), 256>>>(w_add_out, wtao, DMODEL, DMODEL);

    // 1) qkv = hidden @ w_qkv            (fp16 out, 256x128 tiles)
    gemm_nt_big<<<dim3(D3/128, S_IMG/256), 256, BGEMM_SMEM>>>(
        hh, wtq, nullptr, qkvh, DMODEL, DMODEL, DMODEL, D3, 1);

    // 2) eqkv = enc @ w_add_qkv + b      (fp16 out, 128x128 tiles)
    gemm_nt_h<<<dim3(D3/128, S_TXT/128, 1), 256, GEMM_SMEM_BYTES>>>(
        eh, wtaq, b_add_qkv, eqkvh, DMODEL, DMODEL, DMODEL, D3, 0, 0, 0, 1);

    // 3) RMSNorm + RoPE -> fp16 q,k and fp16 V^T
    fuse_norm_rope<<<dim3(S_TOT, NHEADS), 128>>>(
        qkvh, eqkvh, ids, norm_q_w, norm_k_w, norm_aq_w, norm_ak_w, qh, kh, vt);

    // 4) fused attention -> attnh fp16 [S, 3072]
    flash_attn<<<dim3(S_TOT/128, NHEADS), 256, FA_SMEM>>>(qh, kh, vt, attnh);

    // 5) img_out = attn[512:] @ w_out + b_out     (256x128 tiles)
    gemm_nt_big<<<dim3(DMODEL/128, S_IMG/256), 256, BGEMM_SMEM>>>(
        attnh + (size_t)S_TXT * DMODEL, wto, b_out, out,
        DMODEL, DMODEL, DMODEL, DMODEL, 0);

    // 6) enc_out = attn[:512] @ w_add_out + b_add_out  (128x128 tiles)
    gemm_nt_h<<<dim3(DMODEL/128, S_TXT/128, 1), 256, GEMM_SMEM_BYTES>>>(
        attnh, wtao, b_add_out, out + (size_t)S_IMG * DMODEL,
        DMODEL, DMODEL, DMODEL, DMODEL, 0, 0, 0, 0);
}

// round 10
// speedup vs baseline: 1.0992x; 1.0992x over previous
#include <cuda_runtime.h>
#include <cuda_fp16.h>
#include <cstdint>
#include <math.h>

// ---------------------------------------------------------------------------
// Problem constants (Flux dual-stream attention block)
// ---------------------------------------------------------------------------
#define S_TXT   512
#define S_IMG   2048
#define S_TOT   2560
#define DMODEL  3072
#define NHEADS  24
#define DH      128
#define D3      9216

// ---------------------------------------------------------------------------
// Scratch (device globals -- allocation is forbidden)
// ---------------------------------------------------------------------------
__device__ __align__(256) __half g_qkvh [(size_t)S_IMG * D3];
__device__ __align__(256) __half g_eqkvh[(size_t)S_TXT * D3];
__device__ __align__(256) __half g_hh   [(size_t)S_IMG * DMODEL];
__device__ __align__(256) __half g_eh   [(size_t)S_TXT * DMODEL];
__device__ __align__(256) __half g_qh   [(size_t)S_TOT * DMODEL];
__device__ __align__(256) __half g_kh   [(size_t)S_TOT * DMODEL];
__device__ __align__(256) __half g_vt   [(size_t)DMODEL * S_TOT];
__device__ __align__(256) __half g_attnh[(size_t)S_TOT * DMODEL];
__device__ __align__(256) __half g_wtq  [(size_t)D3 * DMODEL];
__device__ __align__(256) __half g_wtaq [(size_t)D3 * DMODEL];
__device__ __align__(256) __half g_wto  [(size_t)DMODEL * DMODEL];
__device__ __align__(256) __half g_wtao [(size_t)DMODEL * DMODEL];

// ---------------------------------------------------------------------------
// helpers
// ---------------------------------------------------------------------------
__device__ __forceinline__ uint32_t smem_u32(const void* p) {
    uint32_t a;
    asm("{ .reg .u64 t; cvta.to.shared.u64 t, %1; cvt.u32.u64 %0, t; }" : "=r"(a) : "l"(p));
    return a;
}
__device__ __forceinline__ uint32_t packh2(float lo, float hi) {
    uint32_t r;
    asm("cvt.rn.f16x2.f32 %0, %1, %2;" : "=r"(r) : "f"(hi), "f"(lo));
    return r;
}
__device__ __forceinline__ uint32_t ex2h2(uint32_t x) {
    uint32_t r;
    asm("ex2.approx.f16x2 %0, %1;" : "=r"(r) : "r"(x));
    return r;
}
__device__ __forceinline__ void cp16(uint32_t saddr, const void* gptr) {
    asm volatile("cp.async.cg.shared.global [%0], [%1], 16;" :: "r"(saddr), "l"(gptr));
}
__device__ __forceinline__ void ldmx4(uint4& f, uint32_t addr) {
    asm volatile("ldmatrix.sync.aligned.m8n8.x4.shared.b16 {%0,%1,%2,%3}, [%4];"
                 : "=r"(f.x), "=r"(f.y), "=r"(f.z), "=r"(f.w) : "r"(addr));
}
#define MMA16816(acc, a, b0, b1)                                               \
    asm volatile("mma.sync.aligned.m16n8k16.row.col.f32.f16.f16.f32 "          \
                 "{%0,%1,%2,%3}, {%4,%5,%6,%7}, {%8,%9}, {%0,%1,%2,%3};"       \
                 : "+f"((acc)[0]), "+f"((acc)[1]), "+f"((acc)[2]), "+f"((acc)[3]) \
                 : "r"((a).x), "r"((a).y), "r"((a).z), "r"((a).w),             \
                   "r"(b0), "r"(b1))

// ---------------------------------------------------------------------------
// fp16 cp.async NT GEMM, 128x128 tile (proven R6 design)
// ---------------------------------------------------------------------------
#define STAGE_BYTES 16384
#define GEMM_SMEM_BYTES (4 * STAGE_BYTES)

__global__ __launch_bounds__(256)
void gemm_nt_h(const __half* __restrict__ A, const __half* __restrict__ B,
               const float* __restrict__ bias, void* __restrict__ Cv,
               int K, int lda, int ldb, int ldc,
               long long sA, long long sB, long long sC, int out_half)
{
    extern __shared__ char smem[];
    const uint32_t sbase = smem_u32(smem);
    const int tid    = threadIdx.x;
    const int lane   = tid & 31;
    const int wid    = tid >> 5;
    const int warp_m = wid >> 2;
    const int warp_n = wid & 3;
    const int bm     = blockIdx.y * 128;
    const int bn     = blockIdx.x * 128;

    A += (size_t)blockIdx.z * sA + (size_t)bm * lda;
    B += (size_t)blockIdx.z * sB + (size_t)bn * ldb;

    uint32_t soff[2];
    size_t   goa[2], gob[2];
#pragma unroll
    for (int j = 0; j < 2; j++) {
        const int c  = tid + j * 256;
        const int r  = c >> 2;
        const int kc = c & 3;
        const int sw = kc ^ ((r >> 1) & 3);
        soff[j] = (uint32_t)(r * 64 + sw * 16);
        goa[j]  = (size_t)r * lda + kc * 8;
        gob[j]  = (size_t)r * ldb + kc * 8;
    }

    const int T = K >> 5;

#pragma unroll
    for (int s = 0; s < 3; s++) {
        const uint32_t sa = sbase + s * STAGE_BYTES;
        if (s < T) {
#pragma unroll
            for (int j = 0; j < 2; j++) {
                cp16(sa + soff[j],        A + goa[j] + s * 32);
                cp16(sa + 8192 + soff[j], B + gob[j] + s * 32);
            }
        }
        asm volatile("cp.async.commit_group;");
    }

    float acc[4][4][4];
#pragma unroll
    for (int m = 0; m < 4; m++)
#pragma unroll
        for (int n = 0; n < 4; n++)
#pragma unroll
            for (int x = 0; x < 4; x++) acc[m][n][x] = 0.0f;

    const int p    = lane >> 3;
    const int li   = lane & 7;
    const int rA0  = warp_m * 64 + (p & 1) * 8 + li;
    const int rB0  = warp_n * 32 + (p & 1) * 8 + li;
    const int kaddp = p >> 1;

    for (int t = 0; t < T; t++) {
        asm volatile("cp.async.wait_group 2;");
        __syncthreads();
        {
            const int kt = t + 3;
            const uint32_t sa = sbase + (kt & 3) * STAGE_BYTES;
            if (kt < T) {
#pragma unroll
                for (int j = 0; j < 2; j++) {
                    cp16(sa + soff[j],        A + goa[j] + (size_t)kt * 32);
                    cp16(sa + 8192 + soff[j], B + gob[j] + (size_t)kt * 32);
                }
            }
            asm volatile("cp.async.commit_group;");
        }

        const uint32_t st = sbase + (t & 3) * STAGE_BYTES;
#pragma unroll
        for (int ks = 0; ks < 2; ks++) {
            const int kc = ks * 2 + kaddp;
            uint4 af[4];
#pragma unroll
            for (int mt = 0; mt < 4; mt++) {
                const int row = rA0 + mt * 16;
                const int sw  = kc ^ ((row >> 1) & 3);
                ldmx4(af[mt], st + row * 64 + sw * 16);
            }
            uint4 bq[2];
#pragma unroll
            for (int ntp = 0; ntp < 2; ntp++) {
                const int row = rB0 + ntp * 16;
                const int sw  = kc ^ ((row >> 1) & 3);
                ldmx4(bq[ntp], st + 8192 + row * 64 + sw * 16);
            }
            uint2 bf[4];
            bf[0] = make_uint2(bq[0].x, bq[0].z);
            bf[1] = make_uint2(bq[0].y, bq[0].w);
            bf[2] = make_uint2(bq[1].x, bq[1].z);
            bf[3] = make_uint2(bq[1].y, bq[1].w);
#pragma unroll
            for (int m = 0; m < 4; m++)
#pragma unroll
                for (int n = 0; n < 4; n++)
                    MMA16816(acc[m][n], af[m], bf[n].x, bf[n].y);
        }
        __syncthreads();
    }

    const int g  = lane >> 2;
    const int tg = lane & 3;
    if (out_half) {
        __half* C = (__half*)Cv + (size_t)blockIdx.z * sC;
#pragma unroll
        for (int m = 0; m < 4; m++) {
            const int row0 = bm + warp_m * 64 + m * 16 + g;
#pragma unroll
            for (int n = 0; n < 4; n++) {
                const int col = bn + warp_n * 32 + n * 8 + tg * 2;
                float bx = 0.f, by = 0.f;
                if (bias) { bx = bias[col]; by = bias[col + 1]; }
                *(uint32_t*)(C + (size_t)row0 * ldc + col) =
                    packh2(acc[m][n][0] + bx, acc[m][n][1] + by);
                *(uint32_t*)(C + (size_t)(row0 + 8) * ldc + col) =
                    packh2(acc[m][n][2] + bx, acc[m][n][3] + by);
            }
        }
    } else {
        float* C = (float*)Cv + (size_t)blockIdx.z * sC;
#pragma unroll
        for (int m = 0; m < 4; m++) {
            const int row0 = bm + warp_m * 64 + m * 16 + g;
#pragma unroll
            for (int n = 0; n < 4; n++) {
                const int col = bn + warp_n * 32 + n * 8 + tg * 2;
                float bx = 0.f, by = 0.f;
                if (bias) { bx = bias[col]; by = bias[col + 1]; }
                *(float2*)(C + (size_t)row0 * ldc + col) =
                    make_float2(acc[m][n][0] + bx, acc[m][n][1] + by);
                *(float2*)(C + (size_t)(row0 + 8) * ldc + col) =
                    make_float2(acc[m][n][2] + bx, acc[m][n][3] + by);
            }
        }
    }
}

// ---------------------------------------------------------------------------
// Fused flash attention (R8 version: log2 softmax, ex2.f16x2, mma row sums)
// ---------------------------------------------------------------------------
#define FA_QSM    32768
#define FA_KBYTES 32768
#define FA_VSEC   9216
#define FA_VBYTES (4 * FA_VSEC)
#define FA_KV     (FA_KBYTES + FA_VBYTES)
#define FA_SMEM   (FA_QSM + 2 * FA_KV)
#define NBLK      (S_TOT / 128)

__global__ __launch_bounds__(256)
void flash_attn(const __half* __restrict__ Qg, const __half* __restrict__ Kg,
                const __half* __restrict__ VTg, __half* __restrict__ Og)
{
    extern __shared__ char smem[];
    const uint32_t sbase = smem_u32(smem);
    const int tid  = threadIdx.x;
    const int lane = tid & 31;
    const int wid  = tid >> 5;
    const int qb   = blockIdx.x;
    const int h    = blockIdx.y;

    uint32_t soff[2];
    int rr[2], kc8[2];
#pragma unroll
    for (int j = 0; j < 2; j++) {
        const int c  = tid + j * 256;
        const int r  = c >> 2;
        const int kc = c & 3;
        soff[j] = (uint32_t)(r * 64 + (kc ^ ((r >> 1) & 3)) * 16);
        rr[j]   = r;
        kc8[j]  = kc * 8;
    }

    const __half* Qp = Qg + (size_t)(qb * 128) * DMODEL + h * DH;
    const __half* Kp = Kg + h * DH;
    const __half* Vp = VTg + (size_t)(h * DH) * S_TOT;

#pragma unroll
    for (int bs = 0; bs < 8; bs++) {
        const int buf = bs >> 2;
        const int sec = bs & 3;
        const uint32_t base = FA_QSM + buf * FA_KV + FA_KBYTES
                            + sec * FA_VSEC + 128 * 64;
        const int w = tid;
        *(uint32_t*)(smem + base + w * 4) = (w < 16) ? 0x3C003C00u : 0u;
    }

#pragma unroll
    for (int sec = 0; sec < 4; sec++)
#pragma unroll
        for (int j = 0; j < 2; j++)
            cp16(sbase + sec * 8192 + soff[j],
                 Qp + (size_t)rr[j] * DMODEL + sec * 32 + kc8[j]);
    {
        const uint32_t kb = sbase + FA_QSM;
        const uint32_t vb = kb + FA_KBYTES;
#pragma unroll
        for (int sec = 0; sec < 4; sec++)
#pragma unroll
            for (int j = 0; j < 2; j++) {
                cp16(kb + sec * 8192 + soff[j],
                     Kp + (size_t)rr[j] * DMODEL + sec * 32 + kc8[j]);
                cp16(vb + sec * FA_VSEC + soff[j],
                     Vp + (size_t)rr[j] * S_TOT + sec * 32 + kc8[j]);
            }
    }
    asm volatile("cp.async.commit_group;");
    {
        const uint32_t kb = sbase + FA_QSM + FA_KV;
        const uint32_t vb = kb + FA_KBYTES;
#pragma unroll
        for (int sec = 0; sec < 4; sec++)
#pragma unroll
            for (int j = 0; j < 2; j++) {
                cp16(kb + sec * 8192 + soff[j],
                     Kp + (size_t)(128 + rr[j]) * DMODEL + sec * 32 + kc8[j]);
                cp16(vb + sec * FA_VSEC + soff[j],
                     Vp + (size_t)rr[j] * S_TOT + 128 + sec * 32 + kc8[j]);
            }
    }
    asm volatile("cp.async.commit_group;");

    const int p     = lane >> 3;
    const int li    = lane & 7;
    const int kaddp = p >> 1;
    const int rowQ  = wid * 16 + (p & 1) * 8 + li;
    const int rB0   = (p & 1) * 8 + li;
    const int g     = lane >> 2;
    const int tg    = lane & 3;

    float mrow[2] = {-1e30f, -1e30f};
    float o[18][4];
#pragma unroll
    for (int j = 0; j < 18; j++)
#pragma unroll
        for (int x = 0; x < 4; x++) o[j][x] = 0.f;
    uint4 qf[8];

    for (int jb = 0; jb < NBLK; jb++) {
        asm volatile("cp.async.wait_group 1;");
        __syncthreads();

        if (jb == 0) {
#pragma unroll
            for (int kc = 0; kc < 8; kc++) {
                const int sec = kc >> 1;
                const int c   = (kc & 1) * 2 + kaddp;
                const int sw  = c ^ ((rowQ >> 1) & 3);
                ldmx4(qf[kc], sbase + sec * 8192 + rowQ * 64 + sw * 16);
            }
        }

        const uint32_t kb = sbase + FA_QSM + (jb & 1) * FA_KV;
        const uint32_t vb = kb + FA_KBYTES;

        float sacc[16][4];
#pragma unroll
        for (int j = 0; j < 16; j++)
#pragma unroll
            for (int x = 0; x < 4; x++) sacc[j][x] = 0.f;
#pragma unroll
        for (int kc = 0; kc < 8; kc++) {
            const int sec = kc >> 1;
            const int c   = (kc & 1) * 2 + kaddp;
#pragma unroll
            for (int np = 0; np < 8; np++) {
                const int row = np * 16 + rB0;
                const int sw  = c ^ ((row >> 1) & 3);
                uint4 bq;
                ldmx4(bq, kb + sec * 8192 + row * 64 + sw * 16);
                MMA16816(sacc[np * 2],     qf[kc], bq.x, bq.z);
                MMA16816(sacc[np * 2 + 1], qf[kc], bq.y, bq.w);
            }
        }

        float mx0 = -1e30f, mx1 = -1e30f;
#pragma unroll
        for (int j = 0; j < 16; j++) {
            mx0 = fmaxf(mx0, fmaxf(sacc[j][0], sacc[j][1]));
            mx1 = fmaxf(mx1, fmaxf(sacc[j][2], sacc[j][3]));
        }
        mx0 = fmaxf(mx0, __shfl_xor_sync(0xffffffffu, mx0, 1));
        mx0 = fmaxf(mx0, __shfl_xor_sync(0xffffffffu, mx0, 2));
        mx1 = fmaxf(mx1, __shfl_xor_sync(0xffffffffu, mx1, 1));
        mx1 = fmaxf(mx1, __shfl_xor_sync(0xffffffffu, mx1, 2));

        const float mn0 = fmaxf(mrow[0], mx0);
        const float mn1 = fmaxf(mrow[1], mx1);
        const float sc0 = exp2f(mrow[0] - mn0);
        const float sc1 = exp2f(mrow[1] - mn1);
        mrow[0] = mn0; mrow[1] = mn1;

        uint32_t pf[16][2];
#pragma unroll
        for (int j = 0; j < 16; j++) {
            pf[j][0] = ex2h2(packh2(sacc[j][0] - mn0, sacc[j][1] - mn0));
            pf[j][1] = ex2h2(packh2(sacc[j][2] - mn1, sacc[j][3] - mn1));
        }
#pragma unroll
        for (int j = 0; j < 18; j++) {
            o[j][0] *= sc0; o[j][1] *= sc0;
            o[j][2] *= sc1; o[j][3] *= sc1;
        }

#pragma unroll
        for (int kc = 0; kc < 8; kc++) {
            const int sec = kc >> 1;
            const int c   = (kc & 1) * 2 + kaddp;
            uint4 a;
            a.x = pf[kc * 2][0];
            a.y = pf[kc * 2][1];
            a.z = pf[kc * 2 + 1][0];
            a.w = pf[kc * 2 + 1][1];
#pragma unroll
            for (int np = 0; np < 9; np++) {
                const int row = np * 16 + rB0;
                const int sw  = c ^ ((row >> 1) & 3);
                uint4 bq;
                ldmx4(bq, vb + sec * FA_VSEC + row * 64 + sw * 16);
                MMA16816(o[np * 2],     a, bq.x, bq.z);
                MMA16816(o[np * 2 + 1], a, bq.y, bq.w);
            }
        }

        __syncthreads();

        const int nb = jb + 2;
        if (nb < NBLK) {
            const uint32_t nkb = sbase + FA_QSM + (nb & 1) * FA_KV;
            const uint32_t nvb = nkb + FA_KBYTES;
#pragma unroll
            for (int sec = 0; sec < 4; sec++)
#pragma unroll
                for (int j = 0; j < 2; j++) {
                    cp16(nkb + sec * 8192 + soff[j],
                         Kp + (size_t)(nb * 128 + rr[j]) * DMODEL + sec * 32 + kc8[j]);
                    cp16(nvb + sec * FA_VSEC + soff[j],
                         Vp + (size_t)rr[j] * S_TOT + nb * 128 + sec * 32 + kc8[j]);
                }
        }
        asm volatile("cp.async.commit_group;");
    }

    const float l0 = __shfl_sync(0xffffffffu, o[16][0], lane & 28);
    const float l1 = __shfl_sync(0xffffffffu, o[16][2], lane & 28);
    const float inv0 = 1.0f / l0;
    const float inv1 = 1.0f / l1;
    __half* Op = Og + (size_t)(qb * 128) * DMODEL + h * DH;
#pragma unroll
    for (int j = 0; j < 16; j++) {
        const int col  = j * 8 + tg * 2;
        const int row0 = wid * 16 + g;
        *(uint32_t*)(Op + (size_t)row0 * DMODEL + col) =
            packh2(o[j][0] * inv0, o[j][1] * inv0);
        *(uint32_t*)(Op + (size_t)(row0 + 8) * DMODEL + col) =
            packh2(o[j][2] * inv1, o[j][3] * inv1);
    }
}

// ---------------------------------------------------------------------------
// float -> half elementwise
// ---------------------------------------------------------------------------
__global__ __launch_bounds__(256)
void f2h_kernel(const float* __restrict__ in, __half* __restrict__ out)
{
    const size_t i = ((size_t)blockIdx.x * 256 + threadIdx.x) * 4;
    float4 v = *(const float4*)(in + i);
    *(uint2*)(out + i) = make_uint2(packh2(v.x, v.y), packh2(v.z, v.w));
}

// ---------------------------------------------------------------------------
// 64x64 vectorized transpose fp32 -> fp16 (63% HBM; best so far)
// ---------------------------------------------------------------------------
__global__ __launch_bounds__(256)
void transpose64(const float* __restrict__ in, __half* __restrict__ out,
                 int R, int C)
{
    __shared__ float t[64][65];
    const int bx  = blockIdx.x * 64;
    const int by  = blockIdx.y * 64;
    const int tx4 = (threadIdx.x & 15) * 4;
    const int ty  = threadIdx.x >> 4;
#pragma unroll
    for (int j = 0; j < 4; j++) {
        const int row = ty + j * 16;
        float4 v = *(const float4*)(in + (size_t)(by + row) * C + bx + tx4);
        t[row][tx4 + 0] = v.x; t[row][tx4 + 1] = v.y;
        t[row][tx4 + 2] = v.z; t[row][tx4 + 3] = v.w;
    }
    __syncthreads();
#pragma unroll
    for (int j = 0; j < 4; j++) {
        const int orow = ty + j * 16;
        uint2 w = make_uint2(
            packh2(t[tx4 + 0][orow], t[tx4 + 1][orow]),
            packh2(t[tx4 + 2][orow], t[tx4 + 3][orow]));
        *(uint2*)(out + (size_t)(bx + orow) * R + by + tx4) = w;
    }
}

// ---------------------------------------------------------------------------
// Fused RMSNorm + RoPE (fp16 in) -> fp16 q (scale*log2e), k, V^T
// ---------------------------------------------------------------------------
__device__ __forceinline__ float warp_sum(float v) {
#pragma unroll
    for (int o = 16; o > 0; o >>= 1) v += __shfl_xor_sync(0xffffffffu, v, o);
    return v;
}

__global__ __launch_bounds__(128)
void fuse_norm_rope(const __half* __restrict__ qkv, const __half* __restrict__ eqkv,
                    const int* __restrict__ ids,
                    const float* __restrict__ nq_w,  const float* __restrict__ nk_w,
                    const float* __restrict__ naq_w, const float* __restrict__ nak_w,
                    __half* __restrict__ Q, __half* __restrict__ Ko,
                    __half* __restrict__ VT)
{
    const int s = blockIdx.x;
    const int h = blockIdx.y;
    const int d = threadIdx.x;

    const __half* src;
    const float* qw;
    const float* kw;
    if (s < S_TXT) { src = eqkv + (size_t)s * D3;           qw = naq_w; kw = nak_w; }
    else           { src = qkv  + (size_t)(s - S_TXT) * D3; qw = nq_w;  kw = nk_w; }

    float qv = __half2float(src[h * DH + d]);
    float kv = __half2float(src[DMODEL   + h * DH + d]);
    float vv = __half2float(src[2*DMODEL + h * DH + d]);

    __shared__ float sq[4], sk[4];
    float wq = warp_sum(qv * qv);
    float wk = warp_sum(kv * kv);
    const int w = d >> 5;
    if ((d & 31) == 0) { sq[w] = wq; sk[w] = wk; }
    __syncthreads();
    float qsum = sq[0] + sq[1] + sq[2] + sq[3];
    float ksum = sk[0] + sk[1] + sk[2] + sk[3];
    float qn = qv * rsqrtf(qsum * (1.0f / DH) + 1e-5f) * qw[d];
    float kn = kv * rsqrtf(ksum * (1.0f / DH) + 1e-5f) * kw[d];

    const int pr = d >> 1;
    int axis, base, dax;
    if      (pr < 8)  { axis = 0; base = 0;  dax = 16; }
    else if (pr < 36) { axis = 1; base = 8;  dax = 56; }
    else              { axis = 2; base = 36; dax = 56; }
    float e    = (2.0f * (float)(pr - base)) / (float)dax;
    float freq = expf(-e * 9.210340371976184f);
    float pos  = (float)ids[s * 3 + axis];
    float ang  = pos * freq;
    float cs, sn;
    sincosf(ang, &sn, &cs);

    float q_other = __shfl_xor_sync(0xffffffffu, qn, 1);
    float k_other = __shfl_xor_sync(0xffffffffu, kn, 1);
    float qr, kr;
    if (d & 1) { qr = qn * cs + q_other * sn; kr = kn * cs + k_other * sn; }
    else       { qr = qn * cs - q_other * sn; kr = kn * cs - k_other * sn; }

    const size_t o = (size_t)s * DMODEL + h * DH + d;
    Q[o]  = __float2half(qr * (0.08838834764831845f * 1.4426950408889634f));
    Ko[o] = __float2half(kr);
    VT[(size_t)(h * DH + d) * S_TOT + s] = __float2half(vv);
}

// ---------------------------------------------------------------------------
// kernel_launch
// ---------------------------------------------------------------------------
extern "C" void kernel_launch(void* const* d_in, const int* in_sizes, int n_in,
                              void* d_out, int out_size)
{
    const float* hidden     = (const float*)d_in[0];
    const float* enc        = (const float*)d_in[1];
    const int*   ids        = (const int*)  d_in[2];
    const float* w_qkv      = (const float*)d_in[3];
    const float* w_add_qkv  = (const float*)d_in[4];
    const float* b_add_qkv  = (const float*)d_in[5];
    const float* w_out      = (const float*)d_in[6];
    const float* b_out      = (const float*)d_in[7];
    const float* w_add_out  = (const float*)d_in[8];
    const float* b_add_out  = (const float*)d_in[9];
    const float* norm_q_w   = (const float*)d_in[10];
    const float* norm_k_w   = (const float*)d_in[11];
    const float* norm_aq_w  = (const float*)d_in[12];
    const float* norm_ak_w  = (const float*)d_in[13];
    float* out = (float*)d_out;

    __half *qkvh, *eqkvh, *hh, *eh, *qh, *kh, *vt, *attnh, *wtq, *wtaq, *wto, *wtao;
    cudaGetSymbolAddress((void**)&qkvh,  g_qkvh);
    cudaGetSymbolAddress((void**)&eqkvh, g_eqkvh);
    cudaGetSymbolAddress((void**)&hh,    g_hh);
    cudaGetSymbolAddress((void**)&eh,    g_eh);
    cudaGetSymbolAddress((void**)&qh,    g_qh);
    cudaGetSymbolAddress((void**)&kh,    g_kh);
    cudaGetSymbolAddress((void**)&vt,    g_vt);
    cudaGetSymbolAddress((void**)&attnh, g_attnh);
    cudaGetSymbolAddress((void**)&wtq,   g_wtq);
    cudaGetSymbolAddress((void**)&wtaq,  g_wtaq);
    cudaGetSymbolAddress((void**)&wto,   g_wto);
    cudaGetSymbolAddress((void**)&wtao,  g_wtao);

    cudaFuncSetAttribute(gemm_nt_h, cudaFuncAttributeMaxDynamicSharedMemorySize,
                         GEMM_SMEM_BYTES);
    cudaFuncSetAttribute(flash_attn, cudaFuncAttributeMaxDynamicSharedMemorySize,
                         FA_SMEM);

    // 0) convert activations, transpose+convert weights (fp16 K-major)
    f2h_kernel<<<(S_IMG * DMODEL) / 1024, 256>>>(hidden, hh);
    f2h_kernel<<<(S_TXT * DMODEL) / 1024, 256>>>(enc, eh);
    transpose64<<<dim3(D3/64, DMODEL/64), 256>>>(w_qkv,     wtq,  DMODEL, D3);
    transpose64<<<dim3(D3/64, DMODEL/64), 256>>>(w_add_qkv, wtaq, DMODEL, D3);
    transpose64<<<dim3(DMODEL/64, DMODEL/64), 256>>>(w_out,     wto,  DMODEL, DMODEL);
    transpose64<<<dim3(DMODEL/64, DMODEL/64), 256>>>(w_add_out, wtao, DMODEL, DMODEL);

    // 1) qkv = hidden @ w_qkv            (fp16 out, 128x128 tiles)
    gemm_nt_h<<<dim3(D3/128, S_IMG/128, 1), 256, GEMM_SMEM_BYTES>>>(
        hh, wtq, nullptr, qkvh, DMODEL, DMODEL, DMODEL, D3, 0, 0, 0, 1);

    // 2) eqkv = enc @ w_add_qkv + b      (fp16 out)
    gemm_nt_h<<<dim3(D3/128, S_TXT/128, 1), 256, GEMM_SMEM_BYTES>>>(
        eh, wtaq, b_add_qkv, eqkvh, DMODEL, DMODEL, DMODEL, D3, 0, 0, 0, 1);

    // 3) RMSNorm + RoPE -> fp16 q,k and fp16 V^T
    fuse_norm_rope<<<dim3(S_TOT, NHEADS), 128>>>(
        qkvh, eqkvh, ids, norm_q_w, norm_k_w, norm_aq_w, norm_ak_w, qh, kh, vt);

    // 4) fused attention -> attnh fp16 [S, 3072]
    flash_attn<<<dim3(S_TOT/128, NHEADS), 256, FA_SMEM>>>(qh, kh, vt, attnh);

    // 5) img_out = attn[512:] @ w_out + b_out
    gemm_nt_h<<<dim3(DMODEL/128, S_IMG/128, 1), 256, GEMM_SMEM_BYTES>>>(
        attnh + (size_t)S_TXT * DMODEL, wto, b_out, out,
        DMODEL, DMODEL, DMODEL, DMODEL, 0, 0, 0, 0);

    // 6) enc_out = attn[:512] @ w_add_out + b_add_out
    gemm_nt_h<<<dim3(DMODEL/128, S_TXT/128, 1), 256, GEMM_SMEM_BYTES>>>(
        attnh, wtao, b_add_out, out + (size_t)S_IMG * DMODEL,
        DMODEL, DMODEL, DMODEL, DMODEL, 0, 0, 0, 0);
}

// round 11
// speedup vs baseline: 1.1305x; 1.0285x over previous
#include <cuda_runtime.h>
#include <cuda_fp16.h>
#include <cstdint>
#include <math.h>

// ---------------------------------------------------------------------------
// Problem constants (Flux dual-stream attention block)
// ---------------------------------------------------------------------------
#define S_TXT   512
#define S_IMG   2048
#define S_TOT   2560
#define DMODEL  3072
#define NHEADS  24
#define DH      128
#define D3      9216

// ---------------------------------------------------------------------------
// Scratch (device globals -- allocation is forbidden)
// ---------------------------------------------------------------------------
__device__ __align__(256) __half g_qkvh [(size_t)S_IMG * D3];
__device__ __align__(256) __half g_eqkvh[(size_t)S_TXT * D3];
__device__ __align__(256) __half g_hh   [(size_t)S_IMG * DMODEL];
__device__ __align__(256) __half g_eh   [(size_t)S_TXT * DMODEL];
__device__ __align__(256) __half g_qh   [(size_t)S_TOT * DMODEL];
__device__ __align__(256) __half g_kh   [(size_t)S_TOT * DMODEL];
__device__ __align__(256) __half g_vt   [(size_t)DMODEL * S_TOT];
__device__ __align__(256) __half g_attnh[(size_t)S_TOT * DMODEL];
__device__ __align__(256) __half g_wtq  [(size_t)D3 * DMODEL];
__device__ __align__(256) __half g_wtaq [(size_t)D3 * DMODEL];
__device__ __align__(256) __half g_wto  [(size_t)DMODEL * DMODEL];
__device__ __align__(256) __half g_wtao [(size_t)DMODEL * DMODEL];

// ---------------------------------------------------------------------------
// helpers
// ---------------------------------------------------------------------------
__device__ __forceinline__ uint32_t smem_u32(const void* p) {
    uint32_t a;
    asm("{ .reg .u64 t; cvta.to.shared.u64 t, %1; cvt.u32.u64 %0, t; }" : "=r"(a) : "l"(p));
    return a;
}
__device__ __forceinline__ uint32_t packh2(float lo, float hi) {
    uint32_t r;
    asm("cvt.rn.f16x2.f32 %0, %1, %2;" : "=r"(r) : "f"(hi), "f"(lo));
    return r;
}
__device__ __forceinline__ uint32_t ex2h2(uint32_t x) {
    uint32_t r;
    asm("ex2.approx.f16x2 %0, %1;" : "=r"(r) : "r"(x));
    return r;
}
__device__ __forceinline__ void cp16(uint32_t saddr, const void* gptr) {
    asm volatile("cp.async.cg.shared.global [%0], [%1], 16;" :: "r"(saddr), "l"(gptr));
}
__device__ __forceinline__ void ldmx4(uint4& f, uint32_t addr) {
    asm volatile("ldmatrix.sync.aligned.m8n8.x4.shared.b16 {%0,%1,%2,%3}, [%4];"
                 : "=r"(f.x), "=r"(f.y), "=r"(f.z), "=r"(f.w) : "r"(addr));
}
#define MMA16816(acc, a, b0, b1)                                               \
    asm volatile("mma.sync.aligned.m16n8k16.row.col.f32.f16.f16.f32 "          \
                 "{%0,%1,%2,%3}, {%4,%5,%6,%7}, {%8,%9}, {%0,%1,%2,%3};"       \
                 : "+f"((acc)[0]), "+f"((acc)[1]), "+f"((acc)[2]), "+f"((acc)[3]) \
                 : "r"((a).x), "r"((a).y), "r"((a).z), "r"((a).w),             \
                   "r"(b0), "r"(b1))

// ---------------------------------------------------------------------------
// fp16 cp.async NT GEMM, 128x128 tile.
// R11: single __syncthreads per k-iter (bottom barrier removed -- the top
// barrier after wait_group already orders all reads of the stage about to be
// overwritten, since that stage was last read before the previous barrier).
// ---------------------------------------------------------------------------
#define STAGE_BYTES 16384
#define GEMM_SMEM_BYTES (4 * STAGE_BYTES)

__global__ __launch_bounds__(256, 2)
void gemm_nt_h(const __half* __restrict__ A, const __half* __restrict__ B,
               const float* __restrict__ bias, void* __restrict__ Cv,
               int K, int lda, int ldb, int ldc,
               long long sA, long long sB, long long sC, int out_half)
{
    extern __shared__ char smem[];
    const uint32_t sbase = smem_u32(smem);
    const int tid    = threadIdx.x;
    const int lane   = tid & 31;
    const int wid    = tid >> 5;
    const int warp_m = wid >> 2;
    const int warp_n = wid & 3;
    const int bm     = blockIdx.y * 128;
    const int bn     = blockIdx.x * 128;

    A += (size_t)blockIdx.z * sA + (size_t)bm * lda;
    B += (size_t)blockIdx.z * sB + (size_t)bn * ldb;

    uint32_t soff[2];
    size_t   goa[2], gob[2];
#pragma unroll
    for (int j = 0; j < 2; j++) {
        const int c  = tid + j * 256;
        const int r  = c >> 2;
        const int kc = c & 3;
        const int sw = kc ^ ((r >> 1) & 3);
        soff[j] = (uint32_t)(r * 64 + sw * 16);
        goa[j]  = (size_t)r * lda + kc * 8;
        gob[j]  = (size_t)r * ldb + kc * 8;
    }

    const int T = K >> 5;

#pragma unroll
    for (int s = 0; s < 3; s++) {
        const uint32_t sa = sbase + s * STAGE_BYTES;
        if (s < T) {
#pragma unroll
            for (int j = 0; j < 2; j++) {
                cp16(sa + soff[j],        A + goa[j] + s * 32);
                cp16(sa + 8192 + soff[j], B + gob[j] + s * 32);
            }
        }
        asm volatile("cp.async.commit_group;");
    }

    float acc[4][4][4];
#pragma unroll
    for (int m = 0; m < 4; m++)
#pragma unroll
        for (int n = 0; n < 4; n++)
#pragma unroll
            for (int x = 0; x < 4; x++) acc[m][n][x] = 0.0f;

    const int p    = lane >> 3;
    const int li   = lane & 7;
    const int rA0  = warp_m * 64 + (p & 1) * 8 + li;
    const int rB0  = warp_n * 32 + (p & 1) * 8 + li;
    const int kaddp = p >> 1;

    for (int t = 0; t < T; t++) {
        asm volatile("cp.async.wait_group 2;");
        __syncthreads();          // sole barrier: orders stage-t visibility AND
                                  // completion of stage t-1 reads by all threads
        {
            const int kt = t + 3;
            const uint32_t sa = sbase + (kt & 3) * STAGE_BYTES;
            if (kt < T) {
#pragma unroll
                for (int j = 0; j < 2; j++) {
                    cp16(sa + soff[j],        A + goa[j] + (size_t)kt * 32);
                    cp16(sa + 8192 + soff[j], B + gob[j] + (size_t)kt * 32);
                }
            }
            asm volatile("cp.async.commit_group;");
        }

        const uint32_t st = sbase + (t & 3) * STAGE_BYTES;
#pragma unroll
        for (int ks = 0; ks < 2; ks++) {
            const int kc = ks * 2 + kaddp;
            uint4 af[4];
#pragma unroll
            for (int mt = 0; mt < 4; mt++) {
                const int row = rA0 + mt * 16;
                const int sw  = kc ^ ((row >> 1) & 3);
                ldmx4(af[mt], st + row * 64 + sw * 16);
            }
            uint4 bq[2];
#pragma unroll
            for (int ntp = 0; ntp < 2; ntp++) {
                const int row = rB0 + ntp * 16;
                const int sw  = kc ^ ((row >> 1) & 3);
                ldmx4(bq[ntp], st + 8192 + row * 64 + sw * 16);
            }
            uint2 bf[4];
            bf[0] = make_uint2(bq[0].x, bq[0].z);
            bf[1] = make_uint2(bq[0].y, bq[0].w);
            bf[2] = make_uint2(bq[1].x, bq[1].z);
            bf[3] = make_uint2(bq[1].y, bq[1].w);
#pragma unroll
            for (int m = 0; m < 4; m++)
#pragma unroll
                for (int n = 0; n < 4; n++)
                    MMA16816(acc[m][n], af[m], bf[n].x, bf[n].y);
        }
    }

    const int g  = lane >> 2;
    const int tg = lane & 3;
    if (out_half) {
        __half* C = (__half*)Cv + (size_t)blockIdx.z * sC;
#pragma unroll
        for (int m = 0; m < 4; m++) {
            const int row0 = bm + warp_m * 64 + m * 16 + g;
#pragma unroll
            for (int n = 0; n < 4; n++) {
                const int col = bn + warp_n * 32 + n * 8 + tg * 2;
                float bx = 0.f, by = 0.f;
                if (bias) { bx = bias[col]; by = bias[col + 1]; }
                *(uint32_t*)(C + (size_t)row0 * ldc + col) =
                    packh2(acc[m][n][0] + bx, acc[m][n][1] + by);
                *(uint32_t*)(C + (size_t)(row0 + 8) * ldc + col) =
                    packh2(acc[m][n][2] + bx, acc[m][n][3] + by);
            }
        }
    } else {
        float* C = (float*)Cv + (size_t)blockIdx.z * sC;
#pragma unroll
        for (int m = 0; m < 4; m++) {
            const int row0 = bm + warp_m * 64 + m * 16 + g;
#pragma unroll
            for (int n = 0; n < 4; n++) {
                const int col = bn + warp_n * 32 + n * 8 + tg * 2;
                float bx = 0.f, by = 0.f;
                if (bias) { bx = bias[col]; by = bias[col + 1]; }
                *(float2*)(C + (size_t)row0 * ldc + col) =
                    make_float2(acc[m][n][0] + bx, acc[m][n][1] + by);
                *(float2*)(C + (size_t)(row0 + 8) * ldc + col) =
                    make_float2(acc[m][n][2] + bx, acc[m][n][3] + by);
            }
        }
    }
}

// ---------------------------------------------------------------------------
// Fused flash attention (unchanged from R8/R10: proven at 1112us)
// ---------------------------------------------------------------------------
#define FA_QSM    32768
#define FA_KBYTES 32768
#define FA_VSEC   9216
#define FA_VBYTES (4 * FA_VSEC)
#define FA_KV     (FA_KBYTES + FA_VBYTES)
#define FA_SMEM   (FA_QSM + 2 * FA_KV)
#define NBLK      (S_TOT / 128)

__global__ __launch_bounds__(256)
void flash_attn(const __half* __restrict__ Qg, const __half* __restrict__ Kg,
                const __half* __restrict__ VTg, __half* __restrict__ Og)
{
    extern __shared__ char smem[];
    const uint32_t sbase = smem_u32(smem);
    const int tid  = threadIdx.x;
    const int lane = tid & 31;
    const int wid  = tid >> 5;
    const int qb   = blockIdx.x;
    const int h    = blockIdx.y;

    uint32_t soff[2];
    int rr[2], kc8[2];
#pragma unroll
    for (int j = 0; j < 2; j++) {
        const int c  = tid + j * 256;
        const int r  = c >> 2;
        const int kc = c & 3;
        soff[j] = (uint32_t)(r * 64 + (kc ^ ((r >> 1) & 3)) * 16);
        rr[j]   = r;
        kc8[j]  = kc * 8;
    }

    const __half* Qp = Qg + (size_t)(qb * 128) * DMODEL + h * DH;
    const __half* Kp = Kg + h * DH;
    const __half* Vp = VTg + (size_t)(h * DH) * S_TOT;

#pragma unroll
    for (int bs = 0; bs < 8; bs++) {
        const int buf = bs >> 2;
        const int sec = bs & 3;
        const uint32_t base = FA_QSM + buf * FA_KV + FA_KBYTES
                            + sec * FA_VSEC + 128 * 64;
        const int w = tid;
        *(uint32_t*)(smem + base + w * 4) = (w < 16) ? 0x3C003C00u : 0u;
    }

#pragma unroll
    for (int sec = 0; sec < 4; sec++)
#pragma unroll
        for (int j = 0; j < 2; j++)
            cp16(sbase + sec * 8192 + soff[j],
                 Qp + (size_t)rr[j] * DMODEL + sec * 32 + kc8[j]);
    {
        const uint32_t kb = sbase + FA_QSM;
        const uint32_t vb = kb + FA_KBYTES;
#pragma unroll
        for (int sec = 0; sec < 4; sec++)
#pragma unroll
            for (int j = 0; j < 2; j++) {
                cp16(kb + sec * 8192 + soff[j],
                     Kp + (size_t)rr[j] * DMODEL + sec * 32 + kc8[j]);
                cp16(vb + sec * FA_VSEC + soff[j],
                     Vp + (size_t)rr[j] * S_TOT + sec * 32 + kc8[j]);
            }
    }
    asm volatile("cp.async.commit_group;");
    {
        const uint32_t kb = sbase + FA_QSM + FA_KV;
        const uint32_t vb = kb + FA_KBYTES;
#pragma unroll
        for (int sec = 0; sec < 4; sec++)
#pragma unroll
            for (int j = 0; j < 2; j++) {
                cp16(kb + sec * 8192 + soff[j],
                     Kp + (size_t)(128 + rr[j]) * DMODEL + sec * 32 + kc8[j]);
                cp16(vb + sec * FA_VSEC + soff[j],
                     Vp + (size_t)rr[j] * S_TOT + 128 + sec * 32 + kc8[j]);
            }
    }
    asm volatile("cp.async.commit_group;");

    const int p     = lane >> 3;
    const int li    = lane & 7;
    const int kaddp = p >> 1;
    const int rowQ  = wid * 16 + (p & 1) * 8 + li;
    const int rB0   = (p & 1) * 8 + li;
    const int g     = lane >> 2;
    const int tg    = lane & 3;

    float mrow[2] = {-1e30f, -1e30f};
    float o[18][4];
#pragma unroll
    for (int j = 0; j < 18; j++)
#pragma unroll
        for (int x = 0; x < 4; x++) o[j][x] = 0.f;
    uint4 qf[8];

    for (int jb = 0; jb < NBLK; jb++) {
        asm volatile("cp.async.wait_group 1;");
        __syncthreads();

        if (jb == 0) {
#pragma unroll
            for (int kc = 0; kc < 8; kc++) {
                const int sec = kc >> 1;
                const int c   = (kc & 1) * 2 + kaddp;
                const int sw  = c ^ ((rowQ >> 1) & 3);
                ldmx4(qf[kc], sbase + sec * 8192 + rowQ * 64 + sw * 16);
            }
        }

        const uint32_t kb = sbase + FA_QSM + (jb & 1) * FA_KV;
        const uint32_t vb = kb + FA_KBYTES;

        float sacc[16][4];
#pragma unroll
        for (int j = 0; j < 16; j++)
#pragma unroll
            for (int x = 0; x < 4; x++) sacc[j][x] = 0.f;
#pragma unroll
        for (int kc = 0; kc < 8; kc++) {
            const int sec = kc >> 1;
            const int c   = (kc & 1) * 2 + kaddp;
#pragma unroll
            for (int np = 0; np < 8; np++) {
                const int row = np * 16 + rB0;
                const int sw  = c ^ ((row >> 1) & 3);
                uint4 bq;
                ldmx4(bq, kb + sec * 8192 + row * 64 + sw * 16);
                MMA16816(sacc[np * 2],     qf[kc], bq.x, bq.z);
                MMA16816(sacc[np * 2 + 1], qf[kc], bq.y, bq.w);
            }
        }

        float mx0 = -1e30f, mx1 = -1e30f;
#pragma unroll
        for (int j = 0; j < 16; j++) {
            mx0 = fmaxf(mx0, fmaxf(sacc[j][0], sacc[j][1]));
            mx1 = fmaxf(mx1, fmaxf(sacc[j][2], sacc[j][3]));
        }
        mx0 = fmaxf(mx0, __shfl_xor_sync(0xffffffffu, mx0, 1));
        mx0 = fmaxf(mx0, __shfl_xor_sync(0xffffffffu, mx0, 2));
        mx1 = fmaxf(mx1, __shfl_xor_sync(0xffffffffu, mx1, 1));
        mx1 = fmaxf(mx1, __shfl_xor_sync(0xffffffffu, mx1, 2));

        const float mn0 = fmaxf(mrow[0], mx0);
        const float mn1 = fmaxf(mrow[1], mx1);
        const float sc0 = exp2f(mrow[0] - mn0);
        const float sc1 = exp2f(mrow[1] - mn1);
        mrow[0] = mn0; mrow[1] = mn1;

        uint32_t pf[16][2];
#pragma unroll
        for (int j = 0; j < 16; j++) {
            pf[j][0] = ex2h2(packh2(sacc[j][0] - mn0, sacc[j][1] - mn0));
            pf[j][1] = ex2h2(packh2(sacc[j][2] - mn1, sacc[j][3] - mn1));
        }
#pragma unroll
        for (int j = 0; j < 18; j++) {
            o[j][0] *= sc0; o[j][1] *= sc0;
            o[j][2] *= sc1; o[j][3] *= sc1;
        }

#pragma unroll
        for (int kc = 0; kc < 8; kc++) {
            const int sec = kc >> 1;
            const int c   = (kc & 1) * 2 + kaddp;
            uint4 a;
            a.x = pf[kc * 2][0];
            a.y = pf[kc * 2][1];
            a.z = pf[kc * 2 + 1][0];
            a.w = pf[kc * 2 + 1][1];
#pragma unroll
            for (int np = 0; np < 9; np++) {
                const int row = np * 16 + rB0;
                const int sw  = c ^ ((row >> 1) & 3);
                uint4 bq;
                ldmx4(bq, vb + sec * FA_VSEC + row * 64 + sw * 16);
                MMA16816(o[np * 2],     a, bq.x, bq.z);
                MMA16816(o[np * 2 + 1], a, bq.y, bq.w);
            }
        }

        __syncthreads();   // required: next issue writes the buffer just read

        const int nb = jb + 2;
        if (nb < NBLK) {
            const uint32_t nkb = sbase + FA_QSM + (nb & 1) * FA_KV;
            const uint32_t nvb = nkb + FA_KBYTES;
#pragma unroll
            for (int sec = 0; sec < 4; sec++)
#pragma unroll
                for (int j = 0; j < 2; j++) {
                    cp16(nkb + sec * 8192 + soff[j],
                         Kp + (size_t)(nb * 128 + rr[j]) * DMODEL + sec * 32 + kc8[j]);
                    cp16(nvb + sec * FA_VSEC + soff[j],
                         Vp + (size_t)rr[j] * S_TOT + nb * 128 + sec * 32 + kc8[j]);
                }
        }
        asm volatile("cp.async.commit_group;");
    }

    const float l0 = __shfl_sync(0xffffffffu, o[16][0], lane & 28);
    const float l1 = __shfl_sync(0xffffffffu, o[16][2], lane & 28);
    const float inv0 = 1.0f / l0;
    const float inv1 = 1.0f / l1;
    __half* Op = Og + (size_t)(qb * 128) * DMODEL + h * DH;
#pragma unroll
    for (int j = 0; j < 16; j++) {
        const int col  = j * 8 + tg * 2;
        const int row0 = wid * 16 + g;
        *(uint32_t*)(Op + (size_t)row0 * DMODEL + col) =
            packh2(o[j][0] * inv0, o[j][1] * inv0);
        *(uint32_t*)(Op + (size_t)(row0 + 8) * DMODEL + col) =
            packh2(o[j][2] * inv1, o[j][3] * inv1);
    }
}

// ---------------------------------------------------------------------------
// Merged float->half: hidden (6144 blocks) then enc (1536 blocks)
// ---------------------------------------------------------------------------
__global__ __launch_bounds__(256)
void f2h_all(const float* __restrict__ hidden, const float* __restrict__ enc,
             __half* __restrict__ hh, __half* __restrict__ eh)
{
    const int b = blockIdx.x;
    const float* in;
    __half* out;
    size_t i;
    if (b < (S_IMG * DMODEL) / 1024) {
        in = hidden; out = hh;
        i = ((size_t)b * 256 + threadIdx.x) * 4;
    } else {
        in = enc; out = eh;
        i = ((size_t)(b - (S_IMG * DMODEL) / 1024) * 256 + threadIdx.x) * 4;
    }
    float4 v = *(const float4*)(in + i);
    *(uint2*)(out + i) = make_uint2(packh2(v.x, v.y), packh2(v.z, v.w));
}

// ---------------------------------------------------------------------------
// Merged 64x64 transpose fp32->fp16 for all 4 weights.
// grid = (144, 48, 4); z in {2,3} early-exits when bx >= 48.
// ---------------------------------------------------------------------------
__global__ __launch_bounds__(256)
void transpose_all(const float* __restrict__ w0, const float* __restrict__ w1,
                   const float* __restrict__ w2, const float* __restrict__ w3,
                   __half* __restrict__ o0, __half* __restrict__ o1,
                   __half* __restrict__ o2, __half* __restrict__ o3)
{
    const int z = blockIdx.z;
    const float* in;
    __half* out;
    int R, C;
    if (z == 0)      { in = w0; out = o0; R = DMODEL; C = D3; }
    else if (z == 1) { in = w1; out = o1; R = DMODEL; C = D3; }
    else if (z == 2) { in = w2; out = o2; R = DMODEL; C = DMODEL; }
    else             { in = w3; out = o3; R = DMODEL; C = DMODEL; }
    const int bx = blockIdx.x * 64;
    const int by = blockIdx.y * 64;
    if (bx >= C) return;

    __shared__ float t[64][65];
    const int tx4 = (threadIdx.x & 15) * 4;
    const int ty  = threadIdx.x >> 4;
#pragma unroll
    for (int j = 0; j < 4; j++) {
        const int row = ty + j * 16;
        float4 v = *(const float4*)(in + (size_t)(by + row) * C + bx + tx4);
        t[row][tx4 + 0] = v.x; t[row][tx4 + 1] = v.y;
        t[row][tx4 + 2] = v.z; t[row][tx4 + 3] = v.w;
    }
    __syncthreads();
#pragma unroll
    for (int j = 0; j < 4; j++) {
        const int orow = ty + j * 16;
        uint2 w = make_uint2(
            packh2(t[tx4 + 0][orow], t[tx4 + 1][orow]),
            packh2(t[tx4 + 2][orow], t[tx4 + 3][orow]));
        *(uint2*)(out + (size_t)(bx + orow) * R + by + tx4) = w;
    }
}

// ---------------------------------------------------------------------------
// Fused RMSNorm + RoPE (fp16 in) -> fp16 q (scale*log2e), k, V^T
// ---------------------------------------------------------------------------
__device__ __forceinline__ float warp_sum(float v) {
#pragma unroll
    for (int o = 16; o > 0; o >>= 1) v += __shfl_xor_sync(0xffffffffu, v, o);
    return v;
}

__global__ __launch_bounds__(128)
void fuse_norm_rope(const __half* __restrict__ qkv, const __half* __restrict__ eqkv,
                    const int* __restrict__ ids,
                    const float* __restrict__ nq_w,  const float* __restrict__ nk_w,
                    const float* __restrict__ naq_w, const float* __restrict__ nak_w,
                    __half* __restrict__ Q, __half* __restrict__ Ko,
                    __half* __restrict__ VT)
{
    const int s = blockIdx.x;
    const int h = blockIdx.y;
    const int d = threadIdx.x;

    const __half* src;
    const float* qw;
    const float* kw;
    if (s < S_TXT) { src = eqkv + (size_t)s * D3;           qw = naq_w; kw = nak_w; }
    else           { src = qkv  + (size_t)(s - S_TXT) * D3; qw = nq_w;  kw = nk_w; }

    float qv = __half2float(src[h * DH + d]);
    float kv = __half2float(src[DMODEL   + h * DH + d]);
    float vv = __half2float(src[2*DMODEL + h * DH + d]);

    __shared__ float sq[4], sk[4];
    float wq = warp_sum(qv * qv);
    float wk = warp_sum(kv * kv);
    const int w = d >> 5;
    if ((d & 31) == 0) { sq[w] = wq; sk[w] = wk; }
    __syncthreads();
    float qsum = sq[0] + sq[1] + sq[2] + sq[3];
    float ksum = sk[0] + sk[1] + sk[2] + sk[3];
    float qn = qv * rsqrtf(qsum * (1.0f / DH) + 1e-5f) * qw[d];
    float kn = kv * rsqrtf(ksum * (1.0f / DH) + 1e-5f) * kw[d];

    const int pr = d >> 1;
    int axis, base, dax;
    if      (pr < 8)  { axis = 0; base = 0;  dax = 16; }
    else if (pr < 36) { axis = 1; base = 8;  dax = 56; }
    else              { axis = 2; base = 36; dax = 56; }
    float e    = (2.0f * (float)(pr - base)) / (float)dax;
    float freq = expf(-e * 9.210340371976184f);
    float pos  = (float)ids[s * 3 + axis];
    float ang  = pos * freq;
    float cs, sn;
    sincosf(ang, &sn, &cs);

    float q_other = __shfl_xor_sync(0xffffffffu, qn, 1);
    float k_other = __shfl_xor_sync(0xffffffffu, kn, 1);
    float qr, kr;
    if (d & 1) { qr = qn * cs + q_other * sn; kr = kn * cs + k_other * sn; }
    else       { qr = qn * cs - q_other * sn; kr = kn * cs - k_other * sn; }

    const size_t o = (size_t)s * DMODEL + h * DH + d;
    Q[o]  = __float2half(qr * (0.08838834764831845f * 1.4426950408889634f));
    Ko[o] = __float2half(kr);
    VT[(size_t)(h * DH + d) * S_TOT + s] = __float2half(vv);
}

// ---------------------------------------------------------------------------
// kernel_launch
// ---------------------------------------------------------------------------
extern "C" void kernel_launch(void* const* d_in, const int* in_sizes, int n_in,
                              void* d_out, int out_size)
{
    const float* hidden     = (const float*)d_in[0];
    const float* enc        = (const float*)d_in[1];
    const int*   ids        = (const int*)  d_in[2];
    const float* w_qkv      = (const float*)d_in[3];
    const float* w_add_qkv  = (const float*)d_in[4];
    const float* b_add_qkv  = (const float*)d_in[5];
    const float* w_out      = (const float*)d_in[6];
    const float* b_out      = (const float*)d_in[7];
    const float* w_add_out  = (const float*)d_in[8];
    const float* b_add_out  = (const float*)d_in[9];
    const float* norm_q_w   = (const float*)d_in[10];
    const float* norm_k_w   = (const float*)d_in[11];
    const float* norm_aq_w  = (const float*)d_in[12];
    const float* norm_ak_w  = (const float*)d_in[13];
    float* out = (float*)d_out;

    __half *qkvh, *eqkvh, *hh, *eh, *qh, *kh, *vt, *attnh, *wtq, *wtaq, *wto, *wtao;
    cudaGetSymbolAddress((void**)&qkvh,  g_qkvh);
    cudaGetSymbolAddress((void**)&eqkvh, g_eqkvh);
    cudaGetSymbolAddress((void**)&hh,    g_hh);
    cudaGetSymbolAddress((void**)&eh,    g_eh);
    cudaGetSymbolAddress((void**)&qh,    g_qh);
    cudaGetSymbolAddress((void**)&kh,    g_kh);
    cudaGetSymbolAddress((void**)&vt,    g_vt);
    cudaGetSymbolAddress((void**)&attnh, g_attnh);
    cudaGetSymbolAddress((void**)&wtq,   g_wtq);
    cudaGetSymbolAddress((void**)&wtaq,  g_wtaq);
    cudaGetSymbolAddress((void**)&wto,   g_wto);
    cudaGetSymbolAddress((void**)&wtao,  g_wtao);

    cudaFuncSetAttribute(gemm_nt_h, cudaFuncAttributeMaxDynamicSharedMemorySize,
                         GEMM_SMEM_BYTES);
    cudaFuncSetAttribute(flash_attn, cudaFuncAttributeMaxDynamicSharedMemorySize,
                         FA_SMEM);

    // 0) convert activations + transpose/convert all weights (2 launches)
    f2h_all<<<(S_IMG * DMODEL + S_TXT * DMODEL) / 1024, 256>>>(hidden, enc, hh, eh);
    transpose_all<<<dim3(D3/64, DMODEL/64, 4), 256>>>(
        w_qkv, w_add_qkv, w_out, w_add_out, wtq, wtaq, wto, wtao);

    // 1) qkv = hidden @ w_qkv            (fp16 out)
    gemm_nt_h<<<dim3(D3/128, S_IMG/128, 1), 256, GEMM_SMEM_BYTES>>>(
        hh, wtq, nullptr, qkvh, DMODEL, DMODEL, DMODEL, D3, 0, 0, 0, 1);

    // 2) eqkv = enc @ w_add_qkv + b      (fp16 out)
    gemm_nt_h<<<dim3(D3/128, S_TXT/128, 1), 256, GEMM_SMEM_BYTES>>>(
        eh, wtaq, b_add_qkv, eqkvh, DMODEL, DMODEL, DMODEL, D3, 0, 0, 0, 1);

    // 3) RMSNorm + RoPE -> fp16 q,k and fp16 V^T
    fuse_norm_rope<<<dim3(S_TOT, NHEADS), 128>>>(
        qkvh, eqkvh, ids, norm_q_w, norm_k_w, norm_aq_w, norm_ak_w, qh, kh, vt);

    // 4) fused attention -> attnh fp16 [S, 3072]
    flash_attn<<<dim3(S_TOT/128, NHEADS), 256, FA_SMEM>>>(qh, kh, vt, attnh);

    // 5) img_out = attn[512:] @ w_out + b_out
    gemm_nt_h<<<dim3(DMODEL/128, S_IMG/128, 1), 256, GEMM_SMEM_BYTES>>>(
        attnh + (size_t)S_TXT * DMODEL, wto, b_out, out,
        DMODEL, DMODEL, DMODEL, DMODEL, 0, 0, 0, 0);

    // 6) enc_out = attn[:512] @ w_add_out + b_add_out
    gemm_nt_h<<<dim3(DMODEL/128, S_TXT/128, 1), 256, GEMM_SMEM_BYTES>>>(
        attnh, wtao, b_add_out, out + (size_t)S_IMG * DMODEL,
        DMODEL, DMODEL, DMODEL, DMODEL, 0, 0, 0, 0);
}

// round 12
// speedup vs baseline: 1.1990x; 1.0606x over previous
#include <cuda_runtime.h>
#include <cuda_fp16.h>
#include <cstdint>
#include <math.h>

// ---------------------------------------------------------------------------
// Problem constants (Flux dual-stream attention block)
// ---------------------------------------------------------------------------
#define S_TXT   512
#define S_IMG   2048
#define S_TOT   2560
#define DMODEL  3072
#define NHEADS  24
#define DH      128
#define D3      9216

// ---------------------------------------------------------------------------
// Scratch (device globals -- allocation is forbidden)
// ---------------------------------------------------------------------------
__device__ __align__(256) __half g_qkvh [(size_t)S_IMG * D3];
__device__ __align__(256) __half g_eqkvh[(size_t)S_TXT * D3];
__device__ __align__(256) __half g_hh   [(size_t)S_IMG * DMODEL];
__device__ __align__(256) __half g_eh   [(size_t)S_TXT * DMODEL];
__device__ __align__(256) __half g_qh   [(size_t)S_TOT * DMODEL];
__device__ __align__(256) __half g_kh   [(size_t)S_TOT * DMODEL];
__device__ __align__(256) __half g_vt   [(size_t)DMODEL * S_TOT];
__device__ __align__(256) __half g_attnh[(size_t)S_TOT * DMODEL];
__device__ __align__(256) __half g_wtq  [(size_t)D3 * DMODEL];
__device__ __align__(256) __half g_wtaq [(size_t)D3 * DMODEL];
__device__ __align__(256) __half g_wto  [(size_t)DMODEL * DMODEL];
__device__ __align__(256) __half g_wtao [(size_t)DMODEL * DMODEL];

// ---------------------------------------------------------------------------
// helpers
// ---------------------------------------------------------------------------
__device__ __forceinline__ uint32_t smem_u32(const void* p) {
    uint32_t a;
    asm("{ .reg .u64 t; cvta.to.shared.u64 t, %1; cvt.u32.u64 %0, t; }" : "=r"(a) : "l"(p));
    return a;
}
__device__ __forceinline__ uint32_t packh2(float lo, float hi) {
    uint32_t r;
    asm("cvt.rn.f16x2.f32 %0, %1, %2;" : "=r"(r) : "f"(hi), "f"(lo));
    return r;
}
__device__ __forceinline__ uint32_t ex2h2(uint32_t x) {
    uint32_t r;
    asm("ex2.approx.f16x2 %0, %1;" : "=r"(r) : "r"(x));
    return r;
}
__device__ __forceinline__ void cp16(uint32_t saddr, const void* gptr) {
    asm volatile("cp.async.cg.shared.global [%0], [%1], 16;" :: "r"(saddr), "l"(gptr));
}
__device__ __forceinline__ void ldmx4(uint4& f, uint32_t addr) {
    asm volatile("ldmatrix.sync.aligned.m8n8.x4.shared.b16 {%0,%1,%2,%3}, [%4];"
                 : "=r"(f.x), "=r"(f.y), "=r"(f.z), "=r"(f.w) : "r"(addr));
}
#define MMA16816(acc, a, b0, b1)                                               \
    asm volatile("mma.sync.aligned.m16n8k16.row.col.f32.f16.f16.f32 "          \
                 "{%0,%1,%2,%3}, {%4,%5,%6,%7}, {%8,%9}, {%0,%1,%2,%3};"       \
                 : "+f"((acc)[0]), "+f"((acc)[1]), "+f"((acc)[2]), "+f"((acc)[3]) \
                 : "r"((a).x), "r"((a).y), "r"((a).z), "r"((a).w),             \
                   "r"(b0), "r"(b1))

// ---------------------------------------------------------------------------
// fp16 cp.async NT GEMM, 128x128 tile, K-tile 64 (R12).
// 3-stage ring (32KB/stage = 16KB A + 16KB B), one barrier per 64 k-elems:
// 64 MMA + 24 LDSM per warp per sync (was 32+12 at k-tile 32).
// Row layout: 128 B/row (8 x 16B chunks); chunk kc at row r lives at
// r*128 + (kc ^ (r & 7))*16  -> conflict-free STS and ldmatrix.
// ---------------------------------------------------------------------------
#define STAGE_BYTES 32768
#define NSTAGE 3
#define GEMM_SMEM_BYTES (NSTAGE * STAGE_BYTES)   // 98304

__global__ __launch_bounds__(256, 2)
void gemm_nt_h(const __half* __restrict__ A, const __half* __restrict__ B,
               const float* __restrict__ bias, void* __restrict__ Cv,
               int K, int lda, int ldb, int ldc,
               long long sA, long long sB, long long sC, int out_half)
{
    extern __shared__ char smem[];
    const uint32_t sbase = smem_u32(smem);
    const int tid    = threadIdx.x;
    const int lane   = tid & 31;
    const int wid    = tid >> 5;
    const int warp_m = wid >> 2;
    const int warp_n = wid & 3;
    const int bm     = blockIdx.y * 128;
    const int bn     = blockIdx.x * 128;

    A += (size_t)blockIdx.z * sA + (size_t)bm * lda;
    B += (size_t)blockIdx.z * sB + (size_t)bn * ldb;

    // staging: 4 x 16B chunks per thread per matrix (128 rows x 8 chunks)
    uint32_t soff[4];
    size_t   goa[4], gob[4];
#pragma unroll
    for (int j = 0; j < 4; j++) {
        const int c  = tid + j * 256;
        const int r  = c >> 3;
        const int kc = c & 7;
        soff[j] = (uint32_t)(r * 128 + ((kc ^ (r & 7)) * 16));
        goa[j]  = (size_t)r * lda + kc * 8;
        gob[j]  = (size_t)r * ldb + kc * 8;
    }

    const int T = K >> 6;     // K-tiles of 64 (K = 3072 -> 48)

    // prologue: stages 0,1
#pragma unroll
    for (int s = 0; s < 2; s++) {
        const uint32_t sa = sbase + s * STAGE_BYTES;
#pragma unroll
        for (int j = 0; j < 4; j++) {
            cp16(sa + soff[j],         A + goa[j] + s * 64);
            cp16(sa + 16384 + soff[j], B + gob[j] + s * 64);
        }
        asm volatile("cp.async.commit_group;");
    }

    float acc[4][4][4];
#pragma unroll
    for (int m = 0; m < 4; m++)
#pragma unroll
        for (int n = 0; n < 4; n++)
#pragma unroll
            for (int x = 0; x < 4; x++) acc[m][n][x] = 0.0f;

    const int p    = lane >> 3;
    const int li   = lane & 7;
    const int rA0  = warp_m * 64 + (p & 1) * 8 + li;
    const int rB0  = warp_n * 32 + (p & 1) * 8 + li;
    const int kaddp = p >> 1;

    int cur = 0, nxt = 2;     // rotating stage indices (mod 3)
    for (int t = 0; t < T; t++) {
        asm volatile("cp.async.wait_group 1;");
        __syncthreads();      // stage `cur` visible; stage `nxt` reads all done

        {
            const int kt = t + 2;
            if (kt < T) {
                const uint32_t sa = sbase + nxt * STAGE_BYTES;
#pragma unroll
                for (int j = 0; j < 4; j++) {
                    cp16(sa + soff[j],         A + goa[j] + (size_t)kt * 64);
                    cp16(sa + 16384 + soff[j], B + gob[j] + (size_t)kt * 64);
                }
            }
            asm volatile("cp.async.commit_group;");
        }

        const uint32_t st = sbase + cur * STAGE_BYTES;
#pragma unroll
        for (int ks = 0; ks < 4; ks++) {
            const int kc = ks * 2 + kaddp;
            uint4 af[4];
#pragma unroll
            for (int mt = 0; mt < 4; mt++) {
                const int row = rA0 + mt * 16;
                ldmx4(af[mt], st + row * 128 + ((kc ^ (row & 7)) * 16));
            }
            uint4 bq[2];
#pragma unroll
            for (int ntp = 0; ntp < 2; ntp++) {
                const int row = rB0 + ntp * 16;
                ldmx4(bq[ntp], st + 16384 + row * 128 + ((kc ^ (row & 7)) * 16));
            }
            uint2 bf[4];
            bf[0] = make_uint2(bq[0].x, bq[0].z);
            bf[1] = make_uint2(bq[0].y, bq[0].w);
            bf[2] = make_uint2(bq[1].x, bq[1].z);
            bf[3] = make_uint2(bq[1].y, bq[1].w);
#pragma unroll
            for (int m = 0; m < 4; m++)
#pragma unroll
                for (int n = 0; n < 4; n++)
                    MMA16816(acc[m][n], af[m], bf[n].x, bf[n].y);
        }

        cur = (cur == 2) ? 0 : cur + 1;
        nxt = (nxt == 2) ? 0 : nxt + 1;
    }

    const int g  = lane >> 2;
    const int tg = lane & 3;
    if (out_half) {
        __half* C = (__half*)Cv + (size_t)blockIdx.z * sC;
#pragma unroll
        for (int m = 0; m < 4; m++) {
            const int row0 = bm + warp_m * 64 + m * 16 + g;
#pragma unroll
            for (int n = 0; n < 4; n++) {
                const int col = bn + warp_n * 32 + n * 8 + tg * 2;
                float bx = 0.f, by = 0.f;
                if (bias) { bx = bias[col]; by = bias[col + 1]; }
                *(uint32_t*)(C + (size_t)row0 * ldc + col) =
                    packh2(acc[m][n][0] + bx, acc[m][n][1] + by);
                *(uint32_t*)(C + (size_t)(row0 + 8) * ldc + col) =
                    packh2(acc[m][n][2] + bx, acc[m][n][3] + by);
            }
        }
    } else {
        float* C = (float*)Cv + (size_t)blockIdx.z * sC;
#pragma unroll
        for (int m = 0; m < 4; m++) {
            const int row0 = bm + warp_m * 64 + m * 16 + g;
#pragma unroll
            for (int n = 0; n < 4; n++) {
                const int col = bn + warp_n * 32 + n * 8 + tg * 2;
                float bx = 0.f, by = 0.f;
                if (bias) { bx = bias[col]; by = bias[col + 1]; }
                *(float2*)(C + (size_t)row0 * ldc + col) =
                    make_float2(acc[m][n][0] + bx, acc[m][n][1] + by);
                *(float2*)(C + (size_t)(row0 + 8) * ldc + col) =
                    make_float2(acc[m][n][2] + bx, acc[m][n][3] + by);
            }
        }
    }
}

// ---------------------------------------------------------------------------
// Fused flash attention (unchanged: proven at 1082us)
// ---------------------------------------------------------------------------
#define FA_QSM    32768
#define FA_KBYTES 32768
#define FA_VSEC   9216
#define FA_VBYTES (4 * FA_VSEC)
#define FA_KV     (FA_KBYTES + FA_VBYTES)
#define FA_SMEM   (FA_QSM + 2 * FA_KV)
#define NBLK      (S_TOT / 128)

__global__ __launch_bounds__(256)
void flash_attn(const __half* __restrict__ Qg, const __half* __restrict__ Kg,
                const __half* __restrict__ VTg, __half* __restrict__ Og)
{
    extern __shared__ char smem[];
    const uint32_t sbase = smem_u32(smem);
    const int tid  = threadIdx.x;
    const int lane = tid & 31;
    const int wid  = tid >> 5;
    const int qb   = blockIdx.x;
    const int h    = blockIdx.y;

    uint32_t soff[2];
    int rr[2], kc8[2];
#pragma unroll
    for (int j = 0; j < 2; j++) {
        const int c  = tid + j * 256;
        const int r  = c >> 2;
        const int kc = c & 3;
        soff[j] = (uint32_t)(r * 64 + (kc ^ ((r >> 1) & 3)) * 16);
        rr[j]   = r;
        kc8[j]  = kc * 8;
    }

    const __half* Qp = Qg + (size_t)(qb * 128) * DMODEL + h * DH;
    const __half* Kp = Kg + h * DH;
    const __half* Vp = VTg + (size_t)(h * DH) * S_TOT;

#pragma unroll
    for (int bs = 0; bs < 8; bs++) {
        const int buf = bs >> 2;
        const int sec = bs & 3;
        const uint32_t base = FA_QSM + buf * FA_KV + FA_KBYTES
                            + sec * FA_VSEC + 128 * 64;
        const int w = tid;
        *(uint32_t*)(smem + base + w * 4) = (w < 16) ? 0x3C003C00u : 0u;
    }

#pragma unroll
    for (int sec = 0; sec < 4; sec++)
#pragma unroll
        for (int j = 0; j < 2; j++)
            cp16(sbase + sec * 8192 + soff[j],
                 Qp + (size_t)rr[j] * DMODEL + sec * 32 + kc8[j]);
    {
        const uint32_t kb = sbase + FA_QSM;
        const uint32_t vb = kb + FA_KBYTES;
#pragma unroll
        for (int sec = 0; sec < 4; sec++)
#pragma unroll
            for (int j = 0; j < 2; j++) {
                cp16(kb + sec * 8192 + soff[j],
                     Kp + (size_t)rr[j] * DMODEL + sec * 32 + kc8[j]);
                cp16(vb + sec * FA_VSEC + soff[j],
                     Vp + (size_t)rr[j] * S_TOT + sec * 32 + kc8[j]);
            }
    }
    asm volatile("cp.async.commit_group;");
    {
        const uint32_t kb = sbase + FA_QSM + FA_KV;
        const uint32_t vb = kb + FA_KBYTES;
#pragma unroll
        for (int sec = 0; sec < 4; sec++)
#pragma unroll
            for (int j = 0; j < 2; j++) {
                cp16(kb + sec * 8192 + soff[j],
                     Kp + (size_t)(128 + rr[j]) * DMODEL + sec * 32 + kc8[j]);
                cp16(vb + sec * FA_VSEC + soff[j],
                     Vp + (size_t)rr[j] * S_TOT + 128 + sec * 32 + kc8[j]);
            }
    }
    asm volatile("cp.async.commit_group;");

    const int p     = lane >> 3;
    const int li    = lane & 7;
    const int kaddp = p >> 1;
    const int rowQ  = wid * 16 + (p & 1) * 8 + li;
    const int rB0   = (p & 1) * 8 + li;
    const int g     = lane >> 2;
    const int tg    = lane & 3;

    float mrow[2] = {-1e30f, -1e30f};
    float o[18][4];
#pragma unroll
    for (int j = 0; j < 18; j++)
#pragma unroll
        for (int x = 0; x < 4; x++) o[j][x] = 0.f;
    uint4 qf[8];

    for (int jb = 0; jb < NBLK; jb++) {
        asm volatile("cp.async.wait_group 1;");
        __syncthreads();

        if (jb == 0) {
#pragma unroll
            for (int kc = 0; kc < 8; kc++) {
                const int sec = kc >> 1;
                const int c   = (kc & 1) * 2 + kaddp;
                const int sw  = c ^ ((rowQ >> 1) & 3);
                ldmx4(qf[kc], sbase + sec * 8192 + rowQ * 64 + sw * 16);
            }
        }

        const uint32_t kb = sbase + FA_QSM + (jb & 1) * FA_KV;
        const uint32_t vb = kb + FA_KBYTES;

        float sacc[16][4];
#pragma unroll
        for (int j = 0; j < 16; j++)
#pragma unroll
            for (int x = 0; x < 4; x++) sacc[j][x] = 0.f;
#pragma unroll
        for (int kc = 0; kc < 8; kc++) {
            const int sec = kc >> 1;
            const int c   = (kc & 1) * 2 + kaddp;
#pragma unroll
            for (int np = 0; np < 8; np++) {
                const int row = np * 16 + rB0;
                const int sw  = c ^ ((row >> 1) & 3);
                uint4 bq;
                ldmx4(bq, kb + sec * 8192 + row * 64 + sw * 16);
                MMA16816(sacc[np * 2],     qf[kc], bq.x, bq.z);
                MMA16816(sacc[np * 2 + 1], qf[kc], bq.y, bq.w);
            }
        }

        float mx0 = -1e30f, mx1 = -1e30f;
#pragma unroll
        for (int j = 0; j < 16; j++) {
            mx0 = fmaxf(mx0, fmaxf(sacc[j][0], sacc[j][1]));
            mx1 = fmaxf(mx1, fmaxf(sacc[j][2], sacc[j][3]));
        }
        mx0 = fmaxf(mx0, __shfl_xor_sync(0xffffffffu, mx0, 1));
        mx0 = fmaxf(mx0, __shfl_xor_sync(0xffffffffu, mx0, 2));
        mx1 = fmaxf(mx1, __shfl_xor_sync(0xffffffffu, mx1, 1));
        mx1 = fmaxf(mx1, __shfl_xor_sync(0xffffffffu, mx1, 2));

        const float mn0 = fmaxf(mrow[0], mx0);
        const float mn1 = fmaxf(mrow[1], mx1);
        const float sc0 = exp2f(mrow[0] - mn0);
        const float sc1 = exp2f(mrow[1] - mn1);
        mrow[0] = mn0; mrow[1] = mn1;

        uint32_t pf[16][2];
#pragma unroll
        for (int j = 0; j < 16; j++) {
            pf[j][0] = ex2h2(packh2(sacc[j][0] - mn0, sacc[j][1] - mn0));
            pf[j][1] = ex2h2(packh2(sacc[j][2] - mn1, sacc[j][3] - mn1));
        }
#pragma unroll
        for (int j = 0; j < 18; j++) {
            o[j][0] *= sc0; o[j][1] *= sc0;
            o[j][2] *= sc1; o[j][3] *= sc1;
        }

#pragma unroll
        for (int kc = 0; kc < 8; kc++) {
            const int sec = kc >> 1;
            const int c   = (kc & 1) * 2 + kaddp;
            uint4 a;
            a.x = pf[kc * 2][0];
            a.y = pf[kc * 2][1];
            a.z = pf[kc * 2 + 1][0];
            a.w = pf[kc * 2 + 1][1];
#pragma unroll
            for (int np = 0; np < 9; np++) {
                const int row = np * 16 + rB0;
                const int sw  = c ^ ((row >> 1) & 3);
                uint4 bq;
                ldmx4(bq, vb + sec * FA_VSEC + row * 64 + sw * 16);
                MMA16816(o[np * 2],     a, bq.x, bq.z);
                MMA16816(o[np * 2 + 1], a, bq.y, bq.w);
            }
        }

        __syncthreads();

        const int nb = jb + 2;
        if (nb < NBLK) {
            const uint32_t nkb = sbase + FA_QSM + (nb & 1) * FA_KV;
            const uint32_t nvb = nkb + FA_KBYTES;
#pragma unroll
            for (int sec = 0; sec < 4; sec++)
#pragma unroll
                for (int j = 0; j < 2; j++) {
                    cp16(nkb + sec * 8192 + soff[j],
                         Kp + (size_t)(nb * 128 + rr[j]) * DMODEL + sec * 32 + kc8[j]);
                    cp16(nvb + sec * FA_VSEC + soff[j],
                         Vp + (size_t)rr[j] * S_TOT + nb * 128 + sec * 32 + kc8[j]);
                }
        }
        asm volatile("cp.async.commit_group;");
    }

    const float l0 = __shfl_sync(0xffffffffu, o[16][0], lane & 28);
    const float l1 = __shfl_sync(0xffffffffu, o[16][2], lane & 28);
    const float inv0 = 1.0f / l0;
    const float inv1 = 1.0f / l1;
    __half* Op = Og + (size_t)(qb * 128) * DMODEL + h * DH;
#pragma unroll
    for (int j = 0; j < 16; j++) {
        const int col  = j * 8 + tg * 2;
        const int row0 = wid * 16 + g;
        *(uint32_t*)(Op + (size_t)row0 * DMODEL + col) =
            packh2(o[j][0] * inv0, o[j][1] * inv0);
        *(uint32_t*)(Op + (size_t)(row0 + 8) * DMODEL + col) =
            packh2(o[j][2] * inv1, o[j][3] * inv1);
    }
}

// ---------------------------------------------------------------------------
// Merged float->half
// ---------------------------------------------------------------------------
__global__ __launch_bounds__(256)
void f2h_all(const float* __restrict__ hidden, const float* __restrict__ enc,
             __half* __restrict__ hh, __half* __restrict__ eh)
{
    const int b = blockIdx.x;
    const float* in;
    __half* out;
    size_t i;
    if (b < (S_IMG * DMODEL) / 1024) {
        in = hidden; out = hh;
        i = ((size_t)b * 256 + threadIdx.x) * 4;
    } else {
        in = enc; out = eh;
        i = ((size_t)(b - (S_IMG * DMODEL) / 1024) * 256 + threadIdx.x) * 4;
    }
    float4 v = *(const float4*)(in + i);
    *(uint2*)(out + i) = make_uint2(packh2(v.x, v.y), packh2(v.z, v.w));
}

// ---------------------------------------------------------------------------
// Merged 64x64 transpose fp32->fp16 for all 4 weights
// ---------------------------------------------------------------------------
__global__ __launch_bounds__(256)
void transpose_all(const float* __restrict__ w0, const float* __restrict__ w1,
                   const float* __restrict__ w2, const float* __restrict__ w3,
                   __half* __restrict__ o0, __half* __restrict__ o1,
                   __half* __restrict__ o2, __half* __restrict__ o3)
{
    const int z = blockIdx.z;
    const float* in;
    __half* out;
    int R, C;
    if (z == 0)      { in = w0; out = o0; R = DMODEL; C = D3; }
    else if (z == 1) { in = w1; out = o1; R = DMODEL; C = D3; }
    else if (z == 2) { in = w2; out = o2; R = DMODEL; C = DMODEL; }
    else             { in = w3; out = o3; R = DMODEL; C = DMODEL; }
    const int bx = blockIdx.x * 64;
    const int by = blockIdx.y * 64;
    if (bx >= C) return;

    __shared__ float t[64][65];
    const int tx4 = (threadIdx.x & 15) * 4;
    const int ty  = threadIdx.x >> 4;
#pragma unroll
    for (int j = 0; j < 4; j++) {
        const int row = ty + j * 16;
        float4 v = *(const float4*)(in + (size_t)(by + row) * C + bx + tx4);
        t[row][tx4 + 0] = v.x; t[row][tx4 + 1] = v.y;
        t[row][tx4 + 2] = v.z; t[row][tx4 + 3] = v.w;
    }
    __syncthreads();
#pragma unroll
    for (int j = 0; j < 4; j++) {
        const int orow = ty + j * 16;
        uint2 w = make_uint2(
            packh2(t[tx4 + 0][orow], t[tx4 + 1][orow]),
            packh2(t[tx4 + 2][orow], t[tx4 + 3][orow]));
        *(uint2*)(out + (size_t)(bx + orow) * R + by + tx4) = w;
    }
}

// ---------------------------------------------------------------------------
// Fused RMSNorm + RoPE (fp16 in) -> fp16 q (scale*log2e), k, V^T
// ---------------------------------------------------------------------------
__device__ __forceinline__ float warp_sum(float v) {
#pragma unroll
    for (int o = 16; o > 0; o >>= 1) v += __shfl_xor_sync(0xffffffffu, v, o);
    return v;
}

__global__ __launch_bounds__(128)
void fuse_norm_rope(const __half* __restrict__ qkv, const __half* __restrict__ eqkv,
                    const int* __restrict__ ids,
                    const float* __restrict__ nq_w,  const float* __restrict__ nk_w,
                    const float* __restrict__ naq_w, const float* __restrict__ nak_w,
                    __half* __restrict__ Q, __half* __restrict__ Ko,
                    __half* __restrict__ VT)
{
    const int s = blockIdx.x;
    const int h = blockIdx.y;
    const int d = threadIdx.x;

    const __half* src;
    const float* qw;
    const float* kw;
    if (s < S_TXT) { src = eqkv + (size_t)s * D3;           qw = naq_w; kw = nak_w; }
    else           { src = qkv  + (size_t)(s - S_TXT) * D3; qw = nq_w;  kw = nk_w; }

    float qv = __half2float(src[h * DH + d]);
    float kv = __half2float(src[DMODEL   + h * DH + d]);
    float vv = __half2float(src[2*DMODEL + h * DH + d]);

    __shared__ float sq[4], sk[4];
    float wq = warp_sum(qv * qv);
    float wk = warp_sum(kv * kv);
    const int w = d >> 5;
    if ((d & 31) == 0) { sq[w] = wq; sk[w] = wk; }
    __syncthreads();
    float qsum = sq[0] + sq[1] + sq[2] + sq[3];
    float ksum = sk[0] + sk[1] + sk[2] + sk[3];
    float qn = qv * rsqrtf(qsum * (1.0f / DH) + 1e-5f) * qw[d];
    float kn = kv * rsqrtf(ksum * (1.0f / DH) + 1e-5f) * kw[d];

    const int pr = d >> 1;
    int axis, base, dax;
    if      (pr < 8)  { axis = 0; base = 0;  dax = 16; }
    else if (pr < 36) { axis = 1; base = 8;  dax = 56; }
    else              { axis = 2; base = 36; dax = 56; }
    float e    = (2.0f * (float)(pr - base)) / (float)dax;
    float freq = expf(-e * 9.210340371976184f);
    float pos  = (float)ids[s * 3 + axis];
    float ang  = pos * freq;
    float cs, sn;
    sincosf(ang, &sn, &cs);

    float q_other = __shfl_xor_sync(0xffffffffu, qn, 1);
    float k_other = __shfl_xor_sync(0xffffffffu, kn, 1);
    float qr, kr;
    if (d & 1) { qr = qn * cs + q_other * sn; kr = kn * cs + k_other * sn; }
    else       { qr = qn * cs - q_other * sn; kr = kn * cs - k_other * sn; }

    const size_t o = (size_t)s * DMODEL + h * DH + d;
    Q[o]  = __float2half(qr * (0.08838834764831845f * 1.4426950408889634f));
    Ko[o] = __float2half(kr);
    VT[(size_t)(h * DH + d) * S_TOT + s] = __float2half(vv);
}

// ---------------------------------------------------------------------------
// kernel_launch
// ---------------------------------------------------------------------------
extern "C" void kernel_launch(void* const* d_in, const int* in_sizes, int n_in,
                              void* d_out, int out_size)
{
    const float* hidden     = (const float*)d_in[0];
    const float* enc        = (const float*)d_in[1];
    const int*   ids        = (const int*)  d_in[2];
    const float* w_qkv      = (const float*)d_in[3];
    const float* w_add_qkv  = (const float*)d_in[4];
    const float* b_add_qkv  = (const float*)d_in[5];
    const float* w_out      = (const float*)d_in[6];
    const float* b_out      = (const float*)d_in[7];
    const float* w_add_out  = (const float*)d_in[8];
    const float* b_add_out  = (const float*)d_in[9];
    const float* norm_q_w   = (const float*)d_in[10];
    const float* norm_k_w   = (const float*)d_in[11];
    const float* norm_aq_w  = (const float*)d_in[12];
    const float* norm_ak_w  = (const float*)d_in[13];
    float* out = (float*)d_out;

    __half *qkvh, *eqkvh, *hh, *eh, *qh, *kh, *vt, *attnh, *wtq, *wtaq, *wto, *wtao;
    cudaGetSymbolAddress((void**)&qkvh,  g_qkvh);
    cudaGetSymbolAddress((void**)&eqkvh, g_eqkvh);
    cudaGetSymbolAddress((void**)&hh,    g_hh);
    cudaGetSymbolAddress((void**)&eh,    g_eh);
    cudaGetSymbolAddress((void**)&qh,    g_qh);
    cudaGetSymbolAddress((void**)&kh,    g_kh);
    cudaGetSymbolAddress((void**)&vt,    g_vt);
    cudaGetSymbolAddress((void**)&attnh, g_attnh);
    cudaGetSymbolAddress((void**)&wtq,   g_wtq);
    cudaGetSymbolAddress((void**)&wtaq,  g_wtaq);
    cudaGetSymbolAddress((void**)&wto,   g_wto);
    cudaGetSymbolAddress((void**)&wtao,  g_wtao);

    cudaFuncSetAttribute(gemm_nt_h, cudaFuncAttributeMaxDynamicSharedMemorySize,
                         GEMM_SMEM_BYTES);
    cudaFuncSetAttribute(flash_attn, cudaFuncAttributeMaxDynamicSharedMemorySize,
                         FA_SMEM);

    // 0) convert activations + transpose/convert all weights (2 launches)
    f2h_all<<<(S_IMG * DMODEL + S_TXT * DMODEL) / 1024, 256>>>(hidden, enc, hh, eh);
    transpose_all<<<dim3(D3/64, DMODEL/64, 4), 256>>>(
        w_qkv, w_add_qkv, w_out, w_add_out, wtq, wtaq, wto, wtao);

    // 1) qkv = hidden @ w_qkv            (fp16 out)
    gemm_nt_h<<<dim3(D3/128, S_IMG/128, 1), 256, GEMM_SMEM_BYTES>>>(
        hh, wtq, nullptr, qkvh, DMODEL, DMODEL, DMODEL, D3, 0, 0, 0, 1);

    // 2) eqkv = enc @ w_add_qkv + b      (fp16 out)
    gemm_nt_h<<<dim3(D3/128, S_TXT/128, 1), 256, GEMM_SMEM_BYTES>>>(
        eh, wtaq, b_add_qkv, eqkvh, DMODEL, DMODEL, DMODEL, D3, 0, 0, 0, 1);

    // 3) RMSNorm + RoPE -> fp16 q,k and fp16 V^T
    fuse_norm_rope<<<dim3(S_TOT, NHEADS), 128>>>(
        qkvh, eqkvh, ids, norm_q_w, norm_k_w, norm_aq_w, norm_ak_w, qh, kh, vt);

    // 4) fused attention -> attnh fp16 [S, 3072]
    flash_attn<<<dim3(S_TOT/128, NHEADS), 256, FA_SMEM>>>(qh, kh, vt, attnh);

    // 5) img_out = attn[512:] @ w_out + b_out
    gemm_nt_h<<<dim3(DMODEL/128, S_IMG/128, 1), 256, GEMM_SMEM_BYTES>>>(
        attnh + (size_t)S_TXT * DMODEL, wto, b_out, out,
        DMODEL, DMODEL, DMODEL, DMODEL, 0, 0, 0, 0);

    // 6) enc_out = attn[:512] @ w_add_out + b_add_out
    gemm_nt_h<<<dim3(DMODEL/128, S_TXT/128, 1), 256, GEMM_SMEM_BYTES>>>(
        attnh, wtao, b_add_out, out + (size_t)S_IMG * DMODEL,
        DMODEL, DMODEL, DMODEL, DMODEL, 0, 0, 0, 0);
}

// round 13
// speedup vs baseline: 1.2134x; 1.0121x over previous
#include <cuda_runtime.h>
#include <cuda_fp16.h>
#include <cstdint>
#include <math.h>

// ---------------------------------------------------------------------------
// Problem constants (Flux dual-stream attention block)
// ---------------------------------------------------------------------------
#define S_TXT   512
#define S_IMG   2048
#define S_TOT   2560
#define DMODEL  3072
#define NHEADS  24
#define DH      128
#define D3      9216

// ---------------------------------------------------------------------------
// Scratch (device globals -- allocation is forbidden)
// ---------------------------------------------------------------------------
__device__ __align__(256) __half g_qkvh [(size_t)S_IMG * D3];
__device__ __align__(256) __half g_eqkvh[(size_t)S_TXT * D3];
__device__ __align__(256) __half g_hh   [(size_t)S_IMG * DMODEL];
__device__ __align__(256) __half g_eh   [(size_t)S_TXT * DMODEL];
__device__ __align__(256) __half g_qh   [(size_t)S_TOT * DMODEL];
__device__ __align__(256) __half g_kh   [(size_t)S_TOT * DMODEL];
__device__ __align__(256) __half g_vt   [(size_t)DMODEL * S_TOT];
__device__ __align__(256) __half g_attnh[(size_t)S_TOT * DMODEL];
__device__ __align__(256) __half g_wtq  [(size_t)D3 * DMODEL];
__device__ __align__(256) __half g_wtaq [(size_t)D3 * DMODEL];
__device__ __align__(256) __half g_wto  [(size_t)DMODEL * DMODEL];
__device__ __align__(256) __half g_wtao [(size_t)DMODEL * DMODEL];

// ---------------------------------------------------------------------------
// helpers
// ---------------------------------------------------------------------------
__device__ __forceinline__ uint32_t smem_u32(const void* p) {
    uint32_t a;
    asm("{ .reg .u64 t; cvta.to.shared.u64 t, %1; cvt.u32.u64 %0, t; }" : "=r"(a) : "l"(p));
    return a;
}
__device__ __forceinline__ uint32_t packh2(float lo, float hi) {
    uint32_t r;
    asm("cvt.rn.f16x2.f32 %0, %1, %2;" : "=r"(r) : "f"(hi), "f"(lo));
    return r;
}
__device__ __forceinline__ uint32_t ex2h2(uint32_t x) {
    uint32_t r;
    asm("ex2.approx.f16x2 %0, %1;" : "=r"(r) : "r"(x));
    return r;
}
__device__ __forceinline__ void cp16(uint32_t saddr, const void* gptr) {
    asm volatile("cp.async.cg.shared.global [%0], [%1], 16;" :: "r"(saddr), "l"(gptr));
}
__device__ __forceinline__ void ldmx4(uint4& f, uint32_t addr) {
    asm volatile("ldmatrix.sync.aligned.m8n8.x4.shared.b16 {%0,%1,%2,%3}, [%4];"
                 : "=r"(f.x), "=r"(f.y), "=r"(f.z), "=r"(f.w) : "r"(addr));
}
#define MMA16816(acc, a, b0, b1)                                               \
    asm volatile("mma.sync.aligned.m16n8k16.row.col.f32.f16.f16.f32 "          \
                 "{%0,%1,%2,%3}, {%4,%5,%6,%7}, {%8,%9}, {%0,%1,%2,%3};"       \
                 : "+f"((acc)[0]), "+f"((acc)[1]), "+f"((acc)[2]), "+f"((acc)[3]) \
                 : "r"((a).x), "r"((a).y), "r"((a).z), "r"((a).w),             \
                   "r"(b0), "r"(b1))

// ---------------------------------------------------------------------------
// fp16 cp.async NT GEMM, 128x128 tile, K-tile 64, 3-stage ring (R12 proven).
// R13: dead batch params removed; out dtype templated.
// ---------------------------------------------------------------------------
#define STAGE_BYTES 32768
#define NSTAGE 3
#define GEMM_SMEM_BYTES (NSTAGE * STAGE_BYTES)   // 98304

template<int OUT_HALF>
__global__ __launch_bounds__(256, 2)
void gemm_nt_h(const __half* __restrict__ A, const __half* __restrict__ B,
               const float* __restrict__ bias, void* __restrict__ Cv,
               int K, int lda, int ldb, int ldc)
{
    extern __shared__ char smem[];
    const uint32_t sbase = smem_u32(smem);
    const int tid    = threadIdx.x;
    const int lane   = tid & 31;
    const int wid    = tid >> 5;
    const int warp_m = wid >> 2;
    const int warp_n = wid & 3;
    const int bm     = blockIdx.y * 128;
    const int bn     = blockIdx.x * 128;

    A += (size_t)bm * lda;
    B += (size_t)bn * ldb;

    uint32_t soff[4];
    size_t   goa[4], gob[4];
#pragma unroll
    for (int j = 0; j < 4; j++) {
        const int c  = tid + j * 256;
        const int r  = c >> 3;
        const int kc = c & 7;
        soff[j] = (uint32_t)(r * 128 + ((kc ^ (r & 7)) * 16));
        goa[j]  = (size_t)r * lda + kc * 8;
        gob[j]  = (size_t)r * ldb + kc * 8;
    }

    const int T = K >> 6;

#pragma unroll
    for (int s = 0; s < 2; s++) {
        const uint32_t sa = sbase + s * STAGE_BYTES;
#pragma unroll
        for (int j = 0; j < 4; j++) {
            cp16(sa + soff[j],         A + goa[j] + s * 64);
            cp16(sa + 16384 + soff[j], B + gob[j] + s * 64);
        }
        asm volatile("cp.async.commit_group;");
    }

    float acc[4][4][4];
#pragma unroll
    for (int m = 0; m < 4; m++)
#pragma unroll
        for (int n = 0; n < 4; n++)
#pragma unroll
            for (int x = 0; x < 4; x++) acc[m][n][x] = 0.0f;

    const int p    = lane >> 3;
    const int li   = lane & 7;
    const int rA0  = warp_m * 64 + (p & 1) * 8 + li;
    const int rB0  = warp_n * 32 + (p & 1) * 8 + li;
    const int kaddp = p >> 1;

    int cur = 0, nxt = 2;
    for (int t = 0; t < T; t++) {
        asm volatile("cp.async.wait_group 1;");
        __syncthreads();

        {
            const int kt = t + 2;
            if (kt < T) {
                const uint32_t sa = sbase + nxt * STAGE_BYTES;
#pragma unroll
                for (int j = 0; j < 4; j++) {
                    cp16(sa + soff[j],         A + goa[j] + (size_t)kt * 64);
                    cp16(sa + 16384 + soff[j], B + gob[j] + (size_t)kt * 64);
                }
            }
            asm volatile("cp.async.commit_group;");
        }

        const uint32_t st = sbase + cur * STAGE_BYTES;
#pragma unroll
        for (int ks = 0; ks < 4; ks++) {
            const int kc = ks * 2 + kaddp;
            uint4 af[4];
#pragma unroll
            for (int mt = 0; mt < 4; mt++) {
                const int row = rA0 + mt * 16;
                ldmx4(af[mt], st + row * 128 + ((kc ^ (row & 7)) * 16));
            }
            uint4 bq[2];
#pragma unroll
            for (int ntp = 0; ntp < 2; ntp++) {
                const int row = rB0 + ntp * 16;
                ldmx4(bq[ntp], st + 16384 + row * 128 + ((kc ^ (row & 7)) * 16));
            }
            uint2 bf[4];
            bf[0] = make_uint2(bq[0].x, bq[0].z);
            bf[1] = make_uint2(bq[0].y, bq[0].w);
            bf[2] = make_uint2(bq[1].x, bq[1].z);
            bf[3] = make_uint2(bq[1].y, bq[1].w);
#pragma unroll
            for (int m = 0; m < 4; m++)
#pragma unroll
                for (int n = 0; n < 4; n++)
                    MMA16816(acc[m][n], af[m], bf[n].x, bf[n].y);
        }

        cur = (cur == 2) ? 0 : cur + 1;
        nxt = (nxt == 2) ? 0 : nxt + 1;
    }

    const int g  = lane >> 2;
    const int tg = lane & 3;
    if (OUT_HALF) {
        __half* C = (__half*)Cv;
#pragma unroll
        for (int m = 0; m < 4; m++) {
            const int row0 = bm + warp_m * 64 + m * 16 + g;
#pragma unroll
            for (int n = 0; n < 4; n++) {
                const int col = bn + warp_n * 32 + n * 8 + tg * 2;
                float bx = 0.f, by = 0.f;
                if (bias) { bx = bias[col]; by = bias[col + 1]; }
                *(uint32_t*)(C + (size_t)row0 * ldc + col) =
                    packh2(acc[m][n][0] + bx, acc[m][n][1] + by);
                *(uint32_t*)(C + (size_t)(row0 + 8) * ldc + col) =
                    packh2(acc[m][n][2] + bx, acc[m][n][3] + by);
            }
        }
    } else {
        float* C = (float*)Cv;
#pragma unroll
        for (int m = 0; m < 4; m++) {
            const int row0 = bm + warp_m * 64 + m * 16 + g;
#pragma unroll
            for (int n = 0; n < 4; n++) {
                const int col = bn + warp_n * 32 + n * 8 + tg * 2;
                float bx = 0.f, by = 0.f;
                if (bias) { bx = bias[col]; by = bias[col + 1]; }
                *(float2*)(C + (size_t)row0 * ldc + col) =
                    make_float2(acc[m][n][0] + bx, acc[m][n][1] + by);
                *(float2*)(C + (size_t)(row0 + 8) * ldc + col) =
                    make_float2(acc[m][n][2] + bx, acc[m][n][3] + by);
            }
        }
    }
}

// ---------------------------------------------------------------------------
// Fused flash attention R13: KV-block 64, 2 CTAs/SM (smem 100KB), Q frags
// re-read from smem each block, ones-row mma sums kept.
// smem: Q 32KB | 2 x (K 16KB(4 sec x 4KB) + V 18KB(2 sec x 9216)).
// ---------------------------------------------------------------------------
#define FA_QSM   32768
#define FA_KSEC  4096
#define FA_KB    16384
#define FA_VSEC  9216
#define FA_VB    (2 * FA_VSEC)     // 18432
#define FA_KV    (FA_KB + FA_VB)   // 34816
#define FA_SMEM  (FA_QSM + 2 * FA_KV)   // 102400
#define NBLK64   (S_TOT / 64)      // 40

__global__ __launch_bounds__(256, 2)
void flash_attn(const __half* __restrict__ Qg, const __half* __restrict__ Kg,
                const __half* __restrict__ VTg, __half* __restrict__ Og)
{
    extern __shared__ char smem[];
    const uint32_t sbase = smem_u32(smem);
    const int tid  = threadIdx.x;
    const int lane = tid & 31;
    const int wid  = tid >> 5;
    const int qb   = blockIdx.x;
    const int h    = blockIdx.y;

    // --- staging precompute ---
    // Q sections: 128 rows x 4 chunks; thread takes 2 chunks (j=0,1)
    uint32_t soffQ[2];
    int rQ[2], kcQ8[2];
#pragma unroll
    for (int j = 0; j < 2; j++) {
        const int c  = tid + j * 256;
        const int r  = c >> 2;
        const int kc = c & 3;
        soffQ[j] = (uint32_t)(r * 64 + ((kc ^ ((r >> 1) & 3)) * 16));
        rQ[j]    = r;
        kcQ8[j]  = kc * 8;
    }
    // K sections: 64 rows x 4 chunks; thread takes exactly 1 chunk
    const int rK  = tid >> 2;
    const int kcK = tid & 3;
    const uint32_t soffK = (uint32_t)(rK * 64 + ((kcK ^ ((rK >> 1) & 3)) * 16));
    // V sections: 128 loaded rows x 4 chunks; thread takes 2 chunks
    // (same indexing as Q)
    const __half* Qp = Qg + (size_t)(qb * 128) * DMODEL + h * DH;
    const __half* Kp = Kg + h * DH;
    const __half* Vp = VTg + (size_t)(h * DH) * S_TOT;

    // --- V pad rows init (row 128 = ones, 129..143 = 0), both bufs, 2 secs ---
#pragma unroll
    for (int bs = 0; bs < 4; bs++) {
        const int buf = bs >> 1;
        const int sec = bs & 1;
        const uint32_t base = FA_QSM + buf * FA_KV + FA_KB
                            + sec * FA_VSEC + 128 * 64;
        *(uint32_t*)(smem + base + tid * 4) = (tid < 16) ? 0x3C003C00u : 0u;
    }

    // --- Q + KV block 0 -> group 0 ---
#pragma unroll
    for (int sec = 0; sec < 4; sec++)
#pragma unroll
        for (int j = 0; j < 2; j++)
            cp16(sbase + sec * 8192 + soffQ[j],
                 Qp + (size_t)rQ[j] * DMODEL + sec * 32 + kcQ8[j]);
    {
        const uint32_t kb = sbase + FA_QSM;
        const uint32_t vb = kb + FA_KB;
#pragma unroll
        for (int sec = 0; sec < 4; sec++)
            cp16(kb + sec * FA_KSEC + soffK,
                 Kp + (size_t)rK * DMODEL + sec * 32 + kcK * 8);
#pragma unroll
        for (int sec = 0; sec < 2; sec++)
#pragma unroll
            for (int j = 0; j < 2; j++)
                cp16(vb + sec * FA_VSEC + soffQ[j],
                     Vp + (size_t)rQ[j] * S_TOT + sec * 32 + kcQ8[j]);
    }
    asm volatile("cp.async.commit_group;");
    // --- KV block 1 -> group 1 ---
    {
        const uint32_t kb = sbase + FA_QSM + FA_KV;
        const uint32_t vb = kb + FA_KB;
#pragma unroll
        for (int sec = 0; sec < 4; sec++)
            cp16(kb + sec * FA_KSEC + soffK,
                 Kp + (size_t)(64 + rK) * DMODEL + sec * 32 + kcK * 8);
#pragma unroll
        for (int sec = 0; sec < 2; sec++)
#pragma unroll
            for (int j = 0; j < 2; j++)
                cp16(vb + sec * FA_VSEC + soffQ[j],
                     Vp + (size_t)rQ[j] * S_TOT + 64 + sec * 32 + kcQ8[j]);
    }
    asm volatile("cp.async.commit_group;");

    const int p     = lane >> 3;
    const int li    = lane & 7;
    const int kaddp = p >> 1;
    const int rowQ  = wid * 16 + (p & 1) * 8 + li;
    const int rB0   = (p & 1) * 8 + li;
    const int g     = lane >> 2;
    const int tg    = lane & 3;

    float mrow[2] = {-1e30f, -1e30f};
    float o[18][4];
#pragma unroll
    for (int j = 0; j < 18; j++)
#pragma unroll
        for (int x = 0; x < 4; x++) o[j][x] = 0.f;

    for (int jb = 0; jb < NBLK64; jb++) {
        asm volatile("cp.async.wait_group 1;");
        __syncthreads();

        const uint32_t kb = sbase + FA_QSM + (jb & 1) * FA_KV;
        const uint32_t vb = kb + FA_KB;

        // ---- S = Q @ K^T (64 kv cols) ----
        float sacc[8][4];
#pragma unroll
        for (int j = 0; j < 8; j++)
#pragma unroll
            for (int x = 0; x < 4; x++) sacc[j][x] = 0.f;
#pragma unroll
        for (int kc = 0; kc < 8; kc++) {
            const int sec = kc >> 1;
            const int c   = (kc & 1) * 2 + kaddp;
            uint4 qa;
            ldmx4(qa, sbase + sec * 8192 + rowQ * 64
                      + ((c ^ ((rowQ >> 1) & 3)) * 16));
#pragma unroll
            for (int np = 0; np < 4; np++) {
                const int row = np * 16 + rB0;
                uint4 bq;
                ldmx4(bq, kb + sec * FA_KSEC + row * 64
                          + ((c ^ ((row >> 1) & 3)) * 16));
                MMA16816(sacc[np * 2],     qa, bq.x, bq.z);
                MMA16816(sacc[np * 2 + 1], qa, bq.y, bq.w);
            }
        }

        // ---- online softmax (log2 domain, ex2.f16x2) ----
        float mx0 = -1e30f, mx1 = -1e30f;
#pragma unroll
        for (int j = 0; j < 8; j++) {
            mx0 = fmaxf(mx0, fmaxf(sacc[j][0], sacc[j][1]));
            mx1 = fmaxf(mx1, fmaxf(sacc[j][2], sacc[j][3]));
        }
        mx0 = fmaxf(mx0, __shfl_xor_sync(0xffffffffu, mx0, 1));
        mx0 = fmaxf(mx0, __shfl_xor_sync(0xffffffffu, mx0, 2));
        mx1 = fmaxf(mx1, __shfl_xor_sync(0xffffffffu, mx1, 1));
        mx1 = fmaxf(mx1, __shfl_xor_sync(0xffffffffu, mx1, 2));

        const float mn0 = fmaxf(mrow[0], mx0);
        const float mn1 = fmaxf(mrow[1], mx1);
        const float sc0 = exp2f(mrow[0] - mn0);
        const float sc1 = exp2f(mrow[1] - mn1);
        mrow[0] = mn0; mrow[1] = mn1;

        uint32_t pf[8][2];
#pragma unroll
        for (int j = 0; j < 8; j++) {
            pf[j][0] = ex2h2(packh2(sacc[j][0] - mn0, sacc[j][1] - mn0));
            pf[j][1] = ex2h2(packh2(sacc[j][2] - mn1, sacc[j][3] - mn1));
        }
#pragma unroll
        for (int j = 0; j < 18; j++) {
            o[j][0] *= sc0; o[j][1] *= sc0;
            o[j][2] *= sc1; o[j][3] *= sc1;
        }

        // ---- O += P @ V (np=8 tile carries ones-row -> row sums) ----
#pragma unroll
        for (int kc = 0; kc < 4; kc++) {
            const int sec = kc >> 1;
            const int c   = (kc & 1) * 2 + kaddp;
            uint4 a;
            a.x = pf[kc * 2][0];
            a.y = pf[kc * 2][1];
            a.z = pf[kc * 2 + 1][0];
            a.w = pf[kc * 2 + 1][1];
#pragma unroll
            for (int np = 0; np < 9; np++) {
                const int row = np * 16 + rB0;
                uint4 bq;
                ldmx4(bq, vb + sec * FA_VSEC + row * 64
                          + ((c ^ ((row >> 1) & 3)) * 16));
                MMA16816(o[np * 2],     a, bq.x, bq.z);
                MMA16816(o[np * 2 + 1], a, bq.y, bq.w);
            }
        }

        __syncthreads();   // all reads of buffer (jb&1) done before refill

        const int nb = jb + 2;
        if (nb < NBLK64) {
            const uint32_t nkb = sbase + FA_QSM + (nb & 1) * FA_KV;
            const uint32_t nvb = nkb + FA_KB;
#pragma unroll
            for (int sec = 0; sec < 4; sec++)
                cp16(nkb + sec * FA_KSEC + soffK,
                     Kp + (size_t)(nb * 64 + rK) * DMODEL + sec * 32 + kcK * 8);
#pragma unroll
            for (int sec = 0; sec < 2; sec++)
#pragma unroll
                for (int j = 0; j < 2; j++)
                    cp16(nvb + sec * FA_VSEC + soffQ[j],
                         Vp + (size_t)rQ[j] * S_TOT + nb * 64 + sec * 32 + kcQ8[j]);
        }
        asm volatile("cp.async.commit_group;");
    }

    // ---- finalize: l from ones-row column, divide, store fp16 ----
    const float l0 = __shfl_sync(0xffffffffu, o[16][0], lane & 28);
    const float l1 = __shfl_sync(0xffffffffu, o[16][2], lane & 28);
    const float inv0 = 1.0f / l0;
    const float inv1 = 1.0f / l1;
    __half* Op = Og + (size_t)(qb * 128) * DMODEL + h * DH;
#pragma unroll
    for (int j = 0; j < 16; j++) {
        const int col  = j * 8 + tg * 2;
        const int row0 = wid * 16 + g;
        *(uint32_t*)(Op + (size_t)row0 * DMODEL + col) =
            packh2(o[j][0] * inv0, o[j][1] * inv0);
        *(uint32_t*)(Op + (size_t)(row0 + 8) * DMODEL + col) =
            packh2(o[j][2] * inv1, o[j][3] * inv1);
    }
}

// ---------------------------------------------------------------------------
// Merged float->half
// ---------------------------------------------------------------------------
__global__ __launch_bounds__(256)
void f2h_all(const float* __restrict__ hidden, const float* __restrict__ enc,
             __half* __restrict__ hh, __half* __restrict__ eh)
{
    const int b = blockIdx.x;
    const float* in;
    __half* out;
    size_t i;
    if (b < (S_IMG * DMODEL) / 1024) {
        in = hidden; out = hh;
        i = ((size_t)b * 256 + threadIdx.x) * 4;
    } else {
        in = enc; out = eh;
        i = ((size_t)(b - (S_IMG * DMODEL) / 1024) * 256 + threadIdx.x) * 4;
    }
    float4 v = *(const float4*)(in + i);
    *(uint2*)(out + i) = make_uint2(packh2(v.x, v.y), packh2(v.z, v.w));
}

// ---------------------------------------------------------------------------
// Merged 64x64 transpose fp32->fp16 for all 4 weights
// ---------------------------------------------------------------------------
__global__ __launch_bounds__(256)
void transpose_all(const float* __restrict__ w0, const float* __restrict__ w1,
                   const float* __restrict__ w2, const float* __restrict__ w3,
                   __half* __restrict__ o0, __half* __restrict__ o1,
                   __half* __restrict__ o2, __half* __restrict__ o3)
{
    const int z = blockIdx.z;
    const float* in;
    __half* out;
    int R, C;
    if (z == 0)      { in = w0; out = o0; R = DMODEL; C = D3; }
    else if (z == 1) { in = w1; out = o1; R = DMODEL; C = D3; }
    else if (z == 2) { in = w2; out = o2; R = DMODEL; C = DMODEL; }
    else             { in = w3; out = o3; R = DMODEL; C = DMODEL; }
    const int bx = blockIdx.x * 64;
    const int by = blockIdx.y * 64;
    if (bx >= C) return;

    __shared__ float t[64][65];
    const int tx4 = (threadIdx.x & 15) * 4;
    const int ty  = threadIdx.x >> 4;
#pragma unroll
    for (int j = 0; j < 4; j++) {
        const int row = ty + j * 16;
        float4 v = *(const float4*)(in + (size_t)(by + row) * C + bx + tx4);
        t[row][tx4 + 0] = v.x; t[row][tx4 + 1] = v.y;
        t[row][tx4 + 2] = v.z; t[row][tx4 + 3] = v.w;
    }
    __syncthreads();
#pragma unroll
    for (int j = 0; j < 4; j++) {
        const int orow = ty + j * 16;
        uint2 w = make_uint2(
            packh2(t[tx4 + 0][orow], t[tx4 + 1][orow]),
            packh2(t[tx4 + 2][orow], t[tx4 + 3][orow]));
        *(uint2*)(out + (size_t)(bx + orow) * R + by + tx4) = w;
    }
}

// ---------------------------------------------------------------------------
// Fused RMSNorm + RoPE (fp16 in) -> fp16 q (scale*log2e), k, V^T
// ---------------------------------------------------------------------------
__device__ __forceinline__ float warp_sum(float v) {
#pragma unroll
    for (int o = 16; o > 0; o >>= 1) v += __shfl_xor_sync(0xffffffffu, v, o);
    return v;
}

__global__ __launch_bounds__(128)
void fuse_norm_rope(const __half* __restrict__ qkv, const __half* __restrict__ eqkv,
                    const int* __restrict__ ids,
                    const float* __restrict__ nq_w,  const float* __restrict__ nk_w,
                    const float* __restrict__ naq_w, const float* __restrict__ nak_w,
                    __half* __restrict__ Q, __half* __restrict__ Ko,
                    __half* __restrict__ VT)
{
    const int s = blockIdx.x;
    const int h = blockIdx.y;
    const int d = threadIdx.x;

    const __half* src;
    const float* qw;
    const float* kw;
    if (s < S_TXT) { src = eqkv + (size_t)s * D3;           qw = naq_w; kw = nak_w; }
    else           { src = qkv  + (size_t)(s - S_TXT) * D3; qw = nq_w;  kw = nk_w; }

    float qv = __half2float(src[h * DH + d]);
    float kv = __half2float(src[DMODEL   + h * DH + d]);
    float vv = __half2float(src[2*DMODEL + h * DH + d]);

    __shared__ float sq[4], sk[4];
    float wq = warp_sum(qv * qv);
    float wk = warp_sum(kv * kv);
    const int w = d >> 5;
    if ((d & 31) == 0) { sq[w] = wq; sk[w] = wk; }
    __syncthreads();
    float qsum = sq[0] + sq[1] + sq[2] + sq[3];
    float ksum = sk[0] + sk[1] + sk[2] + sk[3];
    float qn = qv * rsqrtf(qsum * (1.0f / DH) + 1e-5f) * qw[d];
    float kn = kv * rsqrtf(ksum * (1.0f / DH) + 1e-5f) * kw[d];

    const int pr = d >> 1;
    int axis, base, dax;
    if      (pr < 8)  { axis = 0; base = 0;  dax = 16; }
    else if (pr < 36) { axis = 1; base = 8;  dax = 56; }
    else              { axis = 2; base = 36; dax = 56; }
    float e    = (2.0f * (float)(pr - base)) / (float)dax;
    float freq = expf(-e * 9.210340371976184f);
    float pos  = (float)ids[s * 3 + axis];
    float ang  = pos * freq;
    float cs, sn;
    sincosf(ang, &sn, &cs);

    float q_other = __shfl_xor_sync(0xffffffffu, qn, 1);
    float k_other = __shfl_xor_sync(0xffffffffu, kn, 1);
    float qr, kr;
    if (d & 1) { qr = qn * cs + q_other * sn; kr = kn * cs + k_other * sn; }
    else       { qr = qn * cs - q_other * sn; kr = kn * cs - k_other * sn; }

    const size_t o = (size_t)s * DMODEL + h * DH + d;
    Q[o]  = __float2half(qr * (0.08838834764831845f * 1.4426950408889634f));
    Ko[o] = __float2half(kr);
    VT[(size_t)(h * DH + d) * S_TOT + s] = __float2half(vv);
}

// ---------------------------------------------------------------------------
// kernel_launch
// ---------------------------------------------------------------------------
extern "C" void kernel_launch(void* const* d_in, const int* in_sizes, int n_in,
                              void* d_out, int out_size)
{
    const float* hidden     = (const float*)d_in[0];
    const float* enc        = (const float*)d_in[1];
    const int*   ids        = (const int*)  d_in[2];
    const float* w_qkv      = (const float*)d_in[3];
    const float* w_add_qkv  = (const float*)d_in[4];
    const float* b_add_qkv  = (const float*)d_in[5];
    const float* w_out      = (const float*)d_in[6];
    const float* b_out      = (const float*)d_in[7];
    const float* w_add_out  = (const float*)d_in[8];
    const float* b_add_out  = (const float*)d_in[9];
    const float* norm_q_w   = (const float*)d_in[10];
    const float* norm_k_w   = (const float*)d_in[11];
    const float* norm_aq_w  = (const float*)d_in[12];
    const float* norm_ak_w  = (const float*)d_in[13];
    float* out = (float*)d_out;

    __half *qkvh, *eqkvh, *hh, *eh, *qh, *kh, *vt, *attnh, *wtq, *wtaq, *wto, *wtao;
    cudaGetSymbolAddress((void**)&qkvh,  g_qkvh);
    cudaGetSymbolAddress((void**)&eqkvh, g_eqkvh);
    cudaGetSymbolAddress((void**)&hh,    g_hh);
    cudaGetSymbolAddress((void**)&eh,    g_eh);
    cudaGetSymbolAddress((void**)&qh,    g_qh);
    cudaGetSymbolAddress((void**)&kh,    g_kh);
    cudaGetSymbolAddress((void**)&vt,    g_vt);
    cudaGetSymbolAddress((void**)&attnh, g_attnh);
    cudaGetSymbolAddress((void**)&wtq,   g_wtq);
    cudaGetSymbolAddress((void**)&wtaq,  g_wtaq);
    cudaGetSymbolAddress((void**)&wto,   g_wto);
    cudaGetSymbolAddress((void**)&wtao,  g_wtao);

    cudaFuncSetAttribute(gemm_nt_h<0>, cudaFuncAttributeMaxDynamicSharedMemorySize,
                         GEMM_SMEM_BYTES);
    cudaFuncSetAttribute(gemm_nt_h<1>, cudaFuncAttributeMaxDynamicSharedMemorySize,
                         GEMM_SMEM_BYTES);
    cudaFuncSetAttribute(flash_attn, cudaFuncAttributeMaxDynamicSharedMemorySize,
                         FA_SMEM);

    // 0) convert activations + transpose/convert all weights (2 launches)
    f2h_all<<<(S_IMG * DMODEL + S_TXT * DMODEL) / 1024, 256>>>(hidden, enc, hh, eh);
    transpose_all<<<dim3(D3/64, DMODEL/64, 4), 256>>>(
        w_qkv, w_add_qkv, w_out, w_add_out, wtq, wtaq, wto, wtao);

    // 1) qkv = hidden @ w_qkv            (fp16 out)
    gemm_nt_h<1><<<dim3(D3/128, S_IMG/128), 256, GEMM_SMEM_BYTES>>>(
        hh, wtq, nullptr, qkvh, DMODEL, DMODEL, DMODEL, D3);

    // 2) eqkv = enc @ w_add_qkv + b      (fp16 out)
    gemm_nt_h<1><<<dim3(D3/128, S_TXT/128), 256, GEMM_SMEM_BYTES>>>(
        eh, wtaq, b_add_qkv, eqkvh, DMODEL, DMODEL, DMODEL, D3);

    // 3) RMSNorm + RoPE -> fp16 q,k and fp16 V^T
    fuse_norm_rope<<<dim3(S_TOT, NHEADS), 128>>>(
        qkvh, eqkvh, ids, norm_q_w, norm_k_w, norm_aq_w, norm_ak_w, qh, kh, vt);

    // 4) fused attention -> attnh fp16 [S, 3072]
    flash_attn<<<dim3(S_TOT/128, NHEADS), 256, FA_SMEM>>>(qh, kh, vt, attnh);

    // 5) img_out = attn[512:] @ w_out + b_out
    gemm_nt_h<0><<<dim3(DMODEL/128, S_IMG/128), 256, GEMM_SMEM_BYTES>>>(
        attnh + (size_t)S_TXT * DMODEL, wto, b_out, out,
        DMODEL, DMODEL, DMODEL, DMODEL);

    // 6) enc_out = attn[:512] @ w_add_out + b_add_out
    gemm_nt_h<0><<<dim3(DMODEL/128, S_TXT/128), 256, GEMM_SMEM_BYTES>>>(
        attnh, wtao, b_add_out, out + (size_t)S_IMG * DMODEL,
        DMODEL, DMODEL, DMODEL, DMODEL);
}

// round 14
// speedup vs baseline: 1.2229x; 1.0078x over previous
#include <cuda_runtime.h>
#include <cuda_fp16.h>
#include <cstdint>
#include <math.h>

// ---------------------------------------------------------------------------
// Problem constants (Flux dual-stream attention block)
// ---------------------------------------------------------------------------
#define S_TXT   512
#define S_IMG   2048
#define S_TOT   2560
#define DMODEL  3072
#define NHEADS  24
#define DH      128
#define D3      9216

// ---------------------------------------------------------------------------
// Scratch (device globals -- allocation is forbidden)
// ---------------------------------------------------------------------------
__device__ __align__(256) __half g_qkvh [(size_t)S_IMG * D3];
__device__ __align__(256) __half g_eqkvh[(size_t)S_TXT * D3];
__device__ __align__(256) __half g_hh   [(size_t)S_IMG * DMODEL];
__device__ __align__(256) __half g_eh   [(size_t)S_TXT * DMODEL];
__device__ __align__(256) __half g_qh   [(size_t)S_TOT * DMODEL];
__device__ __align__(256) __half g_kh   [(size_t)S_TOT * DMODEL];
__device__ __align__(256) __half g_vt   [(size_t)DMODEL * S_TOT];
__device__ __align__(256) __half g_attnh[(size_t)S_TOT * DMODEL];
__device__ __align__(256) __half g_wtq  [(size_t)D3 * DMODEL];
__device__ __align__(256) __half g_wtaq [(size_t)D3 * DMODEL];
__device__ __align__(256) __half g_wto  [(size_t)DMODEL * DMODEL];
__device__ __align__(256) __half g_wtao [(size_t)DMODEL * DMODEL];

// ---------------------------------------------------------------------------
// helpers
// ---------------------------------------------------------------------------
__device__ __forceinline__ uint32_t smem_u32(const void* p) {
    uint32_t a;
    asm("{ .reg .u64 t; cvta.to.shared.u64 t, %1; cvt.u32.u64 %0, t; }" : "=r"(a) : "l"(p));
    return a;
}
__device__ __forceinline__ uint32_t packh2(float lo, float hi) {
    uint32_t r;
    asm("cvt.rn.f16x2.f32 %0, %1, %2;" : "=r"(r) : "f"(hi), "f"(lo));
    return r;
}
__device__ __forceinline__ uint32_t ex2h2(uint32_t x) {
    uint32_t r;
    asm("ex2.approx.f16x2 %0, %1;" : "=r"(r) : "r"(x));
    return r;
}
__device__ __forceinline__ void cp16(uint32_t saddr, const void* gptr) {
    asm volatile("cp.async.cg.shared.global [%0], [%1], 16;" :: "r"(saddr), "l"(gptr));
}
__device__ __forceinline__ void ldmx4(uint4& f, uint32_t addr) {
    asm volatile("ldmatrix.sync.aligned.m8n8.x4.shared.b16 {%0,%1,%2,%3}, [%4];"
                 : "=r"(f.x), "=r"(f.y), "=r"(f.z), "=r"(f.w) : "r"(addr));
}
#define MMA16816(acc, a, b0, b1)                                               \
    asm volatile("mma.sync.aligned.m16n8k16.row.col.f32.f16.f16.f32 "          \
                 "{%0,%1,%2,%3}, {%4,%5,%6,%7}, {%8,%9}, {%0,%1,%2,%3};"       \
                 : "+f"((acc)[0]), "+f"((acc)[1]), "+f"((acc)[2]), "+f"((acc)[3]) \
                 : "r"((a).x), "r"((a).y), "r"((a).z), "r"((a).w),             \
                   "r"(b0), "r"(b1))

// ---------------------------------------------------------------------------
// Fused dual-problem fp16 NT GEMM (128x128 tile, K-tile 64, 3-stage ring).
// Row blocks [0, split) use problem 1 (A1,B1,bias1,C1); [split, ...) use
// problem 0. Same K/lda/ldb/ldc for both. Eliminates wave-quantization
// between two back-to-back GEMMs on the same weight shape.
// ---------------------------------------------------------------------------
#define STAGE_BYTES 32768
#define NSTAGE 3
#define GEMM_SMEM_BYTES (NSTAGE * STAGE_BYTES)   // 98304

template<int OUT_HALF>
__global__ __launch_bounds__(256, 2)
void gemm_nt_h(const __half* __restrict__ A0, const __half* __restrict__ B0,
               const float* __restrict__ bias0, void* __restrict__ C0v,
               const __half* __restrict__ A1, const __half* __restrict__ B1,
               const float* __restrict__ bias1, void* __restrict__ C1v,
               int split, int K, int lda, int ldb, int ldc)
{
    extern __shared__ char smem[];
    const uint32_t sbase = smem_u32(smem);
    const int tid    = threadIdx.x;
    const int lane   = tid & 31;
    const int wid    = tid >> 5;
    const int warp_m = wid >> 2;
    const int warp_n = wid & 3;
    const int bn     = blockIdx.x * 128;

    const __half* A;
    const __half* B;
    const float*  bias;
    void*         Cv;
    {
        int by = blockIdx.y;
        if (by < split) {
            A = A1 + (size_t)by * 128 * lda;
            B = B1;  bias = bias1;
            Cv = (OUT_HALF ? (void*)((__half*)C1v + (size_t)by * 128 * ldc)
                           : (void*)((float*)C1v + (size_t)by * 128 * ldc));
        } else {
            by -= split;
            A = A0 + (size_t)by * 128 * lda;
            B = B0;  bias = bias0;
            Cv = (OUT_HALF ? (void*)((__half*)C0v + (size_t)by * 128 * ldc)
                           : (void*)((float*)C0v + (size_t)by * 128 * ldc));
        }
    }
    B += (size_t)bn * ldb;

    uint32_t soff[4];
    size_t   goa[4], gob[4];
#pragma unroll
    for (int j = 0; j < 4; j++) {
        const int c  = tid + j * 256;
        const int r  = c >> 3;
        const int kc = c & 7;
        soff[j] = (uint32_t)(r * 128 + ((kc ^ (r & 7)) * 16));
        goa[j]  = (size_t)r * lda + kc * 8;
        gob[j]  = (size_t)r * ldb + kc * 8;
    }

    const int T = K >> 6;

#pragma unroll
    for (int s = 0; s < 2; s++) {
        const uint32_t sa = sbase + s * STAGE_BYTES;
#pragma unroll
        for (int j = 0; j < 4; j++) {
            cp16(sa + soff[j],         A + goa[j] + s * 64);
            cp16(sa + 16384 + soff[j], B + gob[j] + s * 64);
        }
        asm volatile("cp.async.commit_group;");
    }

    float acc[4][4][4];
#pragma unroll
    for (int m = 0; m < 4; m++)
#pragma unroll
        for (int n = 0; n < 4; n++)
#pragma unroll
            for (int x = 0; x < 4; x++) acc[m][n][x] = 0.0f;

    const int p    = lane >> 3;
    const int li   = lane & 7;
    const int rA0  = warp_m * 64 + (p & 1) * 8 + li;
    const int rB0  = warp_n * 32 + (p & 1) * 8 + li;
    const int kaddp = p >> 1;

    int cur = 0, nxt = 2;
    for (int t = 0; t < T; t++) {
        asm volatile("cp.async.wait_group 1;");
        __syncthreads();

        {
            const int kt = t + 2;
            if (kt < T) {
                const uint32_t sa = sbase + nxt * STAGE_BYTES;
#pragma unroll
                for (int j = 0; j < 4; j++) {
                    cp16(sa + soff[j],         A + goa[j] + (size_t)kt * 64);
                    cp16(sa + 16384 + soff[j], B + gob[j] + (size_t)kt * 64);
                }
            }
            asm volatile("cp.async.commit_group;");
        }

        const uint32_t st = sbase + cur * STAGE_BYTES;
#pragma unroll
        for (int ks = 0; ks < 4; ks++) {
            const int kc = ks * 2 + kaddp;
            uint4 af[4];
#pragma unroll
            for (int mt = 0; mt < 4; mt++) {
                const int row = rA0 + mt * 16;
                ldmx4(af[mt], st + row * 128 + ((kc ^ (row & 7)) * 16));
            }
            uint4 bq[2];
#pragma unroll
            for (int ntp = 0; ntp < 2; ntp++) {
                const int row = rB0 + ntp * 16;
                ldmx4(bq[ntp], st + 16384 + row * 128 + ((kc ^ (row & 7)) * 16));
            }
            uint2 bf[4];
            bf[0] = make_uint2(bq[0].x, bq[0].z);
            bf[1] = make_uint2(bq[0].y, bq[0].w);
            bf[2] = make_uint2(bq[1].x, bq[1].z);
            bf[3] = make_uint2(bq[1].y, bq[1].w);
#pragma unroll
            for (int m = 0; m < 4; m++)
#pragma unroll
                for (int n = 0; n < 4; n++)
                    MMA16816(acc[m][n], af[m], bf[n].x, bf[n].y);
        }

        cur = (cur == 2) ? 0 : cur + 1;
        nxt = (nxt == 2) ? 0 : nxt + 1;
    }

    const int g  = lane >> 2;
    const int tg = lane & 3;
    if (OUT_HALF) {
        __half* C = (__half*)Cv;
#pragma unroll
        for (int m = 0; m < 4; m++) {
            const int row0 = warp_m * 64 + m * 16 + g;
#pragma unroll
            for (int n = 0; n < 4; n++) {
                const int col = bn + warp_n * 32 + n * 8 + tg * 2;
                float bx = 0.f, by2 = 0.f;
                if (bias) { bx = bias[col]; by2 = bias[col + 1]; }
                *(uint32_t*)(C + (size_t)row0 * ldc + col) =
                    packh2(acc[m][n][0] + bx, acc[m][n][1] + by2);
                *(uint32_t*)(C + (size_t)(row0 + 8) * ldc + col) =
                    packh2(acc[m][n][2] + bx, acc[m][n][3] + by2);
            }
        }
    } else {
        float* C = (float*)Cv;
#pragma unroll
        for (int m = 0; m < 4; m++) {
            const int row0 = warp_m * 64 + m * 16 + g;
#pragma unroll
            for (int n = 0; n < 4; n++) {
                const int col = bn + warp_n * 32 + n * 8 + tg * 2;
                float bx = 0.f, by2 = 0.f;
                if (bias) { bx = bias[col]; by2 = bias[col + 1]; }
                *(float2*)(C + (size_t)row0 * ldc + col) =
                    make_float2(acc[m][n][0] + bx, acc[m][n][1] + by2);
                *(float2*)(C + (size_t)(row0 + 8) * ldc + col) =
                    make_float2(acc[m][n][2] + bx, acc[m][n][3] + by2);
            }
        }
    }
}

// ---------------------------------------------------------------------------
// Fused flash attention (R13: KV-block 64, 2 CTAs/SM, ones-row mma sums)
// ---------------------------------------------------------------------------
#define FA_QSM   32768
#define FA_KSEC  4096
#define FA_KB    16384
#define FA_VSEC  9216
#define FA_VB    (2 * FA_VSEC)
#define FA_KV    (FA_KB + FA_VB)
#define FA_SMEM  (FA_QSM + 2 * FA_KV)   // 102400
#define NBLK64   (S_TOT / 64)           // 40

__global__ __launch_bounds__(256, 2)
void flash_attn(const __half* __restrict__ Qg, const __half* __restrict__ Kg,
                const __half* __restrict__ VTg, __half* __restrict__ Og)
{
    extern __shared__ char smem[];
    const uint32_t sbase = smem_u32(smem);
    const int tid  = threadIdx.x;
    const int lane = tid & 31;
    const int wid  = tid >> 5;
    const int qb   = blockIdx.x;
    const int h    = blockIdx.y;

    uint32_t soffQ[2];
    int rQ[2], kcQ8[2];
#pragma unroll
    for (int j = 0; j < 2; j++) {
        const int c  = tid + j * 256;
        const int r  = c >> 2;
        const int kc = c & 3;
        soffQ[j] = (uint32_t)(r * 64 + ((kc ^ ((r >> 1) & 3)) * 16));
        rQ[j]    = r;
        kcQ8[j]  = kc * 8;
    }
    const int rK  = tid >> 2;
    const int kcK = tid & 3;
    const uint32_t soffK = (uint32_t)(rK * 64 + ((kcK ^ ((rK >> 1) & 3)) * 16));

    const __half* Qp = Qg + (size_t)(qb * 128) * DMODEL + h * DH;
    const __half* Kp = Kg + h * DH;
    const __half* Vp = VTg + (size_t)(h * DH) * S_TOT;

#pragma unroll
    for (int bs = 0; bs < 4; bs++) {
        const int buf = bs >> 1;
        const int sec = bs & 1;
        const uint32_t base = FA_QSM + buf * FA_KV + FA_KB
                            + sec * FA_VSEC + 128 * 64;
        *(uint32_t*)(smem + base + tid * 4) = (tid < 16) ? 0x3C003C00u : 0u;
    }

#pragma unroll
    for (int sec = 0; sec < 4; sec++)
#pragma unroll
        for (int j = 0; j < 2; j++)
            cp16(sbase + sec * 8192 + soffQ[j],
                 Qp + (size_t)rQ[j] * DMODEL + sec * 32 + kcQ8[j]);
    {
        const uint32_t kb = sbase + FA_QSM;
        const uint32_t vb = kb + FA_KB;
#pragma unroll
        for (int sec = 0; sec < 4; sec++)
            cp16(kb + sec * FA_KSEC + soffK,
                 Kp + (size_t)rK * DMODEL + sec * 32 + kcK * 8);
#pragma unroll
        for (int sec = 0; sec < 2; sec++)
#pragma unroll
            for (int j = 0; j < 2; j++)
                cp16(vb + sec * FA_VSEC + soffQ[j],
                     Vp + (size_t)rQ[j] * S_TOT + sec * 32 + kcQ8[j]);
    }
    asm volatile("cp.async.commit_group;");
    {
        const uint32_t kb = sbase + FA_QSM + FA_KV;
        const uint32_t vb = kb + FA_KB;
#pragma unroll
        for (int sec = 0; sec < 4; sec++)
            cp16(kb + sec * FA_KSEC + soffK,
                 Kp + (size_t)(64 + rK) * DMODEL + sec * 32 + kcK * 8);
#pragma unroll
        for (int sec = 0; sec < 2; sec++)
#pragma unroll
            for (int j = 0; j < 2; j++)
                cp16(vb + sec * FA_VSEC + soffQ[j],
                     Vp + (size_t)rQ[j] * S_TOT + 64 + sec * 32 + kcQ8[j]);
    }
    asm volatile("cp.async.commit_group;");

    const int p     = lane >> 3;
    const int li    = lane & 7;
    const int kaddp = p >> 1;
    const int rowQ  = wid * 16 + (p & 1) * 8 + li;
    const int rB0   = (p & 1) * 8 + li;
    const int g     = lane >> 2;
    const int tg    = lane & 3;

    float mrow[2] = {-1e30f, -1e30f};
    float o[18][4];
#pragma unroll
    for (int j = 0; j < 18; j++)
#pragma unroll
        for (int x = 0; x < 4; x++) o[j][x] = 0.f;

    for (int jb = 0; jb < NBLK64; jb++) {
        asm volatile("cp.async.wait_group 1;");
        __syncthreads();

        const uint32_t kb = sbase + FA_QSM + (jb & 1) * FA_KV;
        const uint32_t vb = kb + FA_KB;

        float sacc[8][4];
#pragma unroll
        for (int j = 0; j < 8; j++)
#pragma unroll
            for (int x = 0; x < 4; x++) sacc[j][x] = 0.f;
#pragma unroll
        for (int kc = 0; kc < 8; kc++) {
            const int sec = kc >> 1;
            const int c   = (kc & 1) * 2 + kaddp;
            uint4 qa;
            ldmx4(qa, sbase + sec * 8192 + rowQ * 64
                      + ((c ^ ((rowQ >> 1) & 3)) * 16));
#pragma unroll
            for (int np = 0; np < 4; np++) {
                const int row = np * 16 + rB0;
                uint4 bq;
                ldmx4(bq, kb + sec * FA_KSEC + row * 64
                          + ((c ^ ((row >> 1) & 3)) * 16));
                MMA16816(sacc[np * 2],     qa, bq.x, bq.z);
                MMA16816(sacc[np * 2 + 1], qa, bq.y, bq.w);
            }
        }

        float mx0 = -1e30f, mx1 = -1e30f;
#pragma unroll
        for (int j = 0; j < 8; j++) {
            mx0 = fmaxf(mx0, fmaxf(sacc[j][0], sacc[j][1]));
            mx1 = fmaxf(mx1, fmaxf(sacc[j][2], sacc[j][3]));
        }
        mx0 = fmaxf(mx0, __shfl_xor_sync(0xffffffffu, mx0, 1));
        mx0 = fmaxf(mx0, __shfl_xor_sync(0xffffffffu, mx0, 2));
        mx1 = fmaxf(mx1, __shfl_xor_sync(0xffffffffu, mx1, 1));
        mx1 = fmaxf(mx1, __shfl_xor_sync(0xffffffffu, mx1, 2));

        const float mn0 = fmaxf(mrow[0], mx0);
        const float mn1 = fmaxf(mrow[1], mx1);
        const float sc0 = exp2f(mrow[0] - mn0);
        const float sc1 = exp2f(mrow[1] - mn1);
        mrow[0] = mn0; mrow[1] = mn1;

        uint32_t pf[8][2];
#pragma unroll
        for (int j = 0; j < 8; j++) {
            pf[j][0] = ex2h2(packh2(sacc[j][0] - mn0, sacc[j][1] - mn0));
            pf[j][1] = ex2h2(packh2(sacc[j][2] - mn1, sacc[j][3] - mn1));
        }
#pragma unroll
        for (int j = 0; j < 18; j++) {
            o[j][0] *= sc0; o[j][1] *= sc0;
            o[j][2] *= sc1; o[j][3] *= sc1;
        }

#pragma unroll
        for (int kc = 0; kc < 4; kc++) {
            const int sec = kc >> 1;
            const int c   = (kc & 1) * 2 + kaddp;
            uint4 a;
            a.x = pf[kc * 2][0];
            a.y = pf[kc * 2][1];
            a.z = pf[kc * 2 + 1][0];
            a.w = pf[kc * 2 + 1][1];
#pragma unroll
            for (int np = 0; np < 9; np++) {
                const int row = np * 16 + rB0;
                uint4 bq;
                ldmx4(bq, vb + sec * FA_VSEC + row * 64
                          + ((c ^ ((row >> 1) & 3)) * 16));
                MMA16816(o[np * 2],     a, bq.x, bq.z);
                MMA16816(o[np * 2 + 1], a, bq.y, bq.w);
            }
        }

        __syncthreads();

        const int nb = jb + 2;
        if (nb < NBLK64) {
            const uint32_t nkb = sbase + FA_QSM + (nb & 1) * FA_KV;
            const uint32_t nvb = nkb + FA_KB;
#pragma unroll
            for (int sec = 0; sec < 4; sec++)
                cp16(nkb + sec * FA_KSEC + soffK,
                     Kp + (size_t)(nb * 64 + rK) * DMODEL + sec * 32 + kcK * 8);
#pragma unroll
            for (int sec = 0; sec < 2; sec++)
#pragma unroll
                for (int j = 0; j < 2; j++)
                    cp16(nvb + sec * FA_VSEC + soffQ[j],
                         Vp + (size_t)rQ[j] * S_TOT + nb * 64 + sec * 32 + kcQ8[j]);
        }
        asm volatile("cp.async.commit_group;");
    }

    const float l0 = __shfl_sync(0xffffffffu, o[16][0], lane & 28);
    const float l1 = __shfl_sync(0xffffffffu, o[16][2], lane & 28);
    const float inv0 = 1.0f / l0;
    const float inv1 = 1.0f / l1;
    __half* Op = Og + (size_t)(qb * 128) * DMODEL + h * DH;
#pragma unroll
    for (int j = 0; j < 16; j++) {
        const int col  = j * 8 + tg * 2;
        const int row0 = wid * 16 + g;
        *(uint32_t*)(Op + (size_t)row0 * DMODEL + col) =
            packh2(o[j][0] * inv0, o[j][1] * inv0);
        *(uint32_t*)(Op + (size_t)(row0 + 8) * DMODEL + col) =
            packh2(o[j][2] * inv1, o[j][3] * inv1);
    }
}

// ---------------------------------------------------------------------------
// Merged float->half
// ---------------------------------------------------------------------------
__global__ __launch_bounds__(256)
void f2h_all(const float* __restrict__ hidden, const float* __restrict__ enc,
             __half* __restrict__ hh, __half* __restrict__ eh)
{
    const int b = blockIdx.x;
    const float* in;
    __half* out;
    size_t i;
    if (b < (S_IMG * DMODEL) / 1024) {
        in = hidden; out = hh;
        i = ((size_t)b * 256 + threadIdx.x) * 4;
    } else {
        in = enc; out = eh;
        i = ((size_t)(b - (S_IMG * DMODEL) / 1024) * 256 + threadIdx.x) * 4;
    }
    float4 v = *(const float4*)(in + i);
    *(uint2*)(out + i) = make_uint2(packh2(v.x, v.y), packh2(v.z, v.w));
}

// ---------------------------------------------------------------------------
// Merged 64x64 transpose fp32->fp16 for all 4 weights
// ---------------------------------------------------------------------------
__global__ __launch_bounds__(256)
void transpose_all(const float* __restrict__ w0, const float* __restrict__ w1,
                   const float* __restrict__ w2, const float* __restrict__ w3,
                   __half* __restrict__ o0, __half* __restrict__ o1,
                   __half* __restrict__ o2, __half* __restrict__ o3)
{
    const int z = blockIdx.z;
    const float* in;
    __half* out;
    int R, C;
    if (z == 0)      { in = w0; out = o0; R = DMODEL; C = D3; }
    else if (z == 1) { in = w1; out = o1; R = DMODEL; C = D3; }
    else if (z == 2) { in = w2; out = o2; R = DMODEL; C = DMODEL; }
    else             { in = w3; out = o3; R = DMODEL; C = DMODEL; }
    const int bx = blockIdx.x * 64;
    const int by = blockIdx.y * 64;
    if (bx >= C) return;

    __shared__ float t[64][65];
    const int tx4 = (threadIdx.x & 15) * 4;
    const int ty  = threadIdx.x >> 4;
#pragma unroll
    for (int j = 0; j < 4; j++) {
        const int row = ty + j * 16;
        float4 v = *(const float4*)(in + (size_t)(by + row) * C + bx + tx4);
        t[row][tx4 + 0] = v.x; t[row][tx4 + 1] = v.y;
        t[row][tx4 + 2] = v.z; t[row][tx4 + 3] = v.w;
    }
    __syncthreads();
#pragma unroll
    for (int j = 0; j < 4; j++) {
        const int orow = ty + j * 16;
        uint2 w = make_uint2(
            packh2(t[tx4 + 0][orow], t[tx4 + 1][orow]),
            packh2(t[tx4 + 2][orow], t[tx4 + 3][orow]));
        *(uint2*)(out + (size_t)(bx + orow) * R + by + tx4) = w;
    }
}

// ---------------------------------------------------------------------------
// Fused RMSNorm + RoPE (fp16 in) -> fp16 q (scale*log2e), k, V^T
// ---------------------------------------------------------------------------
__device__ __forceinline__ float warp_sum(float v) {
#pragma unroll
    for (int o = 16; o > 0; o >>= 1) v += __shfl_xor_sync(0xffffffffu, v, o);
    return v;
}

__global__ __launch_bounds__(128)
void fuse_norm_rope(const __half* __restrict__ qkv, const __half* __restrict__ eqkv,
                    const int* __restrict__ ids,
                    const float* __restrict__ nq_w,  const float* __restrict__ nk_w,
                    const float* __restrict__ naq_w, const float* __restrict__ nak_w,
                    __half* __restrict__ Q, __half* __restrict__ Ko,
                    __half* __restrict__ VT)
{
    const int s = blockIdx.x;
    const int h = blockIdx.y;
    const int d = threadIdx.x;

    const __half* src;
    const float* qw;
    const float* kw;
    if (s < S_TXT) { src = eqkv + (size_t)s * D3;           qw = naq_w; kw = nak_w; }
    else           { src = qkv  + (size_t)(s - S_TXT) * D3; qw = nq_w;  kw = nk_w; }

    float qv = __half2float(src[h * DH + d]);
    float kv = __half2float(src[DMODEL   + h * DH + d]);
    float vv = __half2float(src[2*DMODEL + h * DH + d]);

    __shared__ float sq[4], sk[4];
    float wq = warp_sum(qv * qv);
    float wk = warp_sum(kv * kv);
    const int w = d >> 5;
    if ((d & 31) == 0) { sq[w] = wq; sk[w] = wk; }
    __syncthreads();
    float qsum = sq[0] + sq[1] + sq[2] + sq[3];
    float ksum = sk[0] + sk[1] + sk[2] + sk[3];
    float qn = qv * rsqrtf(qsum * (1.0f / DH) + 1e-5f) * qw[d];
    float kn = kv * rsqrtf(ksum * (1.0f / DH) + 1e-5f) * kw[d];

    const int pr = d >> 1;
    int axis, base, dax;
    if      (pr < 8)  { axis = 0; base = 0;  dax = 16; }
    else if (pr < 36) { axis = 1; base = 8;  dax = 56; }
    else              { axis = 2; base = 36; dax = 56; }
    float e    = (2.0f * (float)(pr - base)) / (float)dax;
    float freq = expf(-e * 9.210340371976184f);
    float pos  = (float)ids[s * 3 + axis];
    float ang  = pos * freq;
    float cs, sn;
    sincosf(ang, &sn, &cs);

    float q_other = __shfl_xor_sync(0xffffffffu, qn, 1);
    float k_other = __shfl_xor_sync(0xffffffffu, kn, 1);
    float qr, kr;
    if (d & 1) { qr = qn * cs + q_other * sn; kr = kn * cs + k_other * sn; }
    else       { qr = qn * cs - q_other * sn; kr = kn * cs - k_other * sn; }

    const size_t o = (size_t)s * DMODEL + h * DH + d;
    Q[o]  = __float2half(qr * (0.08838834764831845f * 1.4426950408889634f));
    Ko[o] = __float2half(kr);
    VT[(size_t)(h * DH + d) * S_TOT + s] = __float2half(vv);
}

// ---------------------------------------------------------------------------
// kernel_launch
// ---------------------------------------------------------------------------
extern "C" void kernel_launch(void* const* d_in, const int* in_sizes, int n_in,
                              void* d_out, int out_size)
{
    const float* hidden     = (const float*)d_in[0];
    const float* enc        = (const float*)d_in[1];
    const int*   ids        = (const int*)  d_in[2];
    const float* w_qkv      = (const float*)d_in[3];
    const float* w_add_qkv  = (const float*)d_in[4];
    const float* b_add_qkv  = (const float*)d_in[5];
    const float* w_out      = (const float*)d_in[6];
    const float* b_out      = (const float*)d_in[7];
    const float* w_add_out  = (const float*)d_in[8];
    const float* b_add_out  = (const float*)d_in[9];
    const float* norm_q_w   = (const float*)d_in[10];
    const float* norm_k_w   = (const float*)d_in[11];
    const float* norm_aq_w  = (const float*)d_in[12];
    const float* norm_ak_w  = (const float*)d_in[13];
    float* out = (float*)d_out;

    __half *qkvh, *eqkvh, *hh, *eh, *qh, *kh, *vt, *attnh, *wtq, *wtaq, *wto, *wtao;
    cudaGetSymbolAddress((void**)&qkvh,  g_qkvh);
    cudaGetSymbolAddress((void**)&eqkvh, g_eqkvh);
    cudaGetSymbolAddress((void**)&hh,    g_hh);
    cudaGetSymbolAddress((void**)&eh,    g_eh);
    cudaGetSymbolAddress((void**)&qh,    g_qh);
    cudaGetSymbolAddress((void**)&kh,    g_kh);
    cudaGetSymbolAddress((void**)&vt,    g_vt);
    cudaGetSymbolAddress((void**)&attnh, g_attnh);
    cudaGetSymbolAddress((void**)&wtq,   g_wtq);
    cudaGetSymbolAddress((void**)&wtaq,  g_wtaq);
    cudaGetSymbolAddress((void**)&wto,   g_wto);
    cudaGetSymbolAddress((void**)&wtao,  g_wtao);

    cudaFuncSetAttribute(gemm_nt_h<0>, cudaFuncAttributeMaxDynamicSharedMemorySize,
                         GEMM_SMEM_BYTES);
    cudaFuncSetAttribute(gemm_nt_h<1>, cudaFuncAttributeMaxDynamicSharedMemorySize,
                         GEMM_SMEM_BYTES);
    cudaFuncSetAttribute(flash_attn, cudaFuncAttributeMaxDynamicSharedMemorySize,
                         FA_SMEM);

    // 0) convert activations + transpose/convert all weights (2 launches)
    f2h_all<<<(S_IMG * DMODEL + S_TXT * DMODEL) / 1024, 256>>>(hidden, enc, hh, eh);
    transpose_all<<<dim3(D3/64, DMODEL/64, 4), 256>>>(
        w_qkv, w_add_qkv, w_out, w_add_out, wtq, wtaq, wto, wtao);

    // 1+2) [eqkv | qkv] fused: rows 0..3 -> enc problem, 4..19 -> img problem
    gemm_nt_h<1><<<dim3(D3/128, S_TOT/128), 256, GEMM_SMEM_BYTES>>>(
        hh, wtq, nullptr, qkvh,
        eh, wtaq, b_add_qkv, eqkvh,
        S_TXT/128, DMODEL, DMODEL, DMODEL, D3);

    // 3) RMSNorm + RoPE -> fp16 q,k and fp16 V^T
    fuse_norm_rope<<<dim3(S_TOT, NHEADS), 128>>>(
        qkvh, eqkvh, ids, norm_q_w, norm_k_w, norm_aq_w, norm_ak_w, qh, kh, vt);

    // 4) fused attention -> attnh fp16 [S, 3072]
    flash_attn<<<dim3(S_TOT/128, NHEADS), 256, FA_SMEM>>>(qh, kh, vt, attnh);

    // 5+6) [enc_out | img_out] fused
    gemm_nt_h<0><<<dim3(DMODEL/128, S_TOT/128), 256, GEMM_SMEM_BYTES>>>(
        attnh + (size_t)S_TXT * DMODEL, wto, b_out, out,
        attnh, wtao, b_add_out, out + (size_t)S_IMG * DMODEL,
        S_TXT/128, DMODEL, DMODEL, DMODEL, DMODEL);
}

// round 15
// speedup vs baseline: 1.2563x; 1.0273x over previous
#include <cuda_runtime.h>
#include <cuda_fp16.h>
#include <cstdint>
#include <math.h>

// ---------------------------------------------------------------------------
// Problem constants (Flux dual-stream attention block)
// ---------------------------------------------------------------------------
#define S_TXT   512
#define S_IMG   2048
#define S_TOT   2560
#define DMODEL  3072
#define NHEADS  24
#define DH      128
#define D3      9216

// ---------------------------------------------------------------------------
// Scratch (device globals -- allocation is forbidden)
// ---------------------------------------------------------------------------
__device__ __align__(256) __half g_qkvh [(size_t)S_IMG * D3];
__device__ __align__(256) __half g_eqkvh[(size_t)S_TXT * D3];
__device__ __align__(256) __half g_hh   [(size_t)S_IMG * DMODEL];
__device__ __align__(256) __half g_eh   [(size_t)S_TXT * DMODEL];
__device__ __align__(256) __half g_qh   [(size_t)S_TOT * DMODEL];
__device__ __align__(256) __half g_kh   [(size_t)S_TOT * DMODEL];
__device__ __align__(256) __half g_vt   [(size_t)DMODEL * S_TOT];
__device__ __align__(256) __half g_attnh[(size_t)S_TOT * DMODEL];
__device__ __align__(256) __half g_wtq  [(size_t)D3 * DMODEL];
__device__ __align__(256) __half g_wtaq [(size_t)D3 * DMODEL];
__device__ __align__(256) __half g_wto  [(size_t)DMODEL * DMODEL];
__device__ __align__(256) __half g_wtao [(size_t)DMODEL * DMODEL];

// ---------------------------------------------------------------------------
// helpers
// ---------------------------------------------------------------------------
__device__ __forceinline__ uint32_t smem_u32(const void* p) {
    uint32_t a;
    asm("{ .reg .u64 t; cvta.to.shared.u64 t, %1; cvt.u32.u64 %0, t; }" : "=r"(a) : "l"(p));
    return a;
}
__device__ __forceinline__ uint32_t packh2(float lo, float hi) {
    uint32_t r;
    asm("cvt.rn.f16x2.f32 %0, %1, %2;" : "=r"(r) : "f"(hi), "f"(lo));
    return r;
}
__device__ __forceinline__ uint32_t ex2h2(uint32_t x) {
    uint32_t r;
    asm("ex2.approx.f16x2 %0, %1;" : "=r"(r) : "r"(x));
    return r;
}
__device__ __forceinline__ void cp16(uint32_t saddr, const void* gptr) {
    asm volatile("cp.async.cg.shared.global [%0], [%1], 16;" :: "r"(saddr), "l"(gptr));
}
__device__ __forceinline__ void ldmx4(uint4& f, uint32_t addr) {
    asm volatile("ldmatrix.sync.aligned.m8n8.x4.shared.b16 {%0,%1,%2,%3}, [%4];"
                 : "=r"(f.x), "=r"(f.y), "=r"(f.z), "=r"(f.w) : "r"(addr));
}
#define MMA16816(acc, a, b0, b1)                                               \
    asm volatile("mma.sync.aligned.m16n8k16.row.col.f32.f16.f16.f32 "          \
                 "{%0,%1,%2,%3}, {%4,%5,%6,%7}, {%8,%9}, {%0,%1,%2,%3};"       \
                 : "+f"((acc)[0]), "+f"((acc)[1]), "+f"((acc)[2]), "+f"((acc)[3]) \
                 : "r"((a).x), "r"((a).y), "r"((a).z), "r"((a).w),             \
                   "r"(b0), "r"(b1))

// ---------------------------------------------------------------------------
// Fused dual-problem fp16 NT GEMM (128x128 tile, K-tile 64, 3-stage ring).
// ---------------------------------------------------------------------------
#define STAGE_BYTES 32768
#define NSTAGE 3
#define GEMM_SMEM_BYTES (NSTAGE * STAGE_BYTES)   // 98304

template<int OUT_HALF>
__global__ __launch_bounds__(256, 2)
void gemm_nt_h(const __half* __restrict__ A0, const __half* __restrict__ B0,
               const float* __restrict__ bias0, void* __restrict__ C0v,
               const __half* __restrict__ A1, const __half* __restrict__ B1,
               const float* __restrict__ bias1, void* __restrict__ C1v,
               int split, int K, int lda, int ldb, int ldc)
{
    extern __shared__ char smem[];
    const uint32_t sbase = smem_u32(smem);
    const int tid    = threadIdx.x;
    const int lane   = tid & 31;
    const int wid    = tid >> 5;
    const int warp_m = wid >> 2;
    const int warp_n = wid & 3;
    const int bn     = blockIdx.x * 128;

    const __half* A;
    const __half* B;
    const float*  bias;
    void*         Cv;
    {
        int by = blockIdx.y;
        if (by < split) {
            A = A1 + (size_t)by * 128 * lda;
            B = B1;  bias = bias1;
            Cv = (OUT_HALF ? (void*)((__half*)C1v + (size_t)by * 128 * ldc)
                           : (void*)((float*)C1v + (size_t)by * 128 * ldc));
        } else {
            by -= split;
            A = A0 + (size_t)by * 128 * lda;
            B = B0;  bias = bias0;
            Cv = (OUT_HALF ? (void*)((__half*)C0v + (size_t)by * 128 * ldc)
                           : (void*)((float*)C0v + (size_t)by * 128 * ldc));
        }
    }
    B += (size_t)bn * ldb;

    uint32_t soff[4];
    size_t   goa[4], gob[4];
#pragma unroll
    for (int j = 0; j < 4; j++) {
        const int c  = tid + j * 256;
        const int r  = c >> 3;
        const int kc = c & 7;
        soff[j] = (uint32_t)(r * 128 + ((kc ^ (r & 7)) * 16));
        goa[j]  = (size_t)r * lda + kc * 8;
        gob[j]  = (size_t)r * ldb + kc * 8;
    }

    const int T = K >> 6;

#pragma unroll
    for (int s = 0; s < 2; s++) {
        const uint32_t sa = sbase + s * STAGE_BYTES;
#pragma unroll
        for (int j = 0; j < 4; j++) {
            cp16(sa + soff[j],         A + goa[j] + s * 64);
            cp16(sa + 16384 + soff[j], B + gob[j] + s * 64);
        }
        asm volatile("cp.async.commit_group;");
    }

    float acc[4][4][4];
#pragma unroll
    for (int m = 0; m < 4; m++)
#pragma unroll
        for (int n = 0; n < 4; n++)
#pragma unroll
            for (int x = 0; x < 4; x++) acc[m][n][x] = 0.0f;

    const int p    = lane >> 3;
    const int li   = lane & 7;
    const int rA0  = warp_m * 64 + (p & 1) * 8 + li;
    const int rB0  = warp_n * 32 + (p & 1) * 8 + li;
    const int kaddp = p >> 1;

    int cur = 0, nxt = 2;
    for (int t = 0; t < T; t++) {
        asm volatile("cp.async.wait_group 1;");
        __syncthreads();

        {
            const int kt = t + 2;
            if (kt < T) {
                const uint32_t sa = sbase + nxt * STAGE_BYTES;
#pragma unroll
                for (int j = 0; j < 4; j++) {
                    cp16(sa + soff[j],         A + goa[j] + (size_t)kt * 64);
                    cp16(sa + 16384 + soff[j], B + gob[j] + (size_t)kt * 64);
                }
            }
            asm volatile("cp.async.commit_group;");
        }

        const uint32_t st = sbase + cur * STAGE_BYTES;
#pragma unroll
        for (int ks = 0; ks < 4; ks++) {
            const int kc = ks * 2 + kaddp;
            uint4 af[4];
#pragma unroll
            for (int mt = 0; mt < 4; mt++) {
                const int row = rA0 + mt * 16;
                ldmx4(af[mt], st + row * 128 + ((kc ^ (row & 7)) * 16));
            }
            uint4 bq[2];
#pragma unroll
            for (int ntp = 0; ntp < 2; ntp++) {
                const int row = rB0 + ntp * 16;
                ldmx4(bq[ntp], st + 16384 + row * 128 + ((kc ^ (row & 7)) * 16));
            }
            uint2 bf[4];
            bf[0] = make_uint2(bq[0].x, bq[0].z);
            bf[1] = make_uint2(bq[0].y, bq[0].w);
            bf[2] = make_uint2(bq[1].x, bq[1].z);
            bf[3] = make_uint2(bq[1].y, bq[1].w);
#pragma unroll
            for (int m = 0; m < 4; m++)
#pragma unroll
                for (int n = 0; n < 4; n++)
                    MMA16816(acc[m][n], af[m], bf[n].x, bf[n].y);
        }

        cur = (cur == 2) ? 0 : cur + 1;
        nxt = (nxt == 2) ? 0 : nxt + 1;
    }

    const int g  = lane >> 2;
    const int tg = lane & 3;
    if (OUT_HALF) {
        __half* C = (__half*)Cv;
#pragma unroll
        for (int m = 0; m < 4; m++) {
            const int row0 = warp_m * 64 + m * 16 + g;
#pragma unroll
            for (int n = 0; n < 4; n++) {
                const int col = bn + warp_n * 32 + n * 8 + tg * 2;
                float bx = 0.f, by2 = 0.f;
                if (bias) { bx = bias[col]; by2 = bias[col + 1]; }
                *(uint32_t*)(C + (size_t)row0 * ldc + col) =
                    packh2(acc[m][n][0] + bx, acc[m][n][1] + by2);
                *(uint32_t*)(C + (size_t)(row0 + 8) * ldc + col) =
                    packh2(acc[m][n][2] + bx, acc[m][n][3] + by2);
            }
        }
    } else {
        float* C = (float*)Cv;
#pragma unroll
        for (int m = 0; m < 4; m++) {
            const int row0 = warp_m * 64 + m * 16 + g;
#pragma unroll
            for (int n = 0; n < 4; n++) {
                const int col = bn + warp_n * 32 + n * 8 + tg * 2;
                float bx = 0.f, by2 = 0.f;
                if (bias) { bx = bias[col]; by2 = bias[col + 1]; }
                *(float2*)(C + (size_t)row0 * ldc + col) =
                    make_float2(acc[m][n][0] + bx, acc[m][n][1] + by2);
                *(float2*)(C + (size_t)(row0 + 8) * ldc + col) =
                    make_float2(acc[m][n][2] + bx, acc[m][n][3] + by2);
            }
        }
    }
}

// ---------------------------------------------------------------------------
// Fused flash attention (R13: KV-block 64, 2 CTAs/SM, ones-row mma sums)
// ---------------------------------------------------------------------------
#define FA_QSM   32768
#define FA_KSEC  4096
#define FA_KB    16384
#define FA_VSEC  9216
#define FA_VB    (2 * FA_VSEC)
#define FA_KV    (FA_KB + FA_VB)
#define FA_SMEM  (FA_QSM + 2 * FA_KV)   // 102400
#define NBLK64   (S_TOT / 64)           // 40

__global__ __launch_bounds__(256, 2)
void flash_attn(const __half* __restrict__ Qg, const __half* __restrict__ Kg,
                const __half* __restrict__ VTg, __half* __restrict__ Og)
{
    extern __shared__ char smem[];
    const uint32_t sbase = smem_u32(smem);
    const int tid  = threadIdx.x;
    const int lane = tid & 31;
    const int wid  = tid >> 5;
    const int qb   = blockIdx.x;
    const int h    = blockIdx.y;

    uint32_t soffQ[2];
    int rQ[2], kcQ8[2];
#pragma unroll
    for (int j = 0; j < 2; j++) {
        const int c  = tid + j * 256;
        const int r  = c >> 2;
        const int kc = c & 3;
        soffQ[j] = (uint32_t)(r * 64 + ((kc ^ ((r >> 1) & 3)) * 16));
        rQ[j]    = r;
        kcQ8[j]  = kc * 8;
    }
    const int rK  = tid >> 2;
    const int kcK = tid & 3;
    const uint32_t soffK = (uint32_t)(rK * 64 + ((kcK ^ ((rK >> 1) & 3)) * 16));

    const __half* Qp = Qg + (size_t)(qb * 128) * DMODEL + h * DH;
    const __half* Kp = Kg + h * DH;
    const __half* Vp = VTg + (size_t)(h * DH) * S_TOT;

#pragma unroll
    for (int bs = 0; bs < 4; bs++) {
        const int buf = bs >> 1;
        const int sec = bs & 1;
        const uint32_t base = FA_QSM + buf * FA_KV + FA_KB
                            + sec * FA_VSEC + 128 * 64;
        *(uint32_t*)(smem + base + tid * 4) = (tid < 16) ? 0x3C003C00u : 0u;
    }

#pragma unroll
    for (int sec = 0; sec < 4; sec++)
#pragma unroll
        for (int j = 0; j < 2; j++)
            cp16(sbase + sec * 8192 + soffQ[j],
                 Qp + (size_t)rQ[j] * DMODEL + sec * 32 + kcQ8[j]);
    {
        const uint32_t kb = sbase + FA_QSM;
        const uint32_t vb = kb + FA_KB;
#pragma unroll
        for (int sec = 0; sec < 4; sec++)
            cp16(kb + sec * FA_KSEC + soffK,
                 Kp + (size_t)rK * DMODEL + sec * 32 + kcK * 8);
#pragma unroll
        for (int sec = 0; sec < 2; sec++)
#pragma unroll
            for (int j = 0; j < 2; j++)
                cp16(vb + sec * FA_VSEC + soffQ[j],
                     Vp + (size_t)rQ[j] * S_TOT + sec * 32 + kcQ8[j]);
    }
    asm volatile("cp.async.commit_group;");
    {
        const uint32_t kb = sbase + FA_QSM + FA_KV;
        const uint32_t vb = kb + FA_KB;
#pragma unroll
        for (int sec = 0; sec < 4; sec++)
            cp16(kb + sec * FA_KSEC + soffK,
                 Kp + (size_t)(64 + rK) * DMODEL + sec * 32 + kcK * 8);
#pragma unroll
        for (int sec = 0; sec < 2; sec++)
#pragma unroll
            for (int j = 0; j < 2; j++)
                cp16(vb + sec * FA_VSEC + soffQ[j],
                     Vp + (size_t)rQ[j] * S_TOT + 64 + sec * 32 + kcQ8[j]);
    }
    asm volatile("cp.async.commit_group;");

    const int p     = lane >> 3;
    const int li    = lane & 7;
    const int kaddp = p >> 1;
    const int rowQ  = wid * 16 + (p & 1) * 8 + li;
    const int rB0   = (p & 1) * 8 + li;
    const int g     = lane >> 2;
    const int tg    = lane & 3;

    float mrow[2] = {-1e30f, -1e30f};
    float o[18][4];
#pragma unroll
    for (int j = 0; j < 18; j++)
#pragma unroll
        for (int x = 0; x < 4; x++) o[j][x] = 0.f;

    for (int jb = 0; jb < NBLK64; jb++) {
        asm volatile("cp.async.wait_group 1;");
        __syncthreads();

        const uint32_t kb = sbase + FA_QSM + (jb & 1) * FA_KV;
        const uint32_t vb = kb + FA_KB;

        float sacc[8][4];
#pragma unroll
        for (int j = 0; j < 8; j++)
#pragma unroll
            for (int x = 0; x < 4; x++) sacc[j][x] = 0.f;
#pragma unroll
        for (int kc = 0; kc < 8; kc++) {
            const int sec = kc >> 1;
            const int c   = (kc & 1) * 2 + kaddp;
            uint4 qa;
            ldmx4(qa, sbase + sec * 8192 + rowQ * 64
                      + ((c ^ ((rowQ >> 1) & 3)) * 16));
#pragma unroll
            for (int np = 0; np < 4; np++) {
                const int row = np * 16 + rB0;
                uint4 bq;
                ldmx4(bq, kb + sec * FA_KSEC + row * 64
                          + ((c ^ ((row >> 1) & 3)) * 16));
                MMA16816(sacc[np * 2],     qa, bq.x, bq.z);
                MMA16816(sacc[np * 2 + 1], qa, bq.y, bq.w);
            }
        }

        float mx0 = -1e30f, mx1 = -1e30f;
#pragma unroll
        for (int j = 0; j < 8; j++) {
            mx0 = fmaxf(mx0, fmaxf(sacc[j][0], sacc[j][1]));
            mx1 = fmaxf(mx1, fmaxf(sacc[j][2], sacc[j][3]));
        }
        mx0 = fmaxf(mx0, __shfl_xor_sync(0xffffffffu, mx0, 1));
        mx0 = fmaxf(mx0, __shfl_xor_sync(0xffffffffu, mx0, 2));
        mx1 = fmaxf(mx1, __shfl_xor_sync(0xffffffffu, mx1, 1));
        mx1 = fmaxf(mx1, __shfl_xor_sync(0xffffffffu, mx1, 2));

        const float mn0 = fmaxf(mrow[0], mx0);
        const float mn1 = fmaxf(mrow[1], mx1);
        const float sc0 = exp2f(mrow[0] - mn0);
        const float sc1 = exp2f(mrow[1] - mn1);
        mrow[0] = mn0; mrow[1] = mn1;

        uint32_t pf[8][2];
#pragma unroll
        for (int j = 0; j < 8; j++) {
            pf[j][0] = ex2h2(packh2(sacc[j][0] - mn0, sacc[j][1] - mn0));
            pf[j][1] = ex2h2(packh2(sacc[j][2] - mn1, sacc[j][3] - mn1));
        }
#pragma unroll
        for (int j = 0; j < 18; j++) {
            o[j][0] *= sc0; o[j][1] *= sc0;
            o[j][2] *= sc1; o[j][3] *= sc1;
        }

#pragma unroll
        for (int kc = 0; kc < 4; kc++) {
            const int sec = kc >> 1;
            const int c   = (kc & 1) * 2 + kaddp;
            uint4 a;
            a.x = pf[kc * 2][0];
            a.y = pf[kc * 2][1];
            a.z = pf[kc * 2 + 1][0];
            a.w = pf[kc * 2 + 1][1];
#pragma unroll
            for (int np = 0; np < 9; np++) {
                const int row = np * 16 + rB0;
                uint4 bq;
                ldmx4(bq, vb + sec * FA_VSEC + row * 64
                          + ((c ^ ((row >> 1) & 3)) * 16));
                MMA16816(o[np * 2],     a, bq.x, bq.z);
                MMA16816(o[np * 2 + 1], a, bq.y, bq.w);
            }
        }

        __syncthreads();

        const int nb = jb + 2;
        if (nb < NBLK64) {
            const uint32_t nkb = sbase + FA_QSM + (nb & 1) * FA_KV;
            const uint32_t nvb = nkb + FA_KB;
#pragma unroll
            for (int sec = 0; sec < 4; sec++)
                cp16(nkb + sec * FA_KSEC + soffK,
                     Kp + (size_t)(nb * 64 + rK) * DMODEL + sec * 32 + kcK * 8);
#pragma unroll
            for (int sec = 0; sec < 2; sec++)
#pragma unroll
                for (int j = 0; j < 2; j++)
                    cp16(nvb + sec * FA_VSEC + soffQ[j],
                         Vp + (size_t)rQ[j] * S_TOT + nb * 64 + sec * 32 + kcQ8[j]);
        }
        asm volatile("cp.async.commit_group;");
    }

    const float l0 = __shfl_sync(0xffffffffu, o[16][0], lane & 28);
    const float l1 = __shfl_sync(0xffffffffu, o[16][2], lane & 28);
    const float inv0 = 1.0f / l0;
    const float inv1 = 1.0f / l1;
    __half* Op = Og + (size_t)(qb * 128) * DMODEL + h * DH;
#pragma unroll
    for (int j = 0; j < 16; j++) {
        const int col  = j * 8 + tg * 2;
        const int row0 = wid * 16 + g;
        *(uint32_t*)(Op + (size_t)row0 * DMODEL + col) =
            packh2(o[j][0] * inv0, o[j][1] * inv0);
        *(uint32_t*)(Op + (size_t)(row0 + 8) * DMODEL + col) =
            packh2(o[j][2] * inv1, o[j][3] * inv1);
    }
}

// ---------------------------------------------------------------------------
// V transpose: vt[h*DH + c][s] = qkv_v[s][h*DH + c]  (coalesced both sides)
// Tile = 32 s x 128 c per CTA, grid (80, 24). smem rows padded to 36 halves.
// ---------------------------------------------------------------------------
__global__ __launch_bounds__(256)
void v_transpose(const __half* __restrict__ qkvh, const __half* __restrict__ eqkvh,
                 __half* __restrict__ vt)
{
    __shared__ __half t[128][36];
    const int s0 = blockIdx.x * 32;
    const int h  = blockIdx.y;
    const __half* src = (s0 < S_TXT ? eqkvh + (size_t)s0 * D3
                                    : qkvh + (size_t)(s0 - S_TXT) * D3)
                        + 2 * DMODEL + h * DH;
    const int tid = threadIdx.x;
    const int s   = tid >> 3;     // 0..31
    const int kc  = tid & 7;      // 0..7
#pragma unroll
    for (int j = 0; j < 2; j++) {
        const int c0 = (kc + j * 8) * 8;     // 0..120 step 8
        uint4 v = *(const uint4*)(src + (size_t)s * D3 + c0);
        const __half* hp = (const __half*)&v;
#pragma unroll
        for (int i = 0; i < 8; i++) t[c0 + i][s] = hp[i];
    }
    __syncthreads();
    const int c = tid >> 1;
    const int p = tid & 1;
    uint2 w0 = *(const uint2*)&t[c][p * 16];
    uint2 w1 = *(const uint2*)&t[c][p * 16 + 4];
    uint2 w2 = *(const uint2*)&t[c][p * 16 + 8];
    uint2 w3 = *(const uint2*)&t[c][p * 16 + 12];
    __half* dst = vt + (size_t)(h * DH + c) * S_TOT + s0 + p * 16;
    *(uint2*)(dst)      = w0;
    *(uint2*)(dst + 4)  = w1;
    *(uint2*)(dst + 8)  = w2;
    *(uint2*)(dst + 12) = w3;
}

// ---------------------------------------------------------------------------
// Merged float->half
// ---------------------------------------------------------------------------
__global__ __launch_bounds__(256)
void f2h_all(const float* __restrict__ hidden, const float* __restrict__ enc,
             __half* __restrict__ hh, __half* __restrict__ eh)
{
    const int b = blockIdx.x;
    const float* in;
    __half* out;
    size_t i;
    if (b < (S_IMG * DMODEL) / 1024) {
        in = hidden; out = hh;
        i = ((size_t)b * 256 + threadIdx.x) * 4;
    } else {
        in = enc; out = eh;
        i = ((size_t)(b - (S_IMG * DMODEL) / 1024) * 256 + threadIdx.x) * 4;
    }
    float4 v = *(const float4*)(in + i);
    *(uint2*)(out + i) = make_uint2(packh2(v.x, v.y), packh2(v.z, v.w));
}

// ---------------------------------------------------------------------------
// Merged 64x64 transpose fp32->fp16 for all 4 weights
// ---------------------------------------------------------------------------
__global__ __launch_bounds__(256)
void transpose_all(const float* __restrict__ w0, const float* __restrict__ w1,
                   const float* __restrict__ w2, const float* __restrict__ w3,
                   __half* __restrict__ o0, __half* __restrict__ o1,
                   __half* __restrict__ o2, __half* __restrict__ o3)
{
    const int z = blockIdx.z;
    const float* in;
    __half* out;
    int R, C;
    if (z == 0)      { in = w0; out = o0; R = DMODEL; C = D3; }
    else if (z == 1) { in = w1; out = o1; R = DMODEL; C = D3; }
    else if (z == 2) { in = w2; out = o2; R = DMODEL; C = DMODEL; }
    else             { in = w3; out = o3; R = DMODEL; C = DMODEL; }
    const int bx = blockIdx.x * 64;
    const int by = blockIdx.y * 64;
    if (bx >= C) return;

    __shared__ float t[64][65];
    const int tx4 = (threadIdx.x & 15) * 4;
    const int ty  = threadIdx.x >> 4;
#pragma unroll
    for (int j = 0; j < 4; j++) {
        const int row = ty + j * 16;
        float4 v = *(const float4*)(in + (size_t)(by + row) * C + bx + tx4);
        t[row][tx4 + 0] = v.x; t[row][tx4 + 1] = v.y;
        t[row][tx4 + 2] = v.z; t[row][tx4 + 3] = v.w;
    }
    __syncthreads();
#pragma unroll
    for (int j = 0; j < 4; j++) {
        const int orow = ty + j * 16;
        uint2 w = make_uint2(
            packh2(t[tx4 + 0][orow], t[tx4 + 1][orow]),
            packh2(t[tx4 + 2][orow], t[tx4 + 3][orow]));
        *(uint2*)(out + (size_t)(bx + orow) * R + by + tx4) = w;
    }
}

// ---------------------------------------------------------------------------
// Fused RMSNorm + RoPE (fp16 in) -> fp16 q (scale*log2e), k  (V handled by
// v_transpose; no more 2-byte scatter here)
// ---------------------------------------------------------------------------
__device__ __forceinline__ float warp_sum(float v) {
#pragma unroll
    for (int o = 16; o > 0; o >>= 1) v += __shfl_xor_sync(0xffffffffu, v, o);
    return v;
}

__global__ __launch_bounds__(128)
void fuse_norm_rope(const __half* __restrict__ qkv, const __half* __restrict__ eqkv,
                    const int* __restrict__ ids,
                    const float* __restrict__ nq_w,  const float* __restrict__ nk_w,
                    const float* __restrict__ naq_w, const float* __restrict__ nak_w,
                    __half* __restrict__ Q, __half* __restrict__ Ko)
{
    const int s = blockIdx.x;
    const int h = blockIdx.y;
    const int d = threadIdx.x;

    const __half* src;
    const float* qw;
    const float* kw;
    if (s < S_TXT) { src = eqkv + (size_t)s * D3;           qw = naq_w; kw = nak_w; }
    else           { src = qkv  + (size_t)(s - S_TXT) * D3; qw = nq_w;  kw = nk_w; }

    float qv = __half2float(src[h * DH + d]);
    float kv = __half2float(src[DMODEL   + h * DH + d]);

    __shared__ float sq[4], sk[4];
    float wq = warp_sum(qv * qv);
    float wk = warp_sum(kv * kv);
    const int w = d >> 5;
    if ((d & 31) == 0) { sq[w] = wq; sk[w] = wk; }
    __syncthreads();
    float qsum = sq[0] + sq[1] + sq[2] + sq[3];
    float ksum = sk[0] + sk[1] + sk[2] + sk[3];
    float qn = qv * rsqrtf(qsum * (1.0f / DH) + 1e-5f) * qw[d];
    float kn = kv * rsqrtf(ksum * (1.0f / DH) + 1e-5f) * kw[d];

    const int pr = d >> 1;
    int axis, base, dax;
    if      (pr < 8)  { axis = 0; base = 0;  dax = 16; }
    else if (pr < 36) { axis = 1; base = 8;  dax = 56; }
    else              { axis = 2; base = 36; dax = 56; }
    float e    = (2.0f * (float)(pr - base)) / (float)dax;
    float freq = expf(-e * 9.210340371976184f);
    float pos  = (float)ids[s * 3 + axis];
    float ang  = pos * freq;
    float cs, sn;
    sincosf(ang, &sn, &cs);

    float q_other = __shfl_xor_sync(0xffffffffu, qn, 1);
    float k_other = __shfl_xor_sync(0xffffffffu, kn, 1);
    float qr, kr;
    if (d & 1) { qr = qn * cs + q_other * sn; kr = kn * cs + k_other * sn; }
    else       { qr = qn * cs - q_other * sn; kr = kn * cs - k_other * sn; }

    const size_t o = (size_t)s * DMODEL + h * DH + d;
    Q[o]  = __float2half(qr * (0.08838834764831845f * 1.4426950408889634f));
    Ko[o] = __float2half(kr);
}

// ---------------------------------------------------------------------------
// kernel_launch
// ---------------------------------------------------------------------------
extern "C" void kernel_launch(void* const* d_in, const int* in_sizes, int n_in,
                              void* d_out, int out_size)
{
    const float* hidden     = (const float*)d_in[0];
    const float* enc        = (const float*)d_in[1];
    const int*   ids        = (const int*)  d_in[2];
    const float* w_qkv      = (const float*)d_in[3];
    const float* w_add_qkv  = (const float*)d_in[4];
    const float* b_add_qkv  = (const float*)d_in[5];
    const float* w_out      = (const float*)d_in[6];
    const float* b_out      = (const float*)d_in[7];
    const float* w_add_out  = (const float*)d_in[8];
    const float* b_add_out  = (const float*)d_in[9];
    const float* norm_q_w   = (const float*)d_in[10];
    const float* norm_k_w   = (const float*)d_in[11];
    const float* norm_aq_w  = (const float*)d_in[12];
    const float* norm_ak_w  = (const float*)d_in[13];
    float* out = (float*)d_out;

    __half *qkvh, *eqkvh, *hh, *eh, *qh, *kh, *vt, *attnh, *wtq, *wtaq, *wto, *wtao;
    cudaGetSymbolAddress((void**)&qkvh,  g_qkvh);
    cudaGetSymbolAddress((void**)&eqkvh, g_eqkvh);
    cudaGetSymbolAddress((void**)&hh,    g_hh);
    cudaGetSymbolAddress((void**)&eh,    g_eh);
    cudaGetSymbolAddress((void**)&qh,    g_qh);
    cudaGetSymbolAddress((void**)&kh,    g_kh);
    cudaGetSymbolAddress((void**)&vt,    g_vt);
    cudaGetSymbolAddress((void**)&attnh, g_attnh);
    cudaGetSymbolAddress((void**)&wtq,   g_wtq);
    cudaGetSymbolAddress((void**)&wtaq,  g_wtaq);
    cudaGetSymbolAddress((void**)&wto,   g_wto);
    cudaGetSymbolAddress((void**)&wtao,  g_wtao);

    cudaFuncSetAttribute(gemm_nt_h<0>, cudaFuncAttributeMaxDynamicSharedMemorySize,
                         GEMM_SMEM_BYTES);
    cudaFuncSetAttribute(gemm_nt_h<1>, cudaFuncAttributeMaxDynamicSharedMemorySize,
                         GEMM_SMEM_BYTES);
    cudaFuncSetAttribute(flash_attn, cudaFuncAttributeMaxDynamicSharedMemorySize,
                         FA_SMEM);

    // 0) convert activations + transpose/convert all weights (2 launches)
    f2h_all<<<(S_IMG * DMODEL + S_TXT * DMODEL) / 1024, 256>>>(hidden, enc, hh, eh);
    transpose_all<<<dim3(D3/64, DMODEL/64, 4), 256>>>(
        w_qkv, w_add_qkv, w_out, w_add_out, wtq, wtaq, wto, wtao);

    // 1+2) [eqkv | qkv] fused
    gemm_nt_h<1><<<dim3(D3/128, S_TOT/128), 256, GEMM_SMEM_BYTES>>>(
        hh, wtq, nullptr, qkvh,
        eh, wtaq, b_add_qkv, eqkvh,
        S_TXT/128, DMODEL, DMODEL, DMODEL, D3);

    // 3a) RMSNorm + RoPE -> fp16 q,k  (coalesced only)
    fuse_norm_rope<<<dim3(S_TOT, NHEADS), 128>>>(
        qkvh, eqkvh, ids, norm_q_w, norm_k_w, norm_aq_w, norm_ak_w, qh, kh);

    // 3b) V transpose -> fp16 V^T (coalesced both sides)
    v_transpose<<<dim3(S_TOT/32, NHEADS), 256>>>(qkvh, eqkvh, vt);

    // 4) fused attention -> attnh fp16 [S, 3072]
    flash_attn<<<dim3(S_TOT/128, NHEADS), 256, FA_SMEM>>>(qh, kh, vt, attnh);

    // 5+6) [enc_out | img_out] fused
    gemm_nt_h<0><<<dim3(DMODEL/128, S_TOT/128), 256, GEMM_SMEM_BYTES>>>(
        attnh + (size_t)S_TXT * DMODEL, wto, b_out, out,
        attnh, wtao, b_add_out, out + (size_t)S_IMG * DMODEL,
        S_TXT/128, DMODEL, DMODEL, DMODEL, DMODEL);
}

// round 16
// speedup vs baseline: 1.2701x; 1.0110x over previous
#include <cuda_runtime.h>
#include <cuda_fp16.h>
#include <cstdint>
#include <math.h>

// ---------------------------------------------------------------------------
// Problem constants (Flux dual-stream attention block)
// ---------------------------------------------------------------------------
#define S_TXT   512
#define S_IMG   2048
#define S_TOT   2560
#define DMODEL  3072
#define NHEADS  24
#define DH      128
#define D3      9216

// ---------------------------------------------------------------------------
// Scratch (device globals -- allocation is forbidden)
// ---------------------------------------------------------------------------
__device__ __align__(256) __half g_qkvh [(size_t)S_IMG * D3];
__device__ __align__(256) __half g_eqkvh[(size_t)S_TXT * D3];
__device__ __align__(256) __half g_hh   [(size_t)S_IMG * DMODEL];
__device__ __align__(256) __half g_eh   [(size_t)S_TXT * DMODEL];
__device__ __align__(256) __half g_qh   [(size_t)S_TOT * DMODEL];
__device__ __align__(256) __half g_kh   [(size_t)S_TOT * DMODEL];
__device__ __align__(256) __half g_vt   [(size_t)DMODEL * S_TOT];
__device__ __align__(256) __half g_attnh[(size_t)S_TOT * DMODEL];
__device__ __align__(256) __half g_wtq  [(size_t)D3 * DMODEL];
__device__ __align__(256) __half g_wtaq [(size_t)D3 * DMODEL];
__device__ __align__(256) __half g_wto  [(size_t)DMODEL * DMODEL];
__device__ __align__(256) __half g_wtao [(size_t)DMODEL * DMODEL];
__device__ __align__(256) float2 g_rope [(size_t)S_TOT * 64];   // (cos,sin)

// ---------------------------------------------------------------------------
// helpers
// ---------------------------------------------------------------------------
__device__ __forceinline__ uint32_t smem_u32(const void* p) {
    uint32_t a;
    asm("{ .reg .u64 t; cvta.to.shared.u64 t, %1; cvt.u32.u64 %0, t; }" : "=r"(a) : "l"(p));
    return a;
}
__device__ __forceinline__ uint32_t packh2(float lo, float hi) {
    uint32_t r;
    asm("cvt.rn.f16x2.f32 %0, %1, %2;" : "=r"(r) : "f"(hi), "f"(lo));
    return r;
}
__device__ __forceinline__ uint32_t ex2h2(uint32_t x) {
    uint32_t r;
    asm("ex2.approx.f16x2 %0, %1;" : "=r"(r) : "r"(x));
    return r;
}
__device__ __forceinline__ void cp16(uint32_t saddr, const void* gptr) {
    asm volatile("cp.async.cg.shared.global [%0], [%1], 16;" :: "r"(saddr), "l"(gptr));
}
__device__ __forceinline__ void ldmx4(uint4& f, uint32_t addr) {
    asm volatile("ldmatrix.sync.aligned.m8n8.x4.shared.b16 {%0,%1,%2,%3}, [%4];"
                 : "=r"(f.x), "=r"(f.y), "=r"(f.z), "=r"(f.w) : "r"(addr));
}
#define MMA16816(acc, a, b0, b1)                                               \
    asm volatile("mma.sync.aligned.m16n8k16.row.col.f32.f16.f16.f32 "          \
                 "{%0,%1,%2,%3}, {%4,%5,%6,%7}, {%8,%9}, {%0,%1,%2,%3};"       \
                 : "+f"((acc)[0]), "+f"((acc)[1]), "+f"((acc)[2]), "+f"((acc)[3]) \
                 : "r"((a).x), "r"((a).y), "r"((a).z), "r"((a).w),             \
                   "r"(b0), "r"(b1))

// ---------------------------------------------------------------------------
// Fused dual-problem fp16 NT GEMM (128x128 tile, K-tile 64, 3-stage ring).
// ---------------------------------------------------------------------------
#define STAGE_BYTES 32768
#define NSTAGE 3
#define GEMM_SMEM_BYTES (NSTAGE * STAGE_BYTES)   // 98304

template<int OUT_HALF>
__global__ __launch_bounds__(256, 2)
void gemm_nt_h(const __half* __restrict__ A0, const __half* __restrict__ B0,
               const float* __restrict__ bias0, void* __restrict__ C0v,
               const __half* __restrict__ A1, const __half* __restrict__ B1,
               const float* __restrict__ bias1, void* __restrict__ C1v,
               int split, int K, int lda, int ldb, int ldc)
{
    extern __shared__ char smem[];
    const uint32_t sbase = smem_u32(smem);
    const int tid    = threadIdx.x;
    const int lane   = tid & 31;
    const int wid    = tid >> 5;
    const int warp_m = wid >> 2;
    const int warp_n = wid & 3;
    const int bn     = blockIdx.x * 128;

    const __half* A;
    const __half* B;
    const float*  bias;
    void*         Cv;
    {
        int by = blockIdx.y;
        if (by < split) {
            A = A1 + (size_t)by * 128 * lda;
            B = B1;  bias = bias1;
            Cv = (OUT_HALF ? (void*)((__half*)C1v + (size_t)by * 128 * ldc)
                           : (void*)((float*)C1v + (size_t)by * 128 * ldc));
        } else {
            by -= split;
            A = A0 + (size_t)by * 128 * lda;
            B = B0;  bias = bias0;
            Cv = (OUT_HALF ? (void*)((__half*)C0v + (size_t)by * 128 * ldc)
                           : (void*)((float*)C0v + (size_t)by * 128 * ldc));
        }
    }
    B += (size_t)bn * ldb;

    uint32_t soff[4];
    size_t   goa[4], gob[4];
#pragma unroll
    for (int j = 0; j < 4; j++) {
        const int c  = tid + j * 256;
        const int r  = c >> 3;
        const int kc = c & 7;
        soff[j] = (uint32_t)(r * 128 + ((kc ^ (r & 7)) * 16));
        goa[j]  = (size_t)r * lda + kc * 8;
        gob[j]  = (size_t)r * ldb + kc * 8;
    }

    const int T = K >> 6;

#pragma unroll
    for (int s = 0; s < 2; s++) {
        const uint32_t sa = sbase + s * STAGE_BYTES;
#pragma unroll
        for (int j = 0; j < 4; j++) {
            cp16(sa + soff[j],         A + goa[j] + s * 64);
            cp16(sa + 16384 + soff[j], B + gob[j] + s * 64);
        }
        asm volatile("cp.async.commit_group;");
    }

    float acc[4][4][4];
#pragma unroll
    for (int m = 0; m < 4; m++)
#pragma unroll
        for (int n = 0; n < 4; n++)
#pragma unroll
            for (int x = 0; x < 4; x++) acc[m][n][x] = 0.0f;

    const int p    = lane >> 3;
    const int li   = lane & 7;
    const int rA0  = warp_m * 64 + (p & 1) * 8 + li;
    const int rB0  = warp_n * 32 + (p & 1) * 8 + li;
    const int kaddp = p >> 1;

    int cur = 0, nxt = 2;
    for (int t = 0; t < T; t++) {
        asm volatile("cp.async.wait_group 1;");
        __syncthreads();

        {
            const int kt = t + 2;
            if (kt < T) {
                const uint32_t sa = sbase + nxt * STAGE_BYTES;
#pragma unroll
                for (int j = 0; j < 4; j++) {
                    cp16(sa + soff[j],         A + goa[j] + (size_t)kt * 64);
                    cp16(sa + 16384 + soff[j], B + gob[j] + (size_t)kt * 64);
                }
            }
            asm volatile("cp.async.commit_group;");
        }

        const uint32_t st = sbase + cur * STAGE_BYTES;
#pragma unroll
        for (int ks = 0; ks < 4; ks++) {
            const int kc = ks * 2 + kaddp;
            uint4 af[4];
#pragma unroll
            for (int mt = 0; mt < 4; mt++) {
                const int row = rA0 + mt * 16;
                ldmx4(af[mt], st + row * 128 + ((kc ^ (row & 7)) * 16));
            }
            uint4 bq[2];
#pragma unroll
            for (int ntp = 0; ntp < 2; ntp++) {
                const int row = rB0 + ntp * 16;
                ldmx4(bq[ntp], st + 16384 + row * 128 + ((kc ^ (row & 7)) * 16));
            }
            uint2 bf[4];
            bf[0] = make_uint2(bq[0].x, bq[0].z);
            bf[1] = make_uint2(bq[0].y, bq[0].w);
            bf[2] = make_uint2(bq[1].x, bq[1].z);
            bf[3] = make_uint2(bq[1].y, bq[1].w);
#pragma unroll
            for (int m = 0; m < 4; m++)
#pragma unroll
                for (int n = 0; n < 4; n++)
                    MMA16816(acc[m][n], af[m], bf[n].x, bf[n].y);
        }

        cur = (cur == 2) ? 0 : cur + 1;
        nxt = (nxt == 2) ? 0 : nxt + 1;
    }

    const int g  = lane >> 2;
    const int tg = lane & 3;
    if (OUT_HALF) {
        __half* C = (__half*)Cv;
#pragma unroll
        for (int m = 0; m < 4; m++) {
            const int row0 = warp_m * 64 + m * 16 + g;
#pragma unroll
            for (int n = 0; n < 4; n++) {
                const int col = bn + warp_n * 32 + n * 8 + tg * 2;
                float bx = 0.f, by2 = 0.f;
                if (bias) { bx = bias[col]; by2 = bias[col + 1]; }
                *(uint32_t*)(C + (size_t)row0 * ldc + col) =
                    packh2(acc[m][n][0] + bx, acc[m][n][1] + by2);
                *(uint32_t*)(C + (size_t)(row0 + 8) * ldc + col) =
                    packh2(acc[m][n][2] + bx, acc[m][n][3] + by2);
            }
        }
    } else {
        float* C = (float*)Cv;
#pragma unroll
        for (int m = 0; m < 4; m++) {
            const int row0 = warp_m * 64 + m * 16 + g;
#pragma unroll
            for (int n = 0; n < 4; n++) {
                const int col = bn + warp_n * 32 + n * 8 + tg * 2;
                float bx = 0.f, by2 = 0.f;
                if (bias) { bx = bias[col]; by2 = bias[col + 1]; }
                *(float2*)(C + (size_t)row0 * ldc + col) =
                    make_float2(acc[m][n][0] + bx, acc[m][n][1] + by2);
                *(float2*)(C + (size_t)(row0 + 8) * ldc + col) =
                    make_float2(acc[m][n][2] + bx, acc[m][n][3] + by2);
            }
        }
    }
}

// ---------------------------------------------------------------------------
// Fused flash attention (R13: KV-block 64, 2 CTAs/SM, ones-row mma sums)
// ---------------------------------------------------------------------------
#define FA_QSM   32768
#define FA_KSEC  4096
#define FA_KB    16384
#define FA_VSEC  9216
#define FA_VB    (2 * FA_VSEC)
#define FA_KV    (FA_KB + FA_VB)
#define FA_SMEM  (FA_QSM + 2 * FA_KV)   // 102400
#define NBLK64   (S_TOT / 64)           // 40

__global__ __launch_bounds__(256, 2)
void flash_attn(const __half* __restrict__ Qg, const __half* __restrict__ Kg,
                const __half* __restrict__ VTg, __half* __restrict__ Og)
{
    extern __shared__ char smem[];
    const uint32_t sbase = smem_u32(smem);
    const int tid  = threadIdx.x;
    const int lane = tid & 31;
    const int wid  = tid >> 5;
    const int qb   = blockIdx.x;
    const int h    = blockIdx.y;

    uint32_t soffQ[2];
    int rQ[2], kcQ8[2];
#pragma unroll
    for (int j = 0; j < 2; j++) {
        const int c  = tid + j * 256;
        const int r  = c >> 2;
        const int kc = c & 3;
        soffQ[j] = (uint32_t)(r * 64 + ((kc ^ ((r >> 1) & 3)) * 16));
        rQ[j]    = r;
        kcQ8[j]  = kc * 8;
    }
    const int rK  = tid >> 2;
    const int kcK = tid & 3;
    const uint32_t soffK = (uint32_t)(rK * 64 + ((kcK ^ ((rK >> 1) & 3)) * 16));

    const __half* Qp = Qg + (size_t)(qb * 128) * DMODEL + h * DH;
    const __half* Kp = Kg + h * DH;
    const __half* Vp = VTg + (size_t)(h * DH) * S_TOT;

#pragma unroll
    for (int bs = 0; bs < 4; bs++) {
        const int buf = bs >> 1;
        const int sec = bs & 1;
        const uint32_t base = FA_QSM + buf * FA_KV + FA_KB
                            + sec * FA_VSEC + 128 * 64;
        *(uint32_t*)(smem + base + tid * 4) = (tid < 16) ? 0x3C003C00u : 0u;
    }

#pragma unroll
    for (int sec = 0; sec < 4; sec++)
#pragma unroll
        for (int j = 0; j < 2; j++)
            cp16(sbase + sec * 8192 + soffQ[j],
                 Qp + (size_t)rQ[j] * DMODEL + sec * 32 + kcQ8[j]);
    {
        const uint32_t kb = sbase + FA_QSM;
        const uint32_t vb = kb + FA_KB;
#pragma unroll
        for (int sec = 0; sec < 4; sec++)
            cp16(kb + sec * FA_KSEC + soffK,
                 Kp + (size_t)rK * DMODEL + sec * 32 + kcK * 8);
#pragma unroll
        for (int sec = 0; sec < 2; sec++)
#pragma unroll
            for (int j = 0; j < 2; j++)
                cp16(vb + sec * FA_VSEC + soffQ[j],
                     Vp + (size_t)rQ[j] * S_TOT + sec * 32 + kcQ8[j]);
    }
    asm volatile("cp.async.commit_group;");
    {
        const uint32_t kb = sbase + FA_QSM + FA_KV;
        const uint32_t vb = kb + FA_KB;
#pragma unroll
        for (int sec = 0; sec < 4; sec++)
            cp16(kb + sec * FA_KSEC + soffK,
                 Kp + (size_t)(64 + rK) * DMODEL + sec * 32 + kcK * 8);
#pragma unroll
        for (int sec = 0; sec < 2; sec++)
#pragma unroll
            for (int j = 0; j < 2; j++)
                cp16(vb + sec * FA_VSEC + soffQ[j],
                     Vp + (size_t)rQ[j] * S_TOT + 64 + sec * 32 + kcQ8[j]);
    }
    asm volatile("cp.async.commit_group;");

    const int p     = lane >> 3;
    const int li    = lane & 7;
    const int kaddp = p >> 1;
    const int rowQ  = wid * 16 + (p & 1) * 8 + li;
    const int rB0   = (p & 1) * 8 + li;
    const int g     = lane >> 2;
    const int tg    = lane & 3;

    float mrow[2] = {-1e30f, -1e30f};
    float o[18][4];
#pragma unroll
    for (int j = 0; j < 18; j++)
#pragma unroll
        for (int x = 0; x < 4; x++) o[j][x] = 0.f;

    for (int jb = 0; jb < NBLK64; jb++) {
        asm volatile("cp.async.wait_group 1;");
        __syncthreads();

        const uint32_t kb = sbase + FA_QSM + (jb & 1) * FA_KV;
        const uint32_t vb = kb + FA_KB;

        float sacc[8][4];
#pragma unroll
        for (int j = 0; j < 8; j++)
#pragma unroll
            for (int x = 0; x < 4; x++) sacc[j][x] = 0.f;
#pragma unroll
        for (int kc = 0; kc < 8; kc++) {
            const int sec = kc >> 1;
            const int c   = (kc & 1) * 2 + kaddp;
            uint4 qa;
            ldmx4(qa, sbase + sec * 8192 + rowQ * 64
                      + ((c ^ ((rowQ >> 1) & 3)) * 16));
#pragma unroll
            for (int np = 0; np < 4; np++) {
                const int row = np * 16 + rB0;
                uint4 bq;
                ldmx4(bq, kb + sec * FA_KSEC + row * 64
                          + ((c ^ ((row >> 1) & 3)) * 16));
                MMA16816(sacc[np * 2],     qa, bq.x, bq.z);
                MMA16816(sacc[np * 2 + 1], qa, bq.y, bq.w);
            }
        }

        float mx0 = -1e30f, mx1 = -1e30f;
#pragma unroll
        for (int j = 0; j < 8; j++) {
            mx0 = fmaxf(mx0, fmaxf(sacc[j][0], sacc[j][1]));
            mx1 = fmaxf(mx1, fmaxf(sacc[j][2], sacc[j][3]));
        }
        mx0 = fmaxf(mx0, __shfl_xor_sync(0xffffffffu, mx0, 1));
        mx0 = fmaxf(mx0, __shfl_xor_sync(0xffffffffu, mx0, 2));
        mx1 = fmaxf(mx1, __shfl_xor_sync(0xffffffffu, mx1, 1));
        mx1 = fmaxf(mx1, __shfl_xor_sync(0xffffffffu, mx1, 2));

        const float mn0 = fmaxf(mrow[0], mx0);
        const float mn1 = fmaxf(mrow[1], mx1);
        const float sc0 = exp2f(mrow[0] - mn0);
        const float sc1 = exp2f(mrow[1] - mn1);
        mrow[0] = mn0; mrow[1] = mn1;

        uint32_t pf[8][2];
#pragma unroll
        for (int j = 0; j < 8; j++) {
            pf[j][0] = ex2h2(packh2(sacc[j][0] - mn0, sacc[j][1] - mn0));
            pf[j][1] = ex2h2(packh2(sacc[j][2] - mn1, sacc[j][3] - mn1));
        }
#pragma unroll
        for (int j = 0; j < 18; j++) {
            o[j][0] *= sc0; o[j][1] *= sc0;
            o[j][2] *= sc1; o[j][3] *= sc1;
        }

#pragma unroll
        for (int kc = 0; kc < 4; kc++) {
            const int sec = kc >> 1;
            const int c   = (kc & 1) * 2 + kaddp;
            uint4 a;
            a.x = pf[kc * 2][0];
            a.y = pf[kc * 2][1];
            a.z = pf[kc * 2 + 1][0];
            a.w = pf[kc * 2 + 1][1];
#pragma unroll
            for (int np = 0; np < 9; np++) {
                const int row = np * 16 + rB0;
                uint4 bq;
                ldmx4(bq, vb + sec * FA_VSEC + row * 64
                          + ((c ^ ((row >> 1) & 3)) * 16));
                MMA16816(o[np * 2],     a, bq.x, bq.z);
                MMA16816(o[np * 2 + 1], a, bq.y, bq.w);
            }
        }

        __syncthreads();

        const int nb = jb + 2;
        if (nb < NBLK64) {
            const uint32_t nkb = sbase + FA_QSM + (nb & 1) * FA_KV;
            const uint32_t nvb = nkb + FA_KB;
#pragma unroll
            for (int sec = 0; sec < 4; sec++)
                cp16(nkb + sec * FA_KSEC + soffK,
                     Kp + (size_t)(nb * 64 + rK) * DMODEL + sec * 32 + kcK * 8);
#pragma unroll
            for (int sec = 0; sec < 2; sec++)
#pragma unroll
                for (int j = 0; j < 2; j++)
                    cp16(nvb + sec * FA_VSEC + soffQ[j],
                         Vp + (size_t)rQ[j] * S_TOT + nb * 64 + sec * 32 + kcQ8[j]);
        }
        asm volatile("cp.async.commit_group;");
    }

    const float l0 = __shfl_sync(0xffffffffu, o[16][0], lane & 28);
    const float l1 = __shfl_sync(0xffffffffu, o[16][2], lane & 28);
    const float inv0 = 1.0f / l0;
    const float inv1 = 1.0f / l1;
    __half* Op = Og + (size_t)(qb * 128) * DMODEL + h * DH;
#pragma unroll
    for (int j = 0; j < 16; j++) {
        const int col  = j * 8 + tg * 2;
        const int row0 = wid * 16 + g;
        *(uint32_t*)(Op + (size_t)row0 * DMODEL + col) =
            packh2(o[j][0] * inv0, o[j][1] * inv0);
        *(uint32_t*)(Op + (size_t)(row0 + 8) * DMODEL + col) =
            packh2(o[j][2] * inv1, o[j][3] * inv1);
    }
}

// ---------------------------------------------------------------------------
// V transpose: vt[h*DH + c][s] = qkv_v[s][h*DH + c]
// ---------------------------------------------------------------------------
__global__ __launch_bounds__(256)
void v_transpose(const __half* __restrict__ qkvh, const __half* __restrict__ eqkvh,
                 __half* __restrict__ vt)
{
    __shared__ __half t[128][36];
    const int s0 = blockIdx.x * 32;
    const int h  = blockIdx.y;
    const __half* src = (s0 < S_TXT ? eqkvh + (size_t)s0 * D3
                                    : qkvh + (size_t)(s0 - S_TXT) * D3)
                        + 2 * DMODEL + h * DH;
    const int tid = threadIdx.x;
    const int s   = tid >> 3;
    const int kc  = tid & 7;
#pragma unroll
    for (int j = 0; j < 2; j++) {
        const int c0 = (kc + j * 8) * 8;
        uint4 v = *(const uint4*)(src + (size_t)s * D3 + c0);
        const __half* hp = (const __half*)&v;
#pragma unroll
        for (int i = 0; i < 8; i++) t[c0 + i][s] = hp[i];
    }
    __syncthreads();
    const int c = tid >> 1;
    const int p = tid & 1;
    uint2 w0 = *(const uint2*)&t[c][p * 16];
    uint2 w1 = *(const uint2*)&t[c][p * 16 + 4];
    uint2 w2 = *(const uint2*)&t[c][p * 16 + 8];
    uint2 w3 = *(const uint2*)&t[c][p * 16 + 12];
    __half* dst = vt + (size_t)(h * DH + c) * S_TOT + s0 + p * 16;
    *(uint2*)(dst)      = w0;
    *(uint2*)(dst + 4)  = w1;
    *(uint2*)(dst + 8)  = w2;
    *(uint2*)(dst + 12) = w3;
}

// ---------------------------------------------------------------------------
// Merged float->half
// ---------------------------------------------------------------------------
__global__ __launch_bounds__(256)
void f2h_all(const float* __restrict__ hidden, const float* __restrict__ enc,
             __half* __restrict__ hh, __half* __restrict__ eh)
{
    const int b = blockIdx.x;
    const float* in;
    __half* out;
    size_t i;
    if (b < (S_IMG * DMODEL) / 1024) {
        in = hidden; out = hh;
        i = ((size_t)b * 256 + threadIdx.x) * 4;
    } else {
        in = enc; out = eh;
        i = ((size_t)(b - (S_IMG * DMODEL) / 1024) * 256 + threadIdx.x) * 4;
    }
    float4 v = *(const float4*)(in + i);
    *(uint2*)(out + i) = make_uint2(packh2(v.x, v.y), packh2(v.z, v.w));
}

// ---------------------------------------------------------------------------
// Merged 64x64 transpose fp32->fp16 for all 4 weights
// ---------------------------------------------------------------------------
__global__ __launch_bounds__(256)
void transpose_all(const float* __restrict__ w0, const float* __restrict__ w1,
                   const float* __restrict__ w2, const float* __restrict__ w3,
                   __half* __restrict__ o0, __half* __restrict__ o1,
                   __half* __restrict__ o2, __half* __restrict__ o3)
{
    const int z = blockIdx.z;
    const float* in;
    __half* out;
    int R, C;
    if (z == 0)      { in = w0; out = o0; R = DMODEL; C = D3; }
    else if (z == 1) { in = w1; out = o1; R = DMODEL; C = D3; }
    else if (z == 2) { in = w2; out = o2; R = DMODEL; C = DMODEL; }
    else             { in = w3; out = o3; R = DMODEL; C = DMODEL; }
    const int bx = blockIdx.x * 64;
    const int by = blockIdx.y * 64;
    if (bx >= C) return;

    __shared__ float t[64][65];
    const int tx4 = (threadIdx.x & 15) * 4;
    const int ty  = threadIdx.x >> 4;
#pragma unroll
    for (int j = 0; j < 4; j++) {
        const int row = ty + j * 16;
        float4 v = *(const float4*)(in + (size_t)(by + row) * C + bx + tx4);
        t[row][tx4 + 0] = v.x; t[row][tx4 + 1] = v.y;
        t[row][tx4 + 2] = v.z; t[row][tx4 + 3] = v.w;
    }
    __syncthreads();
#pragma unroll
    for (int j = 0; j < 4; j++) {
        const int orow = ty + j * 16;
        uint2 w = make_uint2(
            packh2(t[tx4 + 0][orow], t[tx4 + 1][orow]),
            packh2(t[tx4 + 2][orow], t[tx4 + 3][orow]));
        *(uint2*)(out + (size_t)(bx + orow) * R + by + tx4) = w;
    }
}

// ---------------------------------------------------------------------------
// RoPE table: g_rope[s*64 + pr] = (cos, sin) of pos(s,axis(pr)) * freq(pr)
// Same expf/sincosf sequence as before -> bit-identical downstream values.
// ---------------------------------------------------------------------------
__global__ __launch_bounds__(256)
void rope_table(const int* __restrict__ ids, float2* __restrict__ tab)
{
    const int idx = blockIdx.x * 256 + threadIdx.x;   // 163840 total
    const int s   = idx >> 6;
    const int pr  = idx & 63;
    int axis, base, dax;
    if      (pr < 8)  { axis = 0; base = 0;  dax = 16; }
    else if (pr < 36) { axis = 1; base = 8;  dax = 56; }
    else              { axis = 2; base = 36; dax = 56; }
    float e    = (2.0f * (float)(pr - base)) / (float)dax;
    float freq = expf(-e * 9.210340371976184f);
    float pos  = (float)ids[s * 3 + axis];
    float cs, sn;
    sincosf(pos * freq, &sn, &cs);
    tab[idx] = make_float2(cs, sn);
}

// ---------------------------------------------------------------------------
// Fused RMSNorm + RoPE (fp16 in, table-driven trig) -> fp16 q (scaled), k
// ---------------------------------------------------------------------------
__device__ __forceinline__ float warp_sum(float v) {
#pragma unroll
    for (int o = 16; o > 0; o >>= 1) v += __shfl_xor_sync(0xffffffffu, v, o);
    return v;
}

__global__ __launch_bounds__(128)
void fuse_norm_rope(const __half* __restrict__ qkv, const __half* __restrict__ eqkv,
                    const float2* __restrict__ rope,
                    const float* __restrict__ nq_w,  const float* __restrict__ nk_w,
                    const float* __restrict__ naq_w, const float* __restrict__ nak_w,
                    __half* __restrict__ Q, __half* __restrict__ Ko)
{
    const int s = blockIdx.x;
    const int h = blockIdx.y;
    const int d = threadIdx.x;

    const __half* src;
    const float* qw;
    const float* kw;
    if (s < S_TXT) { src = eqkv + (size_t)s * D3;           qw = naq_w; kw = nak_w; }
    else           { src = qkv  + (size_t)(s - S_TXT) * D3; qw = nq_w;  kw = nk_w; }

    float qv = __half2float(src[h * DH + d]);
    float kv = __half2float(src[DMODEL   + h * DH + d]);

    __shared__ float sq[4], sk[4];
    float wq = warp_sum(qv * qv);
    float wk = warp_sum(kv * kv);
    const int w = d >> 5;
    if ((d & 31) == 0) { sq[w] = wq; sk[w] = wk; }
    __syncthreads();
    float qsum = sq[0] + sq[1] + sq[2] + sq[3];
    float ksum = sk[0] + sk[1] + sk[2] + sk[3];
    float qn = qv * rsqrtf(qsum * (1.0f / DH) + 1e-5f) * qw[d];
    float kn = kv * rsqrtf(ksum * (1.0f / DH) + 1e-5f) * kw[d];

    const float2 cssn = rope[s * 64 + (d >> 1)];
    const float cs = cssn.x, sn = cssn.y;

    float q_other = __shfl_xor_sync(0xffffffffu, qn, 1);
    float k_other = __shfl_xor_sync(0xffffffffu, kn, 1);
    float qr, kr;
    if (d & 1) { qr = qn * cs + q_other * sn; kr = kn * cs + k_other * sn; }
    else       { qr = qn * cs - q_other * sn; kr = kn * cs - k_other * sn; }

    const size_t o = (size_t)s * DMODEL + h * DH + d;
    Q[o]  = __float2half(qr * (0.08838834764831845f * 1.4426950408889634f));
    Ko[o] = __float2half(kr);
}

// ---------------------------------------------------------------------------
// kernel_launch
// ---------------------------------------------------------------------------
extern "C" void kernel_launch(void* const* d_in, const int* in_sizes, int n_in,
                              void* d_out, int out_size)
{
    const float* hidden     = (const float*)d_in[0];
    const float* enc        = (const float*)d_in[1];
    const int*   ids        = (const int*)  d_in[2];
    const float* w_qkv      = (const float*)d_in[3];
    const float* w_add_qkv  = (const float*)d_in[4];
    const float* b_add_qkv  = (const float*)d_in[5];
    const float* w_out      = (const float*)d_in[6];
    const float* b_out      = (const float*)d_in[7];
    const float* w_add_out  = (const float*)d_in[8];
    const float* b_add_out  = (const float*)d_in[9];
    const float* norm_q_w   = (const float*)d_in[10];
    const float* norm_k_w   = (const float*)d_in[11];
    const float* norm_aq_w  = (const float*)d_in[12];
    const float* norm_ak_w  = (const float*)d_in[13];
    float* out = (float*)d_out;

    __half *qkvh, *eqkvh, *hh, *eh, *qh, *kh, *vt, *attnh, *wtq, *wtaq, *wto, *wtao;
    float2* rope;
    cudaGetSymbolAddress((void**)&qkvh,  g_qkvh);
    cudaGetSymbolAddress((void**)&eqkvh, g_eqkvh);
    cudaGetSymbolAddress((void**)&hh,    g_hh);
    cudaGetSymbolAddress((void**)&eh,    g_eh);
    cudaGetSymbolAddress((void**)&qh,    g_qh);
    cudaGetSymbolAddress((void**)&kh,    g_kh);
    cudaGetSymbolAddress((void**)&vt,    g_vt);
    cudaGetSymbolAddress((void**)&attnh, g_attnh);
    cudaGetSymbolAddress((void**)&wtq,   g_wtq);
    cudaGetSymbolAddress((void**)&wtaq,  g_wtaq);
    cudaGetSymbolAddress((void**)&wto,   g_wto);
    cudaGetSymbolAddress((void**)&wtao,  g_wtao);
    cudaGetSymbolAddress((void**)&rope,  g_rope);

    cudaFuncSetAttribute(gemm_nt_h<0>, cudaFuncAttributeMaxDynamicSharedMemorySize,
                         GEMM_SMEM_BYTES);
    cudaFuncSetAttribute(gemm_nt_h<1>, cudaFuncAttributeMaxDynamicSharedMemorySize,
                         GEMM_SMEM_BYTES);
    cudaFuncSetAttribute(flash_attn, cudaFuncAttributeMaxDynamicSharedMemorySize,
                         FA_SMEM);

    // 0) conversions, weight transposes, rope table
    f2h_all<<<(S_IMG * DMODEL + S_TXT * DMODEL) / 1024, 256>>>(hidden, enc, hh, eh);
    transpose_all<<<dim3(D3/64, DMODEL/64, 4), 256>>>(
        w_qkv, w_add_qkv, w_out, w_add_out, wtq, wtaq, wto, wtao);
    rope_table<<<(S_TOT * 64) / 256, 256>>>(ids, rope);

    // 1+2) [eqkv | qkv] fused
    gemm_nt_h<1><<<dim3(D3/128, S_TOT/128), 256, GEMM_SMEM_BYTES>>>(
        hh, wtq, nullptr, qkvh,
        eh, wtaq, b_add_qkv, eqkvh,
        S_TXT/128, DMODEL, DMODEL, DMODEL, D3);

    // 3a) RMSNorm + RoPE (table trig) -> fp16 q,k
    fuse_norm_rope<<<dim3(S_TOT, NHEADS), 128>>>(
        qkvh, eqkvh, rope, norm_q_w, norm_k_w, norm_aq_w, norm_ak_w, qh, kh);

    // 3b) V transpose -> fp16 V^T
    v_transpose<<<dim3(S_TOT/32, NHEADS), 256>>>(qkvh, eqkvh, vt);

    // 4) fused attention -> attnh fp16 [S, 3072]
    flash_attn<<<dim3(S_TOT/128, NHEADS), 256, FA_SMEM>>>(qh, kh, vt, attnh);

    // 5+6) [enc_out | img_out] fused
    gemm_nt_h<0><<<dim3(DMODEL/128, S_TOT/128), 256, GEMM_SMEM_BYTES>>>(
        attnh + (size_t)S_TXT * DMODEL, wto, b_out, out,
        attnh, wtao, b_add_out, out + (size_t)S_IMG * DMODEL,
        S_TXT/128, DMODEL, DMODEL, DMODEL, DMODEL);
}